// round 6
// baseline (speedup 1.0000x reference)
#include <cuda_runtime.h>
#include <cuda_bf16.h>
#include <math.h>
#include <stdint.h>

#define BB 2
#define CY 96
#define CS 48
#define NN 4096
#define SCALE 0.14433756729740643f  /* 48^-0.5 */

// ---------------- scratch (device globals: no runtime allocation) ----------
__device__ __align__(16) float g_Spe[BB*CS*NN];
__device__ __align__(16) float g_Ype[BB*CY*NN];
__device__ __align__(16) float g_Y1 [BB*NN*CS];
__device__ __align__(16) float g_V  [BB*NN*CS];
__device__ __align__(16) __nv_bfloat16 g_Qh[BB*NN*CS], g_Ql[BB*NN*CS];
__device__ __align__(16) __nv_bfloat16 g_Kh[BB*NN*CS], g_Kl[BB*NN*CS];
__device__ __align__(16) __nv_bfloat16 g_Vth[BB*CS*NN], g_Vtl[BB*CS*NN];
__device__ __align__(16) float g_L[(size_t)BB*NN*NN];   // 128 MB expL [b][q][k]
__device__ __align__(16) float g_psum[BB*32*NN];        // per-qblock column sums
__device__ __align__(16) float g_Xp[4*BB*NN*CS];        // AV partials (4 k-chunks)
__device__ __align__(16) float g_Y3p[2*BB*CY*NN];       // conv partials (2 ci halves)
__device__ __align__(16) float g_peS[CS*256];
__device__ __align__(16) float g_peY[CY*256];

// ---------------- helpers ---------------------------------------------------
__device__ __forceinline__ void mma16816(float* c, const uint32_t* a, const uint32_t* b) {
    asm volatile(
        "mma.sync.aligned.m16n8k16.row.col.f32.bf16.bf16.f32 "
        "{%0,%1,%2,%3}, {%4,%5,%6,%7}, {%8,%9}, {%0,%1,%2,%3};\n"
        : "+f"(c[0]), "+f"(c[1]), "+f"(c[2]), "+f"(c[3])
        : "r"(a[0]), "r"(a[1]), "r"(a[2]), "r"(a[3]), "r"(b[0]), "r"(b[1]));
}

__device__ __forceinline__ uint32_t bf2u(__nv_bfloat16 a, __nv_bfloat16 b) {
    __nv_bfloat162 v(a, b);
    return *reinterpret_cast<uint32_t*>(&v);
}

__device__ __forceinline__ void fma2(unsigned long long& d, unsigned long long a,
                                     unsigned long long b) {
    asm("fma.rn.f32x2 %0, %1, %2, %0;" : "+l"(d) : "l"(a), "l"(b));
}

// ---------------- positional encoding tables --------------------------------
__device__ __forceinline__ float pe_val(int ch, int h, int w, int c) {
    int blk = ch / c, t = ch - blk * c;
    int pos = (blk < 2) ? h : w;    // torch broadcast quirk: x & y blocks both use h
    int half = c >> 1;
    if (t < half) {
        float invf = powf(10000.f, -2.f * (float)t / (float)c);
        return sinf((float)pos * invf);
    } else {
        float invf = powf(10000.f, -2.f * (float)(t - half) / (float)c);
        return cosf((float)pos * invf);
    }
}

__global__ void k_petab() {
    int i = blockIdx.x * 256 + threadIdx.x;
    if (i < CY * 256) {
        int ch = i >> 8, n = i & 255;
        g_peY[i] = pe_val(ch, n >> 4, n & 15, 32);
    } else {
        int j = i - CY * 256;
        if (j < CS * 256) {
            int ch = j >> 8, n = j & 255;
            g_peS[j] = pe_val(ch, n >> 4, n & 15, 16);
        }
    }
}

__global__ void k_addpe_s(const float* __restrict__ S) {
    int i4 = blockIdx.x * 256 + threadIdx.x;
    int i = i4 * 4;
    int n = i & (NN - 1);
    int ch = (i >> 12) % CS;
    float4 s = *(const float4*)&S[i];
    float4 p = *(const float4*)&g_peS[ch * 256 + (n & 255)];
    s.x += p.x; s.y += p.y; s.z += p.z; s.w += p.w;
    *(float4*)&g_Spe[i] = s;
}

__global__ void k_addpe_y(const float* __restrict__ Y) {
    int i4 = blockIdx.x * 256 + threadIdx.x;
    int i = i4 * 4;
    int n = i & (NN - 1);
    int ch = (i >> 12) % CY;
    float4 s = *(const float4*)&Y[i];
    float4 p = *(const float4*)&g_peY[ch * 256 + (n & 255)];
    s.x += p.x; s.y += p.y; s.z += p.z; s.w += p.w;
    *(float4*)&g_Ype[i] = s;
}

// ---------------- S1 projection fused with V = S1 @ Wv ---------------------
__global__ __launch_bounds__(256) void k_proj_sv(
    const float* __restrict__ w_s, const float* __restrict__ b_s,
    const float* __restrict__ g_s, const float* __restrict__ be_s,
    const float* __restrict__ Wv)
{
    __shared__ float in_s[CS * 64];
    __shared__ float wt[CS * CS];
    __shared__ float wv[CS * CS];
    __shared__ float s1[64 * 49];

    int b = blockIdx.y, n0 = blockIdx.x * 64, t = threadIdx.x;
    for (int i = t; i < CS * CS; i += 256) {
        int e = i % CS, c = i / CS;
        wt[i] = w_s[e * CS + c];
        wv[i] = Wv[i];
    }
    const float* src = g_Spe + (b * CS) * NN + n0;
    for (int i = t; i < CS * 64; i += 256) {
        int c = i >> 6, n = i & 63;
        in_s[i] = src[c * NN + n];
    }
    __syncthreads();

    int n = t & 63, eg = t >> 6;
    float acc[12];
#pragma unroll
    for (int j = 0; j < 12; j++) acc[j] = 0.f;
    for (int c = 0; c < CS; c++) {
        float x = in_s[c * 64 + n];
#pragma unroll
        for (int v = 0; v < 3; v++) {
            float4 w4 = *(const float4*)&wt[c * CS + eg * 12 + v * 4];
            acc[v*4+0] += w4.x * x; acc[v*4+1] += w4.y * x;
            acc[v*4+2] += w4.z * x; acc[v*4+3] += w4.w * x;
        }
    }
    float inv = rsqrtf(1.f + 1e-5f);
#pragma unroll
    for (int j = 0; j < 12; j++) {
        int e = eg * 12 + j;
        float y = (acc[j] + b_s[e]) * (g_s[e] * inv) + be_s[e];
        s1[n * 49 + e] = fmaxf(y, 0.f);
    }
    __syncthreads();

#pragma unroll
    for (int j = 0; j < 12; j++) acc[j] = 0.f;
    for (int d = 0; d < CS; d++) {
        float x = s1[n * 49 + d];
#pragma unroll
        for (int v = 0; v < 3; v++) {
            float4 w4 = *(const float4*)&wv[d * CS + eg * 12 + v * 4];
            acc[v*4+0] += w4.x * x; acc[v*4+1] += w4.y * x;
            acc[v*4+2] += w4.z * x; acc[v*4+3] += w4.w * x;
        }
    }
    float* dst = g_V + ((b * NN + n0 + n) * CS) + eg * 12;
#pragma unroll
    for (int v = 0; v < 3; v++)
        *(float4*)&dst[v * 4] = make_float4(acc[v*4], acc[v*4+1], acc[v*4+2], acc[v*4+3]);
}

// ---------------- Y1 projection (96 -> 48) ---------------------------------
__global__ __launch_bounds__(256) void k_proj_y1(
    const float* __restrict__ w_y, const float* __restrict__ b_y,
    const float* __restrict__ g_y, const float* __restrict__ be_y)
{
    __shared__ float in_s[CY * 64];
    __shared__ float wt[CY * CS];

    int b = blockIdx.y, n0 = blockIdx.x * 64, t = threadIdx.x;
    for (int i = t; i < CY * CS; i += 256) {
        int e = i % CS, c = i / CS;
        wt[i] = w_y[e * CY + c];
    }
    const float* src = g_Ype + (b * CY) * NN + n0;
    for (int i = t; i < CY * 64; i += 256) {
        int c = i >> 6, n = i & 63;
        in_s[i] = src[c * NN + n];
    }
    __syncthreads();

    int n = t & 63, eg = t >> 6;
    float acc[12];
#pragma unroll
    for (int j = 0; j < 12; j++) acc[j] = 0.f;
    for (int c = 0; c < CY; c++) {
        float x = in_s[c * 64 + n];
#pragma unroll
        for (int v = 0; v < 3; v++) {
            float4 w4 = *(const float4*)&wt[c * CS + eg * 12 + v * 4];
            acc[v*4+0] += w4.x * x; acc[v*4+1] += w4.y * x;
            acc[v*4+2] += w4.z * x; acc[v*4+3] += w4.w * x;
        }
    }
    float inv = rsqrtf(1.f + 1e-5f);
    float* dst = g_Y1 + ((b * NN + n0 + n) * CS) + eg * 12;
#pragma unroll
    for (int j = 0; j < 12; j++) {
        int e = eg * 12 + j;
        float y = (acc[j] + b_y[e]) * (g_y[e] * inv) + be_y[e];
        dst[j] = fmaxf(y, 0.f);
    }
}

// ---------------- Q/K = Y1 @ Wq / Wk  -> bf16 hi/lo splits ------------------
__global__ __launch_bounds__(256) void k_qk(
    const float* __restrict__ Wq, const float* __restrict__ Wk)
{
    __shared__ float y1[64 * 49];
    __shared__ float wq[CS * CS];
    __shared__ float wk[CS * CS];

    int b = blockIdx.y, n0 = blockIdx.x * 64, t = threadIdx.x;
    for (int i = t; i < CS * CS; i += 256) { wq[i] = Wq[i]; wk[i] = Wk[i]; }
    const float* src = g_Y1 + (b * NN + n0) * CS;
    for (int i = t; i < 64 * CS; i += 256) {
        int n = i / CS, d = i % CS;
        y1[n * 49 + d] = src[i];
    }
    __syncthreads();

    int n = t & 63, eg = t >> 6;
    float aq[12], ak[12];
#pragma unroll
    for (int j = 0; j < 12; j++) { aq[j] = 0.f; ak[j] = 0.f; }
    for (int d = 0; d < CS; d++) {
        float x = y1[n * 49 + d];
#pragma unroll
        for (int v = 0; v < 3; v++) {
            float4 q4 = *(const float4*)&wq[d * CS + eg * 12 + v * 4];
            float4 k4 = *(const float4*)&wk[d * CS + eg * 12 + v * 4];
            aq[v*4+0] += q4.x * x; aq[v*4+1] += q4.y * x;
            aq[v*4+2] += q4.z * x; aq[v*4+3] += q4.w * x;
            ak[v*4+0] += k4.x * x; ak[v*4+1] += k4.y * x;
            ak[v*4+2] += k4.z * x; ak[v*4+3] += k4.w * x;
        }
    }
    int base = (b * NN + n0 + n) * CS + eg * 12;
#pragma unroll
    for (int j = 0; j < 12; j++) {
        __nv_bfloat16 qh = __float2bfloat16(aq[j]);
        __nv_bfloat16 kh = __float2bfloat16(ak[j]);
        g_Qh[base + j] = qh;
        g_Ql[base + j] = __float2bfloat16(aq[j] - __bfloat162float(qh));
        g_Kh[base + j] = kh;
        g_Kl[base + j] = __float2bfloat16(ak[j] - __bfloat162float(kh));
    }
}

// ---------------- logits MMA: L[b][q][k] = exp(SCALE * Q[q]·K[k]) ----------
// Block: 128q x 128k, 8 warps (2 m x 4 n), warp tile 64x32.
// Also produces per-block column sums (over q) into g_psum[b][qblk][k].
#define LPAD 56
#define LOGITS_SMEM (4 * 128 * LPAD * 2)
__global__ __launch_bounds__(256, 2) void k_logits_mma() {
    extern __shared__ __align__(16) unsigned char dsm[];
    __nv_bfloat16* Qsh = (__nv_bfloat16*)dsm;
    __nv_bfloat16* Qsl = Qsh + 128 * LPAD;
    __nv_bfloat16* Ksh = Qsl + 128 * LPAD;
    __nv_bfloat16* Ksl = Ksh + 128 * LPAD;
    __shared__ float colsum[2][128];

    int q0 = blockIdx.x * 128, k0 = blockIdx.y * 128, b = blockIdx.z;
    int t = threadIdx.x, wid = t >> 5, l = t & 31;
    int wm = wid >> 2, wn = wid & 3;

    // stage: 128 rows x 48 bf16 (6 uint4 per row) per matrix
    {
        const __nv_bfloat16* sq = g_Qh + (size_t)(b * NN + q0) * CS;
        for (int i = t; i < 768; i += 256) {
            int r = i / 6, c = i % 6;
            *(uint4*)(Qsh + r * LPAD + c * 8) = *(const uint4*)(sq + r * 48 + c * 8);
        }
        sq = g_Ql + (size_t)(b * NN + q0) * CS;
        for (int i = t; i < 768; i += 256) {
            int r = i / 6, c = i % 6;
            *(uint4*)(Qsl + r * LPAD + c * 8) = *(const uint4*)(sq + r * 48 + c * 8);
        }
        sq = g_Kh + (size_t)(b * NN + k0) * CS;
        for (int i = t; i < 768; i += 256) {
            int r = i / 6, c = i % 6;
            *(uint4*)(Ksh + r * LPAD + c * 8) = *(const uint4*)(sq + r * 48 + c * 8);
        }
        sq = g_Kl + (size_t)(b * NN + k0) * CS;
        for (int i = t; i < 768; i += 256) {
            int r = i / 6, c = i % 6;
            *(uint4*)(Ksl + r * LPAD + c * 8) = *(const uint4*)(sq + r * 48 + c * 8);
        }
    }
    __syncthreads();

    float acc[4][4][4];
#pragma unroll
    for (int mf = 0; mf < 4; mf++)
#pragma unroll
        for (int nf = 0; nf < 4; nf++)
#pragma unroll
            for (int c = 0; c < 4; c++) acc[mf][nf][c] = 0.f;

    int lr = l >> 2, lc = (l & 3) * 2;
#pragma unroll
    for (int ks = 0; ks < 3; ks++) {
        int koff = ks * 16;
        uint32_t bh[4][2], bl[4][2];
#pragma unroll
        for (int nf = 0; nf < 4; nf++) {
            int nb = wn * 32 + nf * 8 + lr;
            bh[nf][0] = *(const uint32_t*)&Ksh[nb * LPAD + koff + lc];
            bh[nf][1] = *(const uint32_t*)&Ksh[nb * LPAD + koff + lc + 8];
            bl[nf][0] = *(const uint32_t*)&Ksl[nb * LPAD + koff + lc];
            bl[nf][1] = *(const uint32_t*)&Ksl[nb * LPAD + koff + lc + 8];
        }
#pragma unroll
        for (int mf = 0; mf < 4; mf++) {
            int mb = wm * 64 + mf * 16;
            uint32_t ah[4], al[4];
            ah[0] = *(const uint32_t*)&Qsh[(mb + lr) * LPAD + koff + lc];
            ah[1] = *(const uint32_t*)&Qsh[(mb + 8 + lr) * LPAD + koff + lc];
            ah[2] = *(const uint32_t*)&Qsh[(mb + lr) * LPAD + koff + lc + 8];
            ah[3] = *(const uint32_t*)&Qsh[(mb + 8 + lr) * LPAD + koff + lc + 8];
            al[0] = *(const uint32_t*)&Qsl[(mb + lr) * LPAD + koff + lc];
            al[1] = *(const uint32_t*)&Qsl[(mb + 8 + lr) * LPAD + koff + lc];
            al[2] = *(const uint32_t*)&Qsl[(mb + lr) * LPAD + koff + lc + 8];
            al[3] = *(const uint32_t*)&Qsl[(mb + 8 + lr) * LPAD + koff + lc + 8];
#pragma unroll
            for (int nf = 0; nf < 4; nf++) {
                mma16816(acc[mf][nf], ah, bh[nf]);
                mma16816(acc[mf][nf], ah, bl[nf]);
                mma16816(acc[mf][nf], al, bh[nf]);
            }
        }
    }

    // epilogue: exp, store, column sums over q
    float s0[4] = {0.f, 0.f, 0.f, 0.f}, s1[4] = {0.f, 0.f, 0.f, 0.f};
#pragma unroll
    for (int mf = 0; mf < 4; mf++) {
        int r = q0 + wm * 64 + mf * 16 + lr;
#pragma unroll
        for (int nf = 0; nf < 4; nf++) {
            int col = k0 + wn * 32 + nf * 8 + lc;
            float e0 = __expf(acc[mf][nf][0] * SCALE);
            float e1 = __expf(acc[mf][nf][1] * SCALE);
            float e2 = __expf(acc[mf][nf][2] * SCALE);
            float e3 = __expf(acc[mf][nf][3] * SCALE);
            *(float2*)&g_L[((size_t)b * NN + r) * NN + col]     = make_float2(e0, e1);
            *(float2*)&g_L[((size_t)b * NN + r + 8) * NN + col] = make_float2(e2, e3);
            s0[nf] += e0 + e2;
            s1[nf] += e1 + e3;
        }
    }
#pragma unroll
    for (int nf = 0; nf < 4; nf++) {
#pragma unroll
        for (int o = 4; o <= 16; o <<= 1) {
            s0[nf] += __shfl_xor_sync(0xffffffffu, s0[nf], o);
            s1[nf] += __shfl_xor_sync(0xffffffffu, s1[nf], o);
        }
        if (lr == 0) {
            int col = wn * 32 + nf * 8 + l * 2;   // l in 0..3 here
            colsum[wm][col]     = s0[nf];
            colsum[wm][col + 1] = s1[nf];
        }
    }
    __syncthreads();
    if (t < 128)
        g_psum[(b * 32 + blockIdx.x) * NN + k0 + t] = colsum[0][t] + colsum[1][t];
}

// ---------------- vprime: fold 1/colsum into V, transpose, bf16 split -------
__global__ __launch_bounds__(256) void k_vprime() {
    int t = threadIdx.x;
    int k = blockIdx.x * 256 + t, b = blockIdx.y;
    float s = 0.f;
#pragma unroll
    for (int i = 0; i < 32; i++) s += g_psum[(b * 32 + i) * NN + k];
    float iz = 1.f / s;
    const float* v = g_V + (size_t)(b * NN + k) * CS;
#pragma unroll
    for (int d = 0; d < CS; d++) {
        float val = v[d] * iz;
        __nv_bfloat16 h = __float2bfloat16(val);
        g_Vth[(b * CS + d) * NN + k] = h;
        g_Vtl[(b * CS + d) * NN + k] = __float2bfloat16(val - __bfloat162float(h));
    }
}

// ---------------- AV MMA: Xp[c][b][q][d] = sum_{k in chunk} P[q][k] V'[k][d]
// Block: 128q x 48d, k-chunk 1024 (8 subtiles of 128). 8 warps (4 m x 2 n).
#define APAD 136
#define AV_SMEM ((2 * 128 * APAD + 2 * 48 * APAD) * 2)
__global__ __launch_bounds__(256, 2) void k_av_mma() {
    extern __shared__ __align__(16) unsigned char dsm[];
    __nv_bfloat16* Ah = (__nv_bfloat16*)dsm;
    __nv_bfloat16* Al = Ah + 128 * APAD;
    __nv_bfloat16* Bh = Al + 128 * APAD;
    __nv_bfloat16* Bl = Bh + 48 * APAD;

    int q0 = blockIdx.x * 128, cz = blockIdx.y, b = blockIdx.z;
    int ck0 = cz * 1024;
    int t = threadIdx.x, wid = t >> 5, l = t & 31;
    int wm = wid >> 1, wn = wid & 1;
    int lr = l >> 2, lc = (l & 3) * 2;

    float acc[2][3][4];
#pragma unroll
    for (int mf = 0; mf < 2; mf++)
#pragma unroll
        for (int nf = 0; nf < 3; nf++)
#pragma unroll
            for (int c = 0; c < 4; c++) acc[mf][nf][c] = 0.f;

    for (int st = 0; st < 8; st++) {
        __syncthreads();
        int kbase = ck0 + st * 128;
        // stage A: L[q0..+127][kbase..+127] fp32 -> bf16 h/l
        {
            int r = t >> 1, half = t & 1;
            const float* src = &g_L[((size_t)b * NN + q0 + r) * NN + kbase];
#pragma unroll
            for (int j = 0; j < 16; j++) {
                int cc = half * 16 + j;
                float4 x = *(const float4*)&src[cc * 4];
                __nv_bfloat16 h0 = __float2bfloat16(x.x);
                __nv_bfloat16 h1 = __float2bfloat16(x.y);
                __nv_bfloat16 h2 = __float2bfloat16(x.z);
                __nv_bfloat16 h3 = __float2bfloat16(x.w);
                *(uint2*)(Ah + r * APAD + cc * 4) =
                    make_uint2(bf2u(h0, h1), bf2u(h2, h3));
                *(uint2*)(Al + r * APAD + cc * 4) = make_uint2(
                    bf2u(__float2bfloat16(x.x - __bfloat162float(h0)),
                         __float2bfloat16(x.y - __bfloat162float(h1))),
                    bf2u(__float2bfloat16(x.z - __bfloat162float(h2)),
                         __float2bfloat16(x.w - __bfloat162float(h3))));
            }
        }
        // stage B: Vth/Vtl[b][d][kbase..+127]
        for (int i = t; i < 1536; i += 256) {
            int m = i / 768, j = i % 768;
            int d = j / 16, sg = j % 16;
            const __nv_bfloat16* src = (m ? g_Vtl : g_Vth) + (size_t)(b * CS + d) * NN + kbase + sg * 8;
            __nv_bfloat16* dst = (m ? Bl : Bh) + d * APAD + sg * 8;
            *(uint4*)dst = *(const uint4*)src;
        }
        __syncthreads();

#pragma unroll
        for (int ksi = 0; ksi < 8; ksi++) {
            int koff = ksi * 16;
            uint32_t bh[3][2], bl[3][2];
#pragma unroll
            for (int nf = 0; nf < 3; nf++) {
                int nb = wn * 24 + nf * 8 + lr;
                bh[nf][0] = *(const uint32_t*)&Bh[nb * APAD + koff + lc];
                bh[nf][1] = *(const uint32_t*)&Bh[nb * APAD + koff + lc + 8];
                bl[nf][0] = *(const uint32_t*)&Bl[nb * APAD + koff + lc];
                bl[nf][1] = *(const uint32_t*)&Bl[nb * APAD + koff + lc + 8];
            }
#pragma unroll
            for (int mf = 0; mf < 2; mf++) {
                int mb = wm * 32 + mf * 16;
                uint32_t ah[4], al[4];
                ah[0] = *(const uint32_t*)&Ah[(mb + lr) * APAD + koff + lc];
                ah[1] = *(const uint32_t*)&Ah[(mb + 8 + lr) * APAD + koff + lc];
                ah[2] = *(const uint32_t*)&Ah[(mb + lr) * APAD + koff + lc + 8];
                ah[3] = *(const uint32_t*)&Ah[(mb + 8 + lr) * APAD + koff + lc + 8];
                al[0] = *(const uint32_t*)&Al[(mb + lr) * APAD + koff + lc];
                al[1] = *(const uint32_t*)&Al[(mb + 8 + lr) * APAD + koff + lc];
                al[2] = *(const uint32_t*)&Al[(mb + lr) * APAD + koff + lc + 8];
                al[3] = *(const uint32_t*)&Al[(mb + 8 + lr) * APAD + koff + lc + 8];
#pragma unroll
                for (int nf = 0; nf < 3; nf++) {
                    mma16816(acc[mf][nf], ah, bh[nf]);
                    mma16816(acc[mf][nf], ah, bl[nf]);
                    mma16816(acc[mf][nf], al, bh[nf]);
                }
            }
        }
    }

#pragma unroll
    for (int mf = 0; mf < 2; mf++) {
        int r = q0 + wm * 32 + mf * 16 + lr;
#pragma unroll
        for (int nf = 0; nf < 3; nf++) {
            int col = wn * 24 + nf * 8 + lc;
            float* base = &g_Xp[((size_t)(cz * BB + b) * NN + r) * CS + col];
            *(float2*)base = make_float2(acc[mf][nf][0], acc[mf][nf][1]);
            *(float2*)(base + 8 * CS) = make_float2(acc[mf][nf][2], acc[mf][nf][3]);
        }
    }
}

// ---------------- conv3d 3x3x3 (96 -> 96), SAME, f32x2, ci-split-2 ---------
__global__ __launch_bounds__(256) void k_conv3d(const float* __restrict__ w3) {
    __shared__ __align__(16) float in_s[3 * 18 * 18];
    __shared__ __align__(16) float ws[27][16];

    int cog = blockIdx.x, d = blockIdx.y;
    int b = blockIdx.z >> 1, half = blockIdx.z & 1;
    int t = threadIdx.x, h = t >> 4, w = t & 15;

    unsigned long long acc[8];
#pragma unroll
    for (int j = 0; j < 8; j++) acc[j] = 0ull;

    for (int ci0 = 0; ci0 < 48; ci0++) {
        int ci = half * 48 + ci0;
        const float* src = g_Ype + (size_t)(b * CY + ci) * NN;
        for (int i = t; i < 3 * 324; i += 256) {
            int dd = i / 324, rem = i - dd * 324, r = rem / 18, c = rem - r * 18;
            int z = d + dd - 1, y = r - 1, x = c - 1;
            float v = 0.f;
            if (z >= 0 && z < 16 && y >= 0 && y < 16 && x >= 0 && x < 16)
                v = src[z * 256 + y * 16 + x];
            in_s[i] = v;
        }
        for (int i = t; i < 16 * 27; i += 256) {
            int tap = i % 27, co = i / 27;
            ws[tap][co] = w3[(size_t)(cog * 16 + co) * (CY * 27) + ci * 27 + tap];
        }
        __syncthreads();

        float in_r[27];
#pragma unroll
        for (int dd = 0; dd < 3; dd++)
#pragma unroll
            for (int dy = 0; dy < 3; dy++)
#pragma unroll
                for (int dx = 0; dx < 3; dx++)
                    in_r[dd*9+dy*3+dx] = in_s[dd*324 + (h+dy)*18 + (w+dx)];

#pragma unroll
        for (int tap = 0; tap < 27; tap++) {
            unsigned long long xx;
            asm("mov.b64 %0, {%1, %1};" : "=l"(xx) : "f"(in_r[tap]));
#pragma unroll
            for (int j = 0; j < 8; j++) {
                unsigned long long ww = *(const unsigned long long*)&ws[tap][2 * j];
                fma2(acc[j], xx, ww);
            }
        }
        __syncthreads();
    }
    int n = d * 256 + t;
    float* dst = g_Y3p + (size_t)half * (BB * CY * NN) + (size_t)(b * CY + cog * 16) * NN + n;
#pragma unroll
    for (int j = 0; j < 8; j++) {
        float lo, hi;
        asm("mov.b64 {%0, %1}, %2;" : "=f"(lo), "=f"(hi) : "l"(acc[j]));
        dst[(2 * j) * NN]     = lo;
        dst[(2 * j + 1) * NN] = hi;
    }
}

// ---------------- Z output: bn_relu(X @ w_o) * Spe -> out[:, 0:48] ---------
__global__ __launch_bounds__(256) void k_zout(
    const float* __restrict__ w_o, const float* __restrict__ b_o,
    const float* __restrict__ g_o, const float* __restrict__ be_o,
    float* __restrict__ out)
{
    __shared__ float xs[CS * 64];
    __shared__ float wot[CS * CS];

    int b = blockIdx.y, n0 = blockIdx.x * 64, t = threadIdx.x;
    for (int i = t; i < CS * CS; i += 256) {
        int e = i % CS, d = i / CS;
        wot[i] = w_o[e * CS + d];
    }
    {
        int n = t & 63, v = t >> 6;
        const size_t cstride = (size_t)BB * NN * CS;
        const float* src = g_Xp + (size_t)(b * NN + n0 + n) * CS;
#pragma unroll
        for (int r = 0; r < 3; r++) {
            int dv = v + r * 4;
            float4 x = *(const float4*)&src[dv * 4];
            float4 x1 = *(const float4*)&src[cstride + dv * 4];
            float4 x2 = *(const float4*)&src[2 * cstride + dv * 4];
            float4 x3 = *(const float4*)&src[3 * cstride + dv * 4];
            x.x += x1.x + x2.x + x3.x;
            x.y += x1.y + x2.y + x3.y;
            x.z += x1.z + x2.z + x3.z;
            x.w += x1.w + x2.w + x3.w;
            xs[(dv*4+0)*64+n] = x.x; xs[(dv*4+1)*64+n] = x.y;
            xs[(dv*4+2)*64+n] = x.z; xs[(dv*4+3)*64+n] = x.w;
        }
    }
    __syncthreads();

    int n = t & 63, eg = t >> 6;
    float acc[12];
#pragma unroll
    for (int j = 0; j < 12; j++) acc[j] = 0.f;
    for (int d = 0; d < CS; d++) {
        float x = xs[d * 64 + n];
#pragma unroll
        for (int v = 0; v < 3; v++) {
            float4 w4 = *(const float4*)&wot[d * CS + eg * 12 + v * 4];
            acc[v*4+0] += w4.x * x; acc[v*4+1] += w4.y * x;
            acc[v*4+2] += w4.z * x; acc[v*4+3] += w4.w * x;
        }
    }
    float inv = rsqrtf(1.f + 1e-5f);
#pragma unroll
    for (int j = 0; j < 12; j++) {
        int e = eg * 12 + j;
        float y = (acc[j] + b_o[e]) * (g_o[e] * inv) + be_o[e];
        y = fmaxf(y, 0.f);
        out[(b * 96 + e) * NN + n0 + n] = y * g_Spe[(b * CS + e) * NN + n0 + n];
    }
}

// ---------------- Y2 output: bn_relu((Y3p0+Y3p1+b3) @ w_y2) -> out[:,48:96] -
__global__ __launch_bounds__(256) void k_y2out(
    const float* __restrict__ w_y2, const float* __restrict__ b_y2,
    const float* __restrict__ g_y2, const float* __restrict__ be_y2,
    const float* __restrict__ b3, float* __restrict__ out)
{
    __shared__ float in_s[CY * 64];
    __shared__ float wt[CY * CS];

    int b = blockIdx.y, n0 = blockIdx.x * 64, t = threadIdx.x;
    for (int i = t; i < CY * CS; i += 256) {
        int e = i % CS, c = i / CS;
        wt[i] = w_y2[e * CY + c];
    }
    const size_t hstride = (size_t)BB * CY * NN;
    const float* src = g_Y3p + (size_t)(b * CY) * NN + n0;
    for (int i = t; i < CY * 64; i += 256) {
        int c = i >> 6, n = i & 63;
        in_s[i] = src[c * NN + n] + src[hstride + c * NN + n] + b3[c];
    }
    __syncthreads();

    int n = t & 63, eg = t >> 6;
    float acc[12];
#pragma unroll
    for (int j = 0; j < 12; j++) acc[j] = 0.f;
    for (int c = 0; c < CY; c++) {
        float x = in_s[c * 64 + n];
#pragma unroll
        for (int v = 0; v < 3; v++) {
            float4 w4 = *(const float4*)&wt[c * CS + eg * 12 + v * 4];
            acc[v*4+0] += w4.x * x; acc[v*4+1] += w4.y * x;
            acc[v*4+2] += w4.z * x; acc[v*4+3] += w4.w * x;
        }
    }
    float inv = rsqrtf(1.f + 1e-5f);
#pragma unroll
    for (int j = 0; j < 12; j++) {
        int e = eg * 12 + j;
        float y = (acc[j] + b_y2[e]) * (g_y2[e] * inv) + be_y2[e];
        out[(b * 96 + 48 + e) * NN + n0 + n] = fmaxf(y, 0.f);
    }
}

// ---------------- launch ----------------------------------------------------
extern "C" void kernel_launch(void* const* d_in, const int* in_sizes, int n_in,
                              void* d_out, int out_size)
{
    const float* Y    = (const float*)d_in[0];
    const float* S    = (const float*)d_in[1];
    const float* w_s  = (const float*)d_in[2];
    const float* b_s  = (const float*)d_in[3];
    const float* g_s  = (const float*)d_in[4];
    const float* be_s = (const float*)d_in[5];
    const float* w_y  = (const float*)d_in[6];
    const float* b_y  = (const float*)d_in[7];
    const float* g_y  = (const float*)d_in[8];
    const float* be_y = (const float*)d_in[9];
    const float* Wq   = (const float*)d_in[10];
    const float* Wk   = (const float*)d_in[11];
    const float* Wv   = (const float*)d_in[12];
    const float* w_o  = (const float*)d_in[13];
    const float* b_o  = (const float*)d_in[14];
    const float* g_o  = (const float*)d_in[15];
    const float* be_o = (const float*)d_in[16];
    const float* w3   = (const float*)d_in[17];
    const float* b3   = (const float*)d_in[18];
    const float* w_y2 = (const float*)d_in[19];
    const float* b_y2 = (const float*)d_in[20];
    const float* g_y2 = (const float*)d_in[21];
    const float* be_y2= (const float*)d_in[22];
    float* out = (float*)d_out;

    static int attr_done = 0;
    if (!attr_done) {
        cudaFuncSetAttribute(k_logits_mma,
            cudaFuncAttributeMaxDynamicSharedMemorySize, LOGITS_SMEM);
        cudaFuncSetAttribute(k_av_mma,
            cudaFuncAttributeMaxDynamicSharedMemorySize, AV_SMEM);
        attr_done = 1;
    }

    k_petab<<<144, 256>>>();
    k_addpe_s<<<BB*CS*NN/1024, 256>>>(S);
    k_addpe_y<<<BB*CY*NN/1024, 256>>>(Y);

    k_proj_sv<<<dim3(NN/64, BB), 256>>>(w_s, b_s, g_s, be_s, Wv);
    k_proj_y1<<<dim3(NN/64, BB), 256>>>(w_y, b_y, g_y, be_y);
    k_qk     <<<dim3(NN/64, BB), 256>>>(Wq, Wk);

    k_logits_mma<<<dim3(32, 32, BB), 256, LOGITS_SMEM>>>();
    k_vprime    <<<dim3(16, BB), 256>>>();
    k_av_mma    <<<dim3(32, 4, BB), 256, AV_SMEM>>>();

    k_conv3d<<<dim3(CY/16, 16, BB*2), 256>>>(w3);

    k_zout <<<dim3(NN/64, BB), 256>>>(w_o, b_o, g_o, be_o, out);
    k_y2out<<<dim3(NN/64, BB), 256>>>(w_y2, b_y2, g_y2, be_y2, b3, out);
}

// round 7
// speedup vs baseline: 1.0499x; 1.0499x over previous
#include <cuda_runtime.h>
#include <cuda_bf16.h>
#include <math.h>
#include <stdint.h>

#define BB 2
#define CY 96
#define CS 48
#define NN 4096
#define SCALE 0.14433756729740643f  /* 48^-0.5 */

// ---------------- scratch ----------------------------------------------------
__device__ __align__(16) float g_Ype[BB*CY*NN];
__device__ __align__(16) float g_V  [BB*NN*CS];
__device__ __align__(16) __nv_bfloat16 g_Qh[BB*NN*CS], g_Ql[BB*NN*CS];
__device__ __align__(16) __nv_bfloat16 g_Kh[BB*NN*CS], g_Kl[BB*NN*CS];
__device__ __align__(16) __nv_bfloat16 g_Vth[BB*CS*NN], g_Vtl[BB*CS*NN];
__device__ __align__(16) float g_psum[BB*2*NN];
__device__ __align__(16) float g_Xp[4*BB*NN*CS];
__device__ __align__(16) float g_Y3p[3*BB*CY*NN];
__device__ __align__(16) float g_peS[CS*256];
__device__ __align__(16) float g_peY[CY*256];

// ---------------- helpers ----------------------------------------------------
__device__ __forceinline__ void mma16816(float* c, const uint32_t* a, const uint32_t* b) {
    asm volatile(
        "mma.sync.aligned.m16n8k16.row.col.f32.bf16.bf16.f32 "
        "{%0,%1,%2,%3}, {%4,%5,%6,%7}, {%8,%9}, {%0,%1,%2,%3};\n"
        : "+f"(c[0]), "+f"(c[1]), "+f"(c[2]), "+f"(c[3])
        : "r"(a[0]), "r"(a[1]), "r"(a[2]), "r"(a[3]), "r"(b[0]), "r"(b[1]));
}
__device__ __forceinline__ uint32_t bf2u(__nv_bfloat16 a, __nv_bfloat16 b) {
    __nv_bfloat162 v(a, b);
    return *reinterpret_cast<uint32_t*>(&v);
}
__device__ __forceinline__ void fma2(unsigned long long& d, unsigned long long a,
                                     unsigned long long b) {
    asm("fma.rn.f32x2 %0, %1, %2, %0;" : "+l"(d) : "l"(a), "l"(b));
}

// ---------------- PE tables --------------------------------------------------
__device__ __forceinline__ float pe_val(int ch, int h, int w, int c) {
    int blk = ch / c, t = ch - blk * c;
    int pos = (blk < 2) ? h : w;    // torch broadcast quirk
    int half = c >> 1;
    if (t < half) {
        float invf = powf(10000.f, -2.f * (float)t / (float)c);
        return sinf((float)pos * invf);
    } else {
        float invf = powf(10000.f, -2.f * (float)(t - half) / (float)c);
        return cosf((float)pos * invf);
    }
}
__global__ void k_petab() {
    int i = blockIdx.x * 256 + threadIdx.x;
    if (i < CY * 256) {
        int ch = i >> 8, n = i & 255;
        g_peY[i] = pe_val(ch, n >> 4, n & 15, 32);
    } else {
        int j = i - CY * 256;
        if (j < CS * 256) {
            int ch = j >> 8, n = j & 255;
            g_peS[j] = pe_val(ch, n >> 4, n & 15, 16);
        }
    }
}

// ============================================================================
// FUSE1: [0,768) addpe_y | [768,896) proj_sv->V | [896,1024) proj_y1+QK
// ============================================================================
#define FUSE1_SMEM 55552
__global__ __launch_bounds__(256) void k_fuse1(
    const float* __restrict__ Y, const float* __restrict__ S,
    const float* __restrict__ w_s, const float* __restrict__ b_s,
    const float* __restrict__ g_s, const float* __restrict__ be_s,
    const float* __restrict__ Wv,
    const float* __restrict__ w_y, const float* __restrict__ b_y,
    const float* __restrict__ g_y, const float* __restrict__ be_y,
    const float* __restrict__ Wq, const float* __restrict__ Wk)
{
    extern __shared__ __align__(16) float pool[];
    int bx = blockIdx.x, t = threadIdx.x;

    if (bx < 768) {
        int i = (bx * 256 + t) * 4;
        int n = i & (NN - 1);
        int ch = (i >> 12) % CY;
        float4 s = *(const float4*)&Y[i];
        float4 p = *(const float4*)&g_peY[ch * 256 + (n & 255)];
        s.x += p.x; s.y += p.y; s.z += p.z; s.w += p.w;
        *(float4*)&g_Ype[i] = s;
        return;
    }

    if (bx < 896) {
        int j = bx - 768;
        int n0 = (j & 63) * 64, b = j >> 6;
        float* in_s = pool;
        float* wt   = pool + 3072;
        float* wv   = pool + 5376;
        float* s1   = pool + 7680;

        for (int i = t; i < CS * CS; i += 256) {
            int e = i % CS, c = i / CS;
            wt[i] = w_s[e * CS + c];
            wv[i] = Wv[i];
        }
        for (int i = t; i < CS * 64; i += 256) {
            int c = i >> 6, nl = i & 63;
            in_s[i] = S[(b * CS + c) * NN + n0 + nl]
                    + g_peS[c * 256 + ((n0 + nl) & 255)];
        }
        __syncthreads();

        int n = t & 63, eg = t >> 6;
        float acc[12];
#pragma unroll
        for (int k = 0; k < 12; k++) acc[k] = 0.f;
        for (int c = 0; c < CS; c++) {
            float x = in_s[c * 64 + n];
#pragma unroll
            for (int v = 0; v < 3; v++) {
                float4 w4 = *(const float4*)&wt[c * CS + eg * 12 + v * 4];
                acc[v*4+0] += w4.x * x; acc[v*4+1] += w4.y * x;
                acc[v*4+2] += w4.z * x; acc[v*4+3] += w4.w * x;
            }
        }
        float inv = rsqrtf(1.f + 1e-5f);
#pragma unroll
        for (int k = 0; k < 12; k++) {
            int e = eg * 12 + k;
            float y = (acc[k] + b_s[e]) * (g_s[e] * inv) + be_s[e];
            s1[n * 49 + e] = fmaxf(y, 0.f);
        }
        __syncthreads();

#pragma unroll
        for (int k = 0; k < 12; k++) acc[k] = 0.f;
        for (int d = 0; d < CS; d++) {
            float x = s1[n * 49 + d];
#pragma unroll
            for (int v = 0; v < 3; v++) {
                float4 w4 = *(const float4*)&wv[d * CS + eg * 12 + v * 4];
                acc[v*4+0] += w4.x * x; acc[v*4+1] += w4.y * x;
                acc[v*4+2] += w4.z * x; acc[v*4+3] += w4.w * x;
            }
        }
        float* dst = g_V + ((b * NN + n0 + n) * CS) + eg * 12;
#pragma unroll
        for (int v = 0; v < 3; v++)
            *(float4*)&dst[v * 4] = make_float4(acc[v*4], acc[v*4+1], acc[v*4+2], acc[v*4+3]);
        return;
    }

    {   // proj_y1 + QK fused; Y1 lives only in smem
        int j = bx - 896;
        int n0 = (j & 63) * 64, b = j >> 6;
        float* in_s = pool;            // [96][64]
        float* wt   = pool + 6144;     // [c][e]
        float* s1   = pool + 10752;    // [n][49]

        for (int i = t; i < CY * CS; i += 256) {
            int e = i % CS, c = i / CS;
            wt[i] = w_y[e * CY + c];
        }
        for (int i = t; i < CY * 64; i += 256) {
            int c = i >> 6, nl = i & 63;
            in_s[i] = Y[(b * CY + c) * NN + n0 + nl]
                    + g_peY[c * 256 + ((n0 + nl) & 255)];
        }
        __syncthreads();

        int n = t & 63, eg = t >> 6;
        float acc[12];
#pragma unroll
        for (int k = 0; k < 12; k++) acc[k] = 0.f;
        for (int c = 0; c < CY; c++) {
            float x = in_s[c * 64 + n];
#pragma unroll
            for (int v = 0; v < 3; v++) {
                float4 w4 = *(const float4*)&wt[c * CS + eg * 12 + v * 4];
                acc[v*4+0] += w4.x * x; acc[v*4+1] += w4.y * x;
                acc[v*4+2] += w4.z * x; acc[v*4+3] += w4.w * x;
            }
        }
        float inv = rsqrtf(1.f + 1e-5f);
#pragma unroll
        for (int k = 0; k < 12; k++) {
            int e = eg * 12 + k;
            float y = (acc[k] + b_y[e]) * (g_y[e] * inv) + be_y[e];
            s1[n * 49 + e] = fmaxf(y, 0.f);
        }
        __syncthreads();

        float* wq = pool;
        float* wk = pool + 2304;
        for (int i = t; i < CS * CS; i += 256) { wq[i] = Wq[i]; wk[i] = Wk[i]; }
        __syncthreads();

        float aq[12], ak[12];
#pragma unroll
        for (int k = 0; k < 12; k++) { aq[k] = 0.f; ak[k] = 0.f; }
        for (int d = 0; d < CS; d++) {
            float x = s1[n * 49 + d];
#pragma unroll
            for (int v = 0; v < 3; v++) {
                float4 q4 = *(const float4*)&wq[d * CS + eg * 12 + v * 4];
                float4 k4 = *(const float4*)&wk[d * CS + eg * 12 + v * 4];
                aq[v*4+0] += q4.x * x; aq[v*4+1] += q4.y * x;
                aq[v*4+2] += q4.z * x; aq[v*4+3] += q4.w * x;
                ak[v*4+0] += k4.x * x; ak[v*4+1] += k4.y * x;
                ak[v*4+2] += k4.z * x; ak[v*4+3] += k4.w * x;
            }
        }
        int base = (b * NN + n0 + n) * CS + eg * 12;
#pragma unroll
        for (int k = 0; k < 12; k++) {
            __nv_bfloat16 qh = __float2bfloat16(aq[k]);
            __nv_bfloat16 kh = __float2bfloat16(ak[k]);
            g_Qh[base + k] = qh;
            g_Ql[base + k] = __float2bfloat16(aq[k] - __bfloat162float(qh));
            g_Kh[base + k] = kh;
            g_Kl[base + k] = __float2bfloat16(ak[k] - __bfloat162float(kh));
        }
    }
}

// ============================================================================
// Pass 1: column sums via A=K, B=Q MMA (softmax-axis sum = register row sum)
// grid (32, 2, BB); smem 4x [128][56] bf16 = 57344 B
// ============================================================================
#define CS_SMEM 57344
__global__ __launch_bounds__(256) void k_colsum() {
    extern __shared__ __align__(16) unsigned char dsm[];
    __nv_bfloat16* KH = (__nv_bfloat16*)dsm;
    __nv_bfloat16* KL = KH + 7168;
    __nv_bfloat16* QH = KH + 14336;
    __nv_bfloat16* QL = KH + 21504;

    int k0 = blockIdx.x * 128, qh = blockIdx.y, b = blockIdx.z;
    int t = threadIdx.x, wid = t >> 5, l = t & 31;
    int lr = l >> 2, lc = (l & 3) * 2;
    int mb = wid * 16;

    {
        const __nv_bfloat16* s = g_Kh + (size_t)(b * NN + k0) * CS;
        for (int i = t; i < 768; i += 256) {
            int r = i / 6, c = i % 6;
            *(uint4*)(KH + r * 56 + c * 8) = *(const uint4*)(s + r * 48 + c * 8);
        }
        s = g_Kl + (size_t)(b * NN + k0) * CS;
        for (int i = t; i < 768; i += 256) {
            int r = i / 6, c = i % 6;
            *(uint4*)(KL + r * 56 + c * 8) = *(const uint4*)(s + r * 48 + c * 8);
        }
    }
    __syncthreads();

    uint32_t kfh[3][4], kfl[3][4];
#pragma unroll
    for (int ks = 0; ks < 3; ks++) {
        int ko = ks * 16;
        kfh[ks][0] = *(uint32_t*)&KH[(mb + lr) * 56 + ko + lc];
        kfh[ks][1] = *(uint32_t*)&KH[(mb + 8 + lr) * 56 + ko + lc];
        kfh[ks][2] = *(uint32_t*)&KH[(mb + lr) * 56 + ko + lc + 8];
        kfh[ks][3] = *(uint32_t*)&KH[(mb + 8 + lr) * 56 + ko + lc + 8];
        kfl[ks][0] = *(uint32_t*)&KL[(mb + lr) * 56 + ko + lc];
        kfl[ks][1] = *(uint32_t*)&KL[(mb + 8 + lr) * 56 + ko + lc];
        kfl[ks][2] = *(uint32_t*)&KL[(mb + lr) * 56 + ko + lc + 8];
        kfl[ks][3] = *(uint32_t*)&KL[(mb + 8 + lr) * 56 + ko + lc + 8];
    }

    float rs0 = 0.f, rs1 = 0.f;
    for (int ch = 0; ch < 16; ch++) {
        int qb = qh * 2048 + ch * 128;
        __syncthreads();
        {
            const __nv_bfloat16* s = g_Qh + (size_t)(b * NN + qb) * CS;
            for (int i = t; i < 768; i += 256) {
                int r = i / 6, c = i % 6;
                *(uint4*)(QH + r * 56 + c * 8) = *(const uint4*)(s + r * 48 + c * 8);
            }
            s = g_Ql + (size_t)(b * NN + qb) * CS;
            for (int i = t; i < 768; i += 256) {
                int r = i / 6, c = i % 6;
                *(uint4*)(QL + r * 56 + c * 8) = *(const uint4*)(s + r * 48 + c * 8);
            }
        }
        __syncthreads();

#pragma unroll
        for (int nfp = 0; nfp < 8; nfp++) {
            float a0[4] = {0.f,0.f,0.f,0.f}, a1[4] = {0.f,0.f,0.f,0.f};
#pragma unroll
            for (int ks = 0; ks < 3; ks++) {
                int ko = ks * 16;
                int i0 = (nfp * 16 + lr) * 56 + ko + lc;
                int i1 = i0 + 8 * 56;
                uint32_t bh0[2] = { *(uint32_t*)&QH[i0], *(uint32_t*)&QH[i0 + 8] };
                uint32_t bl0[2] = { *(uint32_t*)&QL[i0], *(uint32_t*)&QL[i0 + 8] };
                uint32_t bh1[2] = { *(uint32_t*)&QH[i1], *(uint32_t*)&QH[i1 + 8] };
                uint32_t bl1[2] = { *(uint32_t*)&QL[i1], *(uint32_t*)&QL[i1 + 8] };
                mma16816(a0, kfh[ks], bh0); mma16816(a0, kfl[ks], bh0); mma16816(a0, kfh[ks], bl0);
                mma16816(a1, kfh[ks], bh1); mma16816(a1, kfl[ks], bh1); mma16816(a1, kfh[ks], bl1);
            }
            rs0 += __expf(a0[0] * SCALE) + __expf(a0[1] * SCALE)
                 + __expf(a1[0] * SCALE) + __expf(a1[1] * SCALE);
            rs1 += __expf(a0[2] * SCALE) + __expf(a0[3] * SCALE)
                 + __expf(a1[2] * SCALE) + __expf(a1[3] * SCALE);
        }
    }
    rs0 += __shfl_xor_sync(0xffffffffu, rs0, 1);
    rs0 += __shfl_xor_sync(0xffffffffu, rs0, 2);
    rs1 += __shfl_xor_sync(0xffffffffu, rs1, 1);
    rs1 += __shfl_xor_sync(0xffffffffu, rs1, 2);
    if ((l & 3) == 0) {
        g_psum[(b * 2 + qh) * NN + k0 + mb + lr]     = rs0;
        g_psum[(b * 2 + qh) * NN + k0 + mb + 8 + lr] = rs1;
    }
}

// ============================================================================
// vprime: V' = V / colsum, transposed [d][k], bf16 hi/lo. grid (64, BB).
// ============================================================================
__global__ __launch_bounds__(256) void k_vprime() {
    __shared__ float iz_s[64];
    __shared__ __nv_bfloat16 Th[48 * 66], Tl[48 * 66];

    int k0 = blockIdx.x * 64, b = blockIdx.y, t = threadIdx.x;
    if (t < 64) {
        int k = k0 + t;
        iz_s[t] = 1.f / (g_psum[(b * 2) * NN + k] + g_psum[(b * 2 + 1) * NN + k]);
    }
    __syncthreads();

    const float* vsrc = g_V + (size_t)(b * NN + k0) * CS;
    for (int i = t; i < 64 * CS; i += 256) {
        int kk = i / CS, d = i - kk * CS;
        float val = vsrc[i] * iz_s[kk];
        __nv_bfloat16 h = __float2bfloat16(val);
        Th[d * 66 + kk] = h;
        Tl[d * 66 + kk] = __float2bfloat16(val - __bfloat162float(h));
    }
    __syncthreads();

    for (int j = t; j < 48 * 32; j += 256) {
        int d = j >> 5, c2 = (j & 31) * 2;
        *(uint32_t*)&g_Vth[(size_t)(b * CS + d) * NN + k0 + c2] =
            bf2u(Th[d * 66 + c2], Th[d * 66 + c2 + 1]);
        *(uint32_t*)&g_Vtl[(size_t)(b * CS + d) * NN + k0 + c2] =
            bf2u(Tl[d * 66 + c2], Tl[d * 66 + c2 + 1]);
    }
}

// ============================================================================
// FUSE3: [0,256) flash pass2 (P as A-fragments, no P smem) | [256,832) conv3d
// ============================================================================
#define F3_SMEM 83456
__global__ __launch_bounds__(256) void k_fuse3(const float* __restrict__ w3) {
    extern __shared__ __align__(16) unsigned char dsm[];
    int bx = blockIdx.x, t = threadIdx.x;

    if (bx < 256) {
        int qblk = bx & 31, kq = (bx >> 5) & 3, b = bx >> 7;
        __nv_bfloat16* QH = (__nv_bfloat16*)dsm;
        __nv_bfloat16* QL = QH + 7168;
        __nv_bfloat16* KH = QH + 14336;
        __nv_bfloat16* KL = QH + 21504;
        __nv_bfloat16* VH = QH + 28672;   // [48][136]
        __nv_bfloat16* VL = QH + 35200;

        int wid = t >> 5, l = t & 31;
        int lr = l >> 2, lc = (l & 3) * 2;
        int q0 = qblk * 128, mb = wid * 16;

        {
            const __nv_bfloat16* s = g_Qh + (size_t)(b * NN + q0) * CS;
            for (int i = t; i < 768; i += 256) {
                int r = i / 6, c = i % 6;
                *(uint4*)(QH + r * 56 + c * 8) = *(const uint4*)(s + r * 48 + c * 8);
            }
            s = g_Ql + (size_t)(b * NN + q0) * CS;
            for (int i = t; i < 768; i += 256) {
                int r = i / 6, c = i % 6;
                *(uint4*)(QL + r * 56 + c * 8) = *(const uint4*)(s + r * 48 + c * 8);
            }
        }
        __syncthreads();

        uint32_t qfh[3][4], qfl[3][4];
#pragma unroll
        for (int ks = 0; ks < 3; ks++) {
            int ko = ks * 16;
            qfh[ks][0] = *(uint32_t*)&QH[(mb + lr) * 56 + ko + lc];
            qfh[ks][1] = *(uint32_t*)&QH[(mb + 8 + lr) * 56 + ko + lc];
            qfh[ks][2] = *(uint32_t*)&QH[(mb + lr) * 56 + ko + lc + 8];
            qfh[ks][3] = *(uint32_t*)&QH[(mb + 8 + lr) * 56 + ko + lc + 8];
            qfl[ks][0] = *(uint32_t*)&QL[(mb + lr) * 56 + ko + lc];
            qfl[ks][1] = *(uint32_t*)&QL[(mb + 8 + lr) * 56 + ko + lc];
            qfl[ks][2] = *(uint32_t*)&QL[(mb + lr) * 56 + ko + lc + 8];
            qfl[ks][3] = *(uint32_t*)&QL[(mb + 8 + lr) * 56 + ko + lc + 8];
        }

        float pv[6][4];
#pragma unroll
        for (int nv = 0; nv < 6; nv++)
#pragma unroll
            for (int c = 0; c < 4; c++) pv[nv][c] = 0.f;

        for (int ch = 0; ch < 8; ch++) {
            int kb = kq * 1024 + ch * 128;
            __syncthreads();
            {
                const __nv_bfloat16* s = g_Kh + (size_t)(b * NN + kb) * CS;
                for (int i = t; i < 768; i += 256) {
                    int r = i / 6, c = i % 6;
                    *(uint4*)(KH + r * 56 + c * 8) = *(const uint4*)(s + r * 48 + c * 8);
                }
                s = g_Kl + (size_t)(b * NN + kb) * CS;
                for (int i = t; i < 768; i += 256) {
                    int r = i / 6, c = i % 6;
                    *(uint4*)(KL + r * 56 + c * 8) = *(const uint4*)(s + r * 48 + c * 8);
                }
                for (int i = t; i < 768; i += 256) {
                    int r = i / 16, c = i % 16;
                    *(uint4*)(VH + r * 136 + c * 8) =
                        *(const uint4*)(g_Vth + (size_t)(b * CS + r) * NN + kb + c * 8);
                }
                for (int i = t; i < 768; i += 256) {
                    int r = i / 16, c = i % 16;
                    *(uint4*)(VL + r * 136 + c * 8) =
                        *(const uint4*)(g_Vtl + (size_t)(b * CS + r) * NN + kb + c * 8);
                }
            }
            __syncthreads();

#pragma unroll
            for (int nfp = 0; nfp < 8; nfp++) {
                float a0[4] = {0.f,0.f,0.f,0.f}, a1[4] = {0.f,0.f,0.f,0.f};
#pragma unroll
                for (int ks = 0; ks < 3; ks++) {
                    int ko = ks * 16;
                    int i0 = (nfp * 16 + lr) * 56 + ko + lc;
                    int i1 = i0 + 8 * 56;
                    uint32_t bh0[2] = { *(uint32_t*)&KH[i0], *(uint32_t*)&KH[i0 + 8] };
                    uint32_t bl0[2] = { *(uint32_t*)&KL[i0], *(uint32_t*)&KL[i0 + 8] };
                    uint32_t bh1[2] = { *(uint32_t*)&KH[i1], *(uint32_t*)&KH[i1 + 8] };
                    uint32_t bl1[2] = { *(uint32_t*)&KL[i1], *(uint32_t*)&KL[i1 + 8] };
                    mma16816(a0, qfh[ks], bh0); mma16816(a0, qfl[ks], bh0); mma16816(a0, qfh[ks], bl0);
                    mma16816(a1, qfh[ks], bh1); mma16816(a1, qfl[ks], bh1); mma16816(a1, qfh[ks], bl1);
                }
                float e0 = __expf(a0[0]*SCALE), e1 = __expf(a0[1]*SCALE);
                float e2 = __expf(a0[2]*SCALE), e3 = __expf(a0[3]*SCALE);
                float e4 = __expf(a1[0]*SCALE), e5 = __expf(a1[1]*SCALE);
                float e6 = __expf(a1[2]*SCALE), e7 = __expf(a1[3]*SCALE);
                __nv_bfloat16 h0 = __float2bfloat16(e0), h1 = __float2bfloat16(e1);
                __nv_bfloat16 h2 = __float2bfloat16(e2), h3 = __float2bfloat16(e3);
                __nv_bfloat16 h4 = __float2bfloat16(e4), h5 = __float2bfloat16(e5);
                __nv_bfloat16 h6 = __float2bfloat16(e6), h7 = __float2bfloat16(e7);
                uint32_t ph[4] = { bf2u(h0, h1), bf2u(h2, h3), bf2u(h4, h5), bf2u(h6, h7) };
                uint32_t pl[4] = {
                    bf2u(__float2bfloat16(e0 - __bfloat162float(h0)),
                         __float2bfloat16(e1 - __bfloat162float(h1))),
                    bf2u(__float2bfloat16(e2 - __bfloat162float(h2)),
                         __float2bfloat16(e3 - __bfloat162float(h3))),
                    bf2u(__float2bfloat16(e4 - __bfloat162float(h4)),
                         __float2bfloat16(e5 - __bfloat162float(h5))),
                    bf2u(__float2bfloat16(e6 - __bfloat162float(h6)),
                         __float2bfloat16(e7 - __bfloat162float(h7))) };
                int kop = nfp * 16;
#pragma unroll
                for (int nv = 0; nv < 6; nv++) {
                    int iv = (nv * 8 + lr) * 136 + kop + lc;
                    uint32_t vh[2] = { *(uint32_t*)&VH[iv], *(uint32_t*)&VH[iv + 8] };
                    uint32_t vl[2] = { *(uint32_t*)&VL[iv], *(uint32_t*)&VL[iv + 8] };
                    mma16816(pv[nv], ph, vh); mma16816(pv[nv], pl, vh); mma16816(pv[nv], ph, vl);
                }
            }
        }

#pragma unroll
        for (int nv = 0; nv < 6; nv++) {
            int r = q0 + mb + lr, col = nv * 8 + lc;
            float* base = &g_Xp[((size_t)(kq * BB + b) * NN + r) * CS + col];
            *(float2*)base = make_float2(pv[nv][0], pv[nv][1]);
            *(float2*)(base + 8 * CS) = make_float2(pv[nv][2], pv[nv][3]);
        }
        return;
    }

    {   // conv3d 3x3x3 (96->96), SAME, f32x2, ci-split-3
        float* in_s = (float*)dsm;
        float* ws   = (float*)dsm + 976;

        int j = bx - 256;
        int cog = j % 6, rest = j / 6;
        int d = rest % 16, bs = rest / 16;
        int b = bs / 3, s = bs % 3;
        int h = t >> 4, w = t & 15;

        unsigned long long acc[8];
#pragma unroll
        for (int k = 0; k < 8; k++) acc[k] = 0ull;

        for (int ci0 = 0; ci0 < 32; ci0++) {
            int ci = s * 32 + ci0;
            const float* src = g_Ype + (size_t)(b * CY + ci) * NN;
            for (int i = t; i < 3 * 324; i += 256) {
                int dd = i / 324, rem = i - dd * 324, r = rem / 18, c = rem - r * 18;
                int z = d + dd - 1, y = r - 1, x = c - 1;
                float v = 0.f;
                if (z >= 0 && z < 16 && y >= 0 && y < 16 && x >= 0 && x < 16)
                    v = src[z * 256 + y * 16 + x];
                in_s[i] = v;
            }
            for (int i = t; i < 16 * 27; i += 256) {
                int tap = i % 27, co = i / 27;
                ws[tap * 16 + co] = w3[(size_t)(cog * 16 + co) * (CY * 27) + ci * 27 + tap];
            }
            __syncthreads();

            float in_r[27];
#pragma unroll
            for (int dd = 0; dd < 3; dd++)
#pragma unroll
                for (int dy = 0; dy < 3; dy++)
#pragma unroll
                    for (int dx = 0; dx < 3; dx++)
                        in_r[dd*9+dy*3+dx] = in_s[dd*324 + (h+dy)*18 + (w+dx)];

#pragma unroll
            for (int tap = 0; tap < 27; tap++) {
                unsigned long long xx;
                asm("mov.b64 %0, {%1, %1};" : "=l"(xx) : "f"(in_r[tap]));
#pragma unroll
                for (int k = 0; k < 8; k++) {
                    unsigned long long ww = *(const unsigned long long*)&ws[tap * 16 + 2 * k];
                    fma2(acc[k], xx, ww);
                }
            }
            __syncthreads();
        }
        int n = d * 256 + t;
        float* dst = g_Y3p + (size_t)s * (BB * CY * NN)
                   + (size_t)(b * CY + cog * 16) * NN + n;
#pragma unroll
        for (int k = 0; k < 8; k++) {
            float lo, hi;
            asm("mov.b64 {%0, %1}, %2;" : "=f"(lo), "=f"(hi) : "l"(acc[k]));
            dst[(2 * k) * NN]     = lo;
            dst[(2 * k + 1) * NN] = hi;
        }
    }
}

// ============================================================================
// FUSE2: [0,128) zout | [128,256) y2out
// ============================================================================
#define FUSE2_SMEM 43008
__global__ __launch_bounds__(256) void k_fuse2(
    const float* __restrict__ S,
    const float* __restrict__ w_o, const float* __restrict__ b_o,
    const float* __restrict__ g_o, const float* __restrict__ be_o,
    const float* __restrict__ w_y2, const float* __restrict__ b_y2,
    const float* __restrict__ g_y2, const float* __restrict__ be_y2,
    const float* __restrict__ b3, float* __restrict__ out)
{
    extern __shared__ __align__(16) float pool[];
    int bx = blockIdx.x, t = threadIdx.x;

    if (bx < 128) {
        int n0 = (bx & 63) * 64, b = bx >> 6;
        float* xs  = pool;
        float* wot = pool + 3072;

        for (int i = t; i < CS * CS; i += 256) {
            int e = i % CS, d = i / CS;
            wot[i] = w_o[e * CS + d];
        }
        {
            int n = t & 63, v = t >> 6;
            const size_t cstride = (size_t)BB * NN * CS;
            const float* src = g_Xp + (size_t)(b * NN + n0 + n) * CS;
#pragma unroll
            for (int r = 0; r < 3; r++) {
                int dv = v + r * 4;
                float4 x  = *(const float4*)&src[dv * 4];
                float4 x1 = *(const float4*)&src[cstride + dv * 4];
                float4 x2 = *(const float4*)&src[2 * cstride + dv * 4];
                float4 x3 = *(const float4*)&src[3 * cstride + dv * 4];
                x.x += x1.x + x2.x + x3.x;
                x.y += x1.y + x2.y + x3.y;
                x.z += x1.z + x2.z + x3.z;
                x.w += x1.w + x2.w + x3.w;
                xs[(dv*4+0)*64+n] = x.x; xs[(dv*4+1)*64+n] = x.y;
                xs[(dv*4+2)*64+n] = x.z; xs[(dv*4+3)*64+n] = x.w;
            }
        }
        __syncthreads();

        int n = t & 63, eg = t >> 6;
        float acc[12];
#pragma unroll
        for (int k = 0; k < 12; k++) acc[k] = 0.f;
        for (int d = 0; d < CS; d++) {
            float x = xs[d * 64 + n];
#pragma unroll
            for (int v = 0; v < 3; v++) {
                float4 w4 = *(const float4*)&wot[d * CS + eg * 12 + v * 4];
                acc[v*4+0] += w4.x * x; acc[v*4+1] += w4.y * x;
                acc[v*4+2] += w4.z * x; acc[v*4+3] += w4.w * x;
            }
        }
        float inv = rsqrtf(1.f + 1e-5f);
#pragma unroll
        for (int k = 0; k < 12; k++) {
            int e = eg * 12 + k;
            float y = (acc[k] + b_o[e]) * (g_o[e] * inv) + be_o[e];
            y = fmaxf(y, 0.f);
            float spe = S[(b * CS + e) * NN + n0 + n]
                      + g_peS[e * 256 + ((n0 + n) & 255)];
            out[(b * 96 + e) * NN + n0 + n] = y * spe;
        }
        return;
    }

    {
        int j = bx - 128;
        int n0 = (j & 63) * 64, b = j >> 6;
        float* in_s = pool;
        float* wt   = pool + 6144;

        for (int i = t; i < CY * CS; i += 256) {
            int e = i % CS, c = i / CS;
            wt[i] = w_y2[e * CY + c];
        }
        const size_t pstride = (size_t)BB * CY * NN;
        const float* src = g_Y3p + (size_t)(b * CY) * NN + n0;
        for (int i = t; i < CY * 64; i += 256) {
            int c = i >> 6, n = i & 63;
            in_s[i] = src[c * NN + n] + src[pstride + c * NN + n]
                    + src[2 * pstride + c * NN + n] + b3[c];
        }
        __syncthreads();

        int n = t & 63, eg = t >> 6;
        float acc[12];
#pragma unroll
        for (int k = 0; k < 12; k++) acc[k] = 0.f;
        for (int c = 0; c < CY; c++) {
            float x = in_s[c * 64 + n];
#pragma unroll
            for (int v = 0; v < 3; v++) {
                float4 w4 = *(const float4*)&wt[c * CS + eg * 12 + v * 4];
                acc[v*4+0] += w4.x * x; acc[v*4+1] += w4.y * x;
                acc[v*4+2] += w4.z * x; acc[v*4+3] += w4.w * x;
            }
        }
        float inv = rsqrtf(1.f + 1e-5f);
#pragma unroll
        for (int k = 0; k < 12; k++) {
            int e = eg * 12 + k;
            float y = (acc[k] + b_y2[e]) * (g_y2[e] * inv) + be_y2[e];
            out[(b * 96 + 48 + e) * NN + n0 + n] = fmaxf(y, 0.f);
        }
    }
}

// ---------------- launch -----------------------------------------------------
extern "C" void kernel_launch(void* const* d_in, const int* in_sizes, int n_in,
                              void* d_out, int out_size)
{
    const float* Y    = (const float*)d_in[0];
    const float* S    = (const float*)d_in[1];
    const float* w_s  = (const float*)d_in[2];
    const float* b_s  = (const float*)d_in[3];
    const float* g_s  = (const float*)d_in[4];
    const float* be_s = (const float*)d_in[5];
    const float* w_y  = (const float*)d_in[6];
    const float* b_y  = (const float*)d_in[7];
    const float* g_y  = (const float*)d_in[8];
    const float* be_y = (const float*)d_in[9];
    const float* Wq   = (const float*)d_in[10];
    const float* Wk   = (const float*)d_in[11];
    const float* Wv   = (const float*)d_in[12];
    const float* w_o  = (const float*)d_in[13];
    const float* b_o  = (const float*)d_in[14];
    const float* g_o  = (const float*)d_in[15];
    const float* be_o = (const float*)d_in[16];
    const float* w3   = (const float*)d_in[17];
    const float* b3   = (const float*)d_in[18];
    const float* w_y2 = (const float*)d_in[19];
    const float* b_y2 = (const float*)d_in[20];
    const float* g_y2 = (const float*)d_in[21];
    const float* be_y2= (const float*)d_in[22];
    float* out = (float*)d_out;

    static int attr_done = 0;
    if (!attr_done) {
        cudaFuncSetAttribute(k_fuse1,  cudaFuncAttributeMaxDynamicSharedMemorySize, FUSE1_SMEM);
        cudaFuncSetAttribute(k_colsum, cudaFuncAttributeMaxDynamicSharedMemorySize, CS_SMEM);
        cudaFuncSetAttribute(k_fuse3,  cudaFuncAttributeMaxDynamicSharedMemorySize, F3_SMEM);
        attr_done = 1;
    }

    k_petab <<<144, 256>>>();
    k_fuse1 <<<1024, 256, FUSE1_SMEM>>>(Y, S, w_s, b_s, g_s, be_s, Wv,
                                        w_y, b_y, g_y, be_y, Wq, Wk);
    k_colsum<<<dim3(32, 2, BB), 256, CS_SMEM>>>();
    k_vprime<<<dim3(64, BB), 256>>>();
    k_fuse3 <<<832, 256, F3_SMEM>>>(w3);
    k_fuse2 <<<256, 256, FUSE2_SMEM>>>(S, w_o, b_o, g_o, be_o,
                                       w_y2, b_y2, g_y2, be_y2, b3, out);
}

// round 8
// speedup vs baseline: 1.3666x; 1.3017x over previous
#include <cuda_runtime.h>
#include <cuda_bf16.h>
#include <math.h>
#include <stdint.h>

#define BB 2
#define CY 96
#define CS 48
#define NN 4096
#define SCALE 0.14433756729740643f  /* 48^-0.5 */

// ---------------- scratch ----------------------------------------------------
__device__ __align__(16) float g_Ype[BB*CY*NN];
__device__ __align__(16) float g_V  [BB*NN*CS];
__device__ __align__(16) __nv_bfloat16 g_Qh[BB*NN*CS], g_Ql[BB*NN*CS];
__device__ __align__(16) __nv_bfloat16 g_Kh[BB*NN*CS], g_Kl[BB*NN*CS];
__device__ __align__(16) __nv_bfloat16 g_Vth[BB*CS*NN], g_Vtl[BB*CS*NN];
__device__ __align__(16) float g_psum[BB*4*NN];
__device__ __align__(16) float g_Xp[4*BB*NN*CS];
__device__ __align__(16) float g_Y3p[3*BB*CY*NN];
__device__ __align__(16) float g_peS[CS*256];
__device__ __align__(16) float g_peY[CY*256];

// ---------------- helpers ----------------------------------------------------
__device__ __forceinline__ void mma16816(float* c, const uint32_t* a, const uint32_t* b) {
    asm volatile(
        "mma.sync.aligned.m16n8k16.row.col.f32.bf16.bf16.f32 "
        "{%0,%1,%2,%3}, {%4,%5,%6,%7}, {%8,%9}, {%0,%1,%2,%3};\n"
        : "+f"(c[0]), "+f"(c[1]), "+f"(c[2]), "+f"(c[3])
        : "r"(a[0]), "r"(a[1]), "r"(a[2]), "r"(a[3]), "r"(b[0]), "r"(b[1]));
}
__device__ __forceinline__ uint32_t bf2u(__nv_bfloat16 a, __nv_bfloat16 b) {
    __nv_bfloat162 v(a, b);
    return *reinterpret_cast<uint32_t*>(&v);
}
__device__ __forceinline__ void fma2(unsigned long long& d, unsigned long long a,
                                     unsigned long long b) {
    asm("fma.rn.f32x2 %0, %1, %2, %0;" : "+l"(d) : "l"(a), "l"(b));
}
__device__ __forceinline__ void cpa16(__nv_bfloat16* smem, const __nv_bfloat16* gmem) {
    uint32_t s = (uint32_t)__cvta_generic_to_shared(smem);
    asm volatile("cp.async.cg.shared.global [%0], [%1], 16;\n" :: "r"(s), "l"(gmem));
}
#define CPA_COMMIT() asm volatile("cp.async.commit_group;\n" ::: "memory")
#define CPA_WAIT(N)  asm volatile("cp.async.wait_group %0;\n" :: "n"(N) : "memory")

// ---------------- PE tables --------------------------------------------------
__device__ __forceinline__ float pe_val(int ch, int h, int w, int c) {
    int blk = ch / c, t = ch - blk * c;
    int pos = (blk < 2) ? h : w;    // torch broadcast quirk
    int half = c >> 1;
    if (t < half) {
        float invf = powf(10000.f, -2.f * (float)t / (float)c);
        return sinf((float)pos * invf);
    } else {
        float invf = powf(10000.f, -2.f * (float)(t - half) / (float)c);
        return cosf((float)pos * invf);
    }
}
__global__ void k_petab() {
    int i = blockIdx.x * 256 + threadIdx.x;
    if (i < CY * 256) {
        int ch = i >> 8, n = i & 255;
        g_peY[i] = pe_val(ch, n >> 4, n & 15, 32);
    } else {
        int j = i - CY * 256;
        if (j < CS * 256) {
            int ch = j >> 8, n = j & 255;
            g_peS[j] = pe_val(ch, n >> 4, n & 15, 16);
        }
    }
}

// ============================================================================
// FUSE1: [0,768) addpe_y | [768,896) proj_sv->V | [896,1024) proj_y1+QK
// ============================================================================
#define FUSE1_SMEM 55552
__global__ __launch_bounds__(256) void k_fuse1(
    const float* __restrict__ Y, const float* __restrict__ S,
    const float* __restrict__ w_s, const float* __restrict__ b_s,
    const float* __restrict__ g_s, const float* __restrict__ be_s,
    const float* __restrict__ Wv,
    const float* __restrict__ w_y, const float* __restrict__ b_y,
    const float* __restrict__ g_y, const float* __restrict__ be_y,
    const float* __restrict__ Wq, const float* __restrict__ Wk)
{
    extern __shared__ __align__(16) float pool[];
    int bx = blockIdx.x, t = threadIdx.x;

    if (bx < 768) {
        int i = (bx * 256 + t) * 4;
        int n = i & (NN - 1);
        int ch = (i >> 12) % CY;
        float4 s = *(const float4*)&Y[i];
        float4 p = *(const float4*)&g_peY[ch * 256 + (n & 255)];
        s.x += p.x; s.y += p.y; s.z += p.z; s.w += p.w;
        *(float4*)&g_Ype[i] = s;
        return;
    }

    if (bx < 896) {
        int j = bx - 768;
        int n0 = (j & 63) * 64, b = j >> 6;
        float* in_s = pool;
        float* wt   = pool + 3072;
        float* wv   = pool + 5376;
        float* s1   = pool + 7680;

        for (int i = t; i < CS * CS; i += 256) {
            int e = i % CS, c = i / CS;
            wt[i] = w_s[e * CS + c];
            wv[i] = Wv[i];
        }
        for (int i = t; i < CS * 64; i += 256) {
            int c = i >> 6, nl = i & 63;
            in_s[i] = S[(b * CS + c) * NN + n0 + nl]
                    + g_peS[c * 256 + ((n0 + nl) & 255)];
        }
        __syncthreads();

        int n = t & 63, eg = t >> 6;
        float acc[12];
#pragma unroll
        for (int k = 0; k < 12; k++) acc[k] = 0.f;
        for (int c = 0; c < CS; c++) {
            float x = in_s[c * 64 + n];
#pragma unroll
            for (int v = 0; v < 3; v++) {
                float4 w4 = *(const float4*)&wt[c * CS + eg * 12 + v * 4];
                acc[v*4+0] += w4.x * x; acc[v*4+1] += w4.y * x;
                acc[v*4+2] += w4.z * x; acc[v*4+3] += w4.w * x;
            }
        }
        float inv = rsqrtf(1.f + 1e-5f);
#pragma unroll
        for (int k = 0; k < 12; k++) {
            int e = eg * 12 + k;
            float y = (acc[k] + b_s[e]) * (g_s[e] * inv) + be_s[e];
            s1[n * 49 + e] = fmaxf(y, 0.f);
        }
        __syncthreads();

#pragma unroll
        for (int k = 0; k < 12; k++) acc[k] = 0.f;
        for (int d = 0; d < CS; d++) {
            float x = s1[n * 49 + d];
#pragma unroll
            for (int v = 0; v < 3; v++) {
                float4 w4 = *(const float4*)&wv[d * CS + eg * 12 + v * 4];
                acc[v*4+0] += w4.x * x; acc[v*4+1] += w4.y * x;
                acc[v*4+2] += w4.z * x; acc[v*4+3] += w4.w * x;
            }
        }
        float* dst = g_V + ((b * NN + n0 + n) * CS) + eg * 12;
#pragma unroll
        for (int v = 0; v < 3; v++)
            *(float4*)&dst[v * 4] = make_float4(acc[v*4], acc[v*4+1], acc[v*4+2], acc[v*4+3]);
        return;
    }

    {   // proj_y1 + QK fused; Y1 lives only in smem
        int j = bx - 896;
        int n0 = (j & 63) * 64, b = j >> 6;
        float* in_s = pool;            // [96][64]
        float* wt   = pool + 6144;     // [c][e]
        float* s1   = pool + 10752;    // [n][49]

        for (int i = t; i < CY * CS; i += 256) {
            int e = i % CS, c = i / CS;
            wt[i] = w_y[e * CY + c];
        }
        for (int i = t; i < CY * 64; i += 256) {
            int c = i >> 6, nl = i & 63;
            in_s[i] = Y[(b * CY + c) * NN + n0 + nl]
                    + g_peY[c * 256 + ((n0 + nl) & 255)];
        }
        __syncthreads();

        int n = t & 63, eg = t >> 6;
        float acc[12];
#pragma unroll
        for (int k = 0; k < 12; k++) acc[k] = 0.f;
        for (int c = 0; c < CY; c++) {
            float x = in_s[c * 64 + n];
#pragma unroll
            for (int v = 0; v < 3; v++) {
                float4 w4 = *(const float4*)&wt[c * CS + eg * 12 + v * 4];
                acc[v*4+0] += w4.x * x; acc[v*4+1] += w4.y * x;
                acc[v*4+2] += w4.z * x; acc[v*4+3] += w4.w * x;
            }
        }
        float inv = rsqrtf(1.f + 1e-5f);
#pragma unroll
        for (int k = 0; k < 12; k++) {
            int e = eg * 12 + k;
            float y = (acc[k] + b_y[e]) * (g_y[e] * inv) + be_y[e];
            s1[n * 49 + e] = fmaxf(y, 0.f);
        }
        __syncthreads();

        float* wq = pool;
        float* wk = pool + 2304;
        for (int i = t; i < CS * CS; i += 256) { wq[i] = Wq[i]; wk[i] = Wk[i]; }
        __syncthreads();

        float aq[12], ak[12];
#pragma unroll
        for (int k = 0; k < 12; k++) { aq[k] = 0.f; ak[k] = 0.f; }
        for (int d = 0; d < CS; d++) {
            float x = s1[n * 49 + d];
#pragma unroll
            for (int v = 0; v < 3; v++) {
                float4 q4 = *(const float4*)&wq[d * CS + eg * 12 + v * 4];
                float4 k4 = *(const float4*)&wk[d * CS + eg * 12 + v * 4];
                aq[v*4+0] += q4.x * x; aq[v*4+1] += q4.y * x;
                aq[v*4+2] += q4.z * x; aq[v*4+3] += q4.w * x;
                ak[v*4+0] += k4.x * x; ak[v*4+1] += k4.y * x;
                ak[v*4+2] += k4.z * x; ak[v*4+3] += k4.w * x;
            }
        }
        int base = (b * NN + n0 + n) * CS + eg * 12;
#pragma unroll
        for (int k = 0; k < 12; k++) {
            __nv_bfloat16 qh = __float2bfloat16(aq[k]);
            __nv_bfloat16 kh = __float2bfloat16(ak[k]);
            g_Qh[base + k] = qh;
            g_Ql[base + k] = __float2bfloat16(aq[k] - __bfloat162float(qh));
            g_Kh[base + k] = kh;
            g_Kl[base + k] = __float2bfloat16(ak[k] - __bfloat162float(kh));
        }
    }
}

// ============================================================================
// Pass 1: column sums. A = K-tile (persistent frags), B = Q chunks (cp.async
// double-buffered). grid (32 kblk, 4 qq, BB). smem 86016 B -> occ 2.
// ============================================================================
#define CS_SMEM 86016
__global__ __launch_bounds__(256) void k_colsum() {
    extern __shared__ __align__(16) unsigned char dsm[];
    __nv_bfloat16* KH = (__nv_bfloat16*)dsm;          // [128][56]
    __nv_bfloat16* KL = KH + 7168;
    __nv_bfloat16* QB = KH + 14336;                   // 2 bufs x (QH 7168 + QL 7168)

    int k0 = blockIdx.x * 128, qq = blockIdx.y, b = blockIdx.z;
    int t = threadIdx.x, wid = t >> 5, l = t & 31;
    int lr = l >> 2, lc = (l & 3) * 2;
    int mb = wid * 16;

    {
        const __nv_bfloat16* s = g_Kh + (size_t)(b * NN + k0) * CS;
        for (int i = t; i < 768; i += 256) {
            int r = i / 6, c = i % 6;
            *(uint4*)(KH + r * 56 + c * 8) = *(const uint4*)(s + r * 48 + c * 8);
        }
        s = g_Kl + (size_t)(b * NN + k0) * CS;
        for (int i = t; i < 768; i += 256) {
            int r = i / 6, c = i % 6;
            *(uint4*)(KL + r * 56 + c * 8) = *(const uint4*)(s + r * 48 + c * 8);
        }
    }
    __syncthreads();

    uint32_t kfh[3][4], kfl[3][4];
#pragma unroll
    for (int ks = 0; ks < 3; ks++) {
        int ko = ks * 16;
        kfh[ks][0] = *(uint32_t*)&KH[(mb + lr) * 56 + ko + lc];
        kfh[ks][1] = *(uint32_t*)&KH[(mb + 8 + lr) * 56 + ko + lc];
        kfh[ks][2] = *(uint32_t*)&KH[(mb + lr) * 56 + ko + lc + 8];
        kfh[ks][3] = *(uint32_t*)&KH[(mb + 8 + lr) * 56 + ko + lc + 8];
        kfl[ks][0] = *(uint32_t*)&KL[(mb + lr) * 56 + ko + lc];
        kfl[ks][1] = *(uint32_t*)&KL[(mb + 8 + lr) * 56 + ko + lc];
        kfl[ks][2] = *(uint32_t*)&KL[(mb + lr) * 56 + ko + lc + 8];
        kfl[ks][3] = *(uint32_t*)&KL[(mb + 8 + lr) * 56 + ko + lc + 8];
    }

    // prefetch helper: stage Q chunk (128 rows) into buffer bi
    auto prefetchQ = [&](int ch, int bi) {
        int qb = qq * 1024 + ch * 128;
        __nv_bfloat16* QH = QB + bi * 14336;
        __nv_bfloat16* QL = QH + 7168;
        const __nv_bfloat16* sh = g_Qh + (size_t)(b * NN + qb) * CS;
        const __nv_bfloat16* sl = g_Ql + (size_t)(b * NN + qb) * CS;
        for (int i = t; i < 768; i += 256) {
            int r = i / 6, c = i % 6;
            cpa16(QH + r * 56 + c * 8, sh + r * 48 + c * 8);
            cpa16(QL + r * 56 + c * 8, sl + r * 48 + c * 8);
        }
        CPA_COMMIT();
    };

    float rs0 = 0.f, rs1 = 0.f;
    prefetchQ(0, 0);
    for (int ch = 0; ch < 8; ch++) {
        if (ch < 7) prefetchQ(ch + 1, (ch + 1) & 1);
        if (ch < 7) { CPA_WAIT(1); } else { CPA_WAIT(0); }
        __syncthreads();
        __nv_bfloat16* QH = QB + (ch & 1) * 14336;
        __nv_bfloat16* QL = QH + 7168;

#pragma unroll
        for (int nfp = 0; nfp < 8; nfp++) {
            float a0[4] = {0.f,0.f,0.f,0.f}, a1[4] = {0.f,0.f,0.f,0.f};
#pragma unroll
            for (int ks = 0; ks < 3; ks++) {
                int ko = ks * 16;
                int i0 = (nfp * 16 + lr) * 56 + ko + lc;
                int i1 = i0 + 8 * 56;
                uint32_t bh0[2] = { *(uint32_t*)&QH[i0], *(uint32_t*)&QH[i0 + 8] };
                uint32_t bl0[2] = { *(uint32_t*)&QL[i0], *(uint32_t*)&QL[i0 + 8] };
                uint32_t bh1[2] = { *(uint32_t*)&QH[i1], *(uint32_t*)&QH[i1 + 8] };
                uint32_t bl1[2] = { *(uint32_t*)&QL[i1], *(uint32_t*)&QL[i1 + 8] };
                mma16816(a0, kfh[ks], bh0); mma16816(a0, kfl[ks], bh0); mma16816(a0, kfh[ks], bl0);
                mma16816(a1, kfh[ks], bh1); mma16816(a1, kfl[ks], bh1); mma16816(a1, kfh[ks], bl1);
            }
            rs0 += __expf(a0[0] * SCALE) + __expf(a0[1] * SCALE)
                 + __expf(a1[0] * SCALE) + __expf(a1[1] * SCALE);
            rs1 += __expf(a0[2] * SCALE) + __expf(a0[3] * SCALE)
                 + __expf(a1[2] * SCALE) + __expf(a1[3] * SCALE);
        }
        __syncthreads();
    }
    rs0 += __shfl_xor_sync(0xffffffffu, rs0, 1);
    rs0 += __shfl_xor_sync(0xffffffffu, rs0, 2);
    rs1 += __shfl_xor_sync(0xffffffffu, rs1, 1);
    rs1 += __shfl_xor_sync(0xffffffffu, rs1, 2);
    if ((l & 3) == 0) {
        g_psum[(b * 4 + qq) * NN + k0 + mb + lr]     = rs0;
        g_psum[(b * 4 + qq) * NN + k0 + mb + 8 + lr] = rs1;
    }
}

// ============================================================================
// vprime: V' = V / colsum, transposed [d][k], bf16 hi/lo. grid (128, BB).
// ============================================================================
__global__ __launch_bounds__(256) void k_vprime() {
    __shared__ float iz_s[32];
    __shared__ __nv_bfloat16 Th[48 * 34], Tl[48 * 34];

    int k0 = blockIdx.x * 32, b = blockIdx.y, t = threadIdx.x;
    if (t < 32) {
        int k = k0 + t;
        float s = g_psum[(b * 4) * NN + k] + g_psum[(b * 4 + 1) * NN + k]
                + g_psum[(b * 4 + 2) * NN + k] + g_psum[(b * 4 + 3) * NN + k];
        iz_s[t] = 1.f / s;
    }
    __syncthreads();

    const float* vsrc = g_V + (size_t)(b * NN + k0) * CS;
    for (int i = t; i < 32 * CS; i += 256) {
        int kk = i / CS, d = i - kk * CS;
        float val = vsrc[i] * iz_s[kk];
        __nv_bfloat16 h = __float2bfloat16(val);
        Th[d * 34 + kk] = h;
        Tl[d * 34 + kk] = __float2bfloat16(val - __bfloat162float(h));
    }
    __syncthreads();

    for (int j = t; j < 48 * 16; j += 256) {
        int d = j >> 4, c2 = (j & 15) * 2;
        *(uint32_t*)&g_Vth[(size_t)(b * CS + d) * NN + k0 + c2] =
            bf2u(Th[d * 34 + c2], Th[d * 34 + c2 + 1]);
        *(uint32_t*)&g_Vtl[(size_t)(b * CS + d) * NN + k0 + c2] =
            bf2u(Tl[d * 34 + c2], Tl[d * 34 + c2 + 1]);
    }
}

// ============================================================================
// flash pass2: P (recomputed, exp'd, split) fed directly as A-fragments into
// P @ V'. k-chunk 64, cp.async double-buffered K/V. grid (32, 4, BB).
// smem 84992 B -> occ 2.
// ============================================================================
#define FLASH_SMEM 84992
__global__ __launch_bounds__(256) void k_flash() {
    extern __shared__ __align__(16) unsigned char dsm[];
    __nv_bfloat16* QH = (__nv_bfloat16*)dsm;      // [128][56]
    __nv_bfloat16* QL = QH + 7168;
    __nv_bfloat16* KB = QH + 14336;               // 2 bufs x (KH 3584 + KL 3584)  [64][56]
    __nv_bfloat16* VB = QH + 28672;               // 2 bufs x (VH 3456 + VL 3456)  [48][72]

    int qblk = blockIdx.x, kq = blockIdx.y, b = blockIdx.z;
    int t = threadIdx.x, wid = t >> 5, l = t & 31;
    int lr = l >> 2, lc = (l & 3) * 2;
    int q0 = qblk * 128, mb = wid * 16;

    {
        const __nv_bfloat16* s = g_Qh + (size_t)(b * NN + q0) * CS;
        for (int i = t; i < 768; i += 256) {
            int r = i / 6, c = i % 6;
            *(uint4*)(QH + r * 56 + c * 8) = *(const uint4*)(s + r * 48 + c * 8);
        }
        s = g_Ql + (size_t)(b * NN + q0) * CS;
        for (int i = t; i < 768; i += 256) {
            int r = i / 6, c = i % 6;
            *(uint4*)(QL + r * 56 + c * 8) = *(const uint4*)(s + r * 48 + c * 8);
        }
    }
    __syncthreads();

    uint32_t qfh[3][4], qfl[3][4];
#pragma unroll
    for (int ks = 0; ks < 3; ks++) {
        int ko = ks * 16;
        qfh[ks][0] = *(uint32_t*)&QH[(mb + lr) * 56 + ko + lc];
        qfh[ks][1] = *(uint32_t*)&QH[(mb + 8 + lr) * 56 + ko + lc];
        qfh[ks][2] = *(uint32_t*)&QH[(mb + lr) * 56 + ko + lc + 8];
        qfh[ks][3] = *(uint32_t*)&QH[(mb + 8 + lr) * 56 + ko + lc + 8];
        qfl[ks][0] = *(uint32_t*)&QL[(mb + lr) * 56 + ko + lc];
        qfl[ks][1] = *(uint32_t*)&QL[(mb + 8 + lr) * 56 + ko + lc];
        qfl[ks][2] = *(uint32_t*)&QL[(mb + lr) * 56 + ko + lc + 8];
        qfl[ks][3] = *(uint32_t*)&QL[(mb + 8 + lr) * 56 + ko + lc + 8];
    }

    // prefetch k-chunk (64 K rows + 48x64 V cols) into buffer bi
    auto prefetchKV = [&](int ch, int bi) {
        int kb = kq * 1024 + ch * 64;
        __nv_bfloat16* KHc = KB + bi * 7168;
        __nv_bfloat16* KLc = KHc + 3584;
        __nv_bfloat16* VHc = VB + bi * 6912;
        __nv_bfloat16* VLc = VHc + 3456;
        const __nv_bfloat16* skh = g_Kh + (size_t)(b * NN + kb) * CS;
        const __nv_bfloat16* skl = g_Kl + (size_t)(b * NN + kb) * CS;
        for (int i = t; i < 384; i += 256) {
            int r = i / 6, c = i % 6;
            cpa16(KHc + r * 56 + c * 8, skh + r * 48 + c * 8);
            cpa16(KLc + r * 56 + c * 8, skl + r * 48 + c * 8);
        }
        const __nv_bfloat16* svh = g_Vth + (size_t)(b * CS) * NN + kb;
        const __nv_bfloat16* svl = g_Vtl + (size_t)(b * CS) * NN + kb;
        for (int i = t; i < 384; i += 256) {
            int r = i / 8, c = i % 8;
            cpa16(VHc + r * 72 + c * 8, svh + (size_t)r * NN + c * 8);
            cpa16(VLc + r * 72 + c * 8, svl + (size_t)r * NN + c * 8);
        }
        CPA_COMMIT();
    };

    float pv[6][4];
#pragma unroll
    for (int nv = 0; nv < 6; nv++)
#pragma unroll
        for (int c = 0; c < 4; c++) pv[nv][c] = 0.f;

    prefetchKV(0, 0);
    for (int ch = 0; ch < 16; ch++) {
        if (ch < 15) prefetchKV(ch + 1, (ch + 1) & 1);
        if (ch < 15) { CPA_WAIT(1); } else { CPA_WAIT(0); }
        __syncthreads();
        __nv_bfloat16* KHc = KB + (ch & 1) * 7168;
        __nv_bfloat16* KLc = KHc + 3584;
        __nv_bfloat16* VHc = VB + (ch & 1) * 6912;
        __nv_bfloat16* VLc = VHc + 3456;

#pragma unroll
        for (int nfp = 0; nfp < 4; nfp++) {
            float a0[4] = {0.f,0.f,0.f,0.f}, a1[4] = {0.f,0.f,0.f,0.f};
#pragma unroll
            for (int ks = 0; ks < 3; ks++) {
                int ko = ks * 16;
                int i0 = (nfp * 16 + lr) * 56 + ko + lc;
                int i1 = i0 + 8 * 56;
                uint32_t bh0[2] = { *(uint32_t*)&KHc[i0], *(uint32_t*)&KHc[i0 + 8] };
                uint32_t bl0[2] = { *(uint32_t*)&KLc[i0], *(uint32_t*)&KLc[i0 + 8] };
                uint32_t bh1[2] = { *(uint32_t*)&KHc[i1], *(uint32_t*)&KHc[i1 + 8] };
                uint32_t bl1[2] = { *(uint32_t*)&KLc[i1], *(uint32_t*)&KLc[i1 + 8] };
                mma16816(a0, qfh[ks], bh0); mma16816(a0, qfl[ks], bh0); mma16816(a0, qfh[ks], bl0);
                mma16816(a1, qfh[ks], bh1); mma16816(a1, qfl[ks], bh1); mma16816(a1, qfh[ks], bl1);
            }
            float e0 = __expf(a0[0]*SCALE), e1 = __expf(a0[1]*SCALE);
            float e2 = __expf(a0[2]*SCALE), e3 = __expf(a0[3]*SCALE);
            float e4 = __expf(a1[0]*SCALE), e5 = __expf(a1[1]*SCALE);
            float e6 = __expf(a1[2]*SCALE), e7 = __expf(a1[3]*SCALE);
            __nv_bfloat16 h0 = __float2bfloat16(e0), h1 = __float2bfloat16(e1);
            __nv_bfloat16 h2 = __float2bfloat16(e2), h3 = __float2bfloat16(e3);
            __nv_bfloat16 h4 = __float2bfloat16(e4), h5 = __float2bfloat16(e5);
            __nv_bfloat16 h6 = __float2bfloat16(e6), h7 = __float2bfloat16(e7);
            uint32_t ph[4] = { bf2u(h0, h1), bf2u(h2, h3), bf2u(h4, h5), bf2u(h6, h7) };
            uint32_t pl[4] = {
                bf2u(__float2bfloat16(e0 - __bfloat162float(h0)),
                     __float2bfloat16(e1 - __bfloat162float(h1))),
                bf2u(__float2bfloat16(e2 - __bfloat162float(h2)),
                     __float2bfloat16(e3 - __bfloat162float(h3))),
                bf2u(__float2bfloat16(e4 - __bfloat162float(h4)),
                     __float2bfloat16(e5 - __bfloat162float(h5))),
                bf2u(__float2bfloat16(e6 - __bfloat162float(h6)),
                     __float2bfloat16(e7 - __bfloat162float(h7))) };
            int kop = nfp * 16;
#pragma unroll
            for (int nv = 0; nv < 6; nv++) {
                int iv = (nv * 8 + lr) * 72 + kop + lc;
                uint32_t vh[2] = { *(uint32_t*)&VHc[iv], *(uint32_t*)&VHc[iv + 8] };
                uint32_t vl[2] = { *(uint32_t*)&VLc[iv], *(uint32_t*)&VLc[iv + 8] };
                mma16816(pv[nv], ph, vh); mma16816(pv[nv], pl, vh); mma16816(pv[nv], ph, vl);
            }
        }
        __syncthreads();
    }

#pragma unroll
    for (int nv = 0; nv < 6; nv++) {
        int r = q0 + mb + lr, col = nv * 8 + lc;
        float* base = &g_Xp[((size_t)(kq * BB + b) * NN + r) * CS + col];
        *(float2*)base = make_float2(pv[nv][0], pv[nv][1]);
        *(float2*)(base + 8 * CS) = make_float2(pv[nv][2], pv[nv][3]);
    }
}

// ============================================================================
// conv3d 3x3x3 (96->96), SAME, f32x2, ci-split-3; small static smem, own stream
// grid (6, 16, BB*3)
// ============================================================================
__global__ __launch_bounds__(256) void k_conv3d(const float* __restrict__ w3) {
    __shared__ __align__(16) float in_s[3 * 18 * 18];
    __shared__ __align__(16) float ws[27 * 16];

    int cog = blockIdx.x, d = blockIdx.y;
    int b = blockIdx.z / 3, s = blockIdx.z % 3;
    int t = threadIdx.x, h = t >> 4, w = t & 15;

    unsigned long long acc[8];
#pragma unroll
    for (int k = 0; k < 8; k++) acc[k] = 0ull;

    for (int ci0 = 0; ci0 < 32; ci0++) {
        int ci = s * 32 + ci0;
        const float* src = g_Ype + (size_t)(b * CY + ci) * NN;
        for (int i = t; i < 3 * 324; i += 256) {
            int dd = i / 324, rem = i - dd * 324, r = rem / 18, c = rem - r * 18;
            int z = d + dd - 1, y = r - 1, x = c - 1;
            float v = 0.f;
            if (z >= 0 && z < 16 && y >= 0 && y < 16 && x >= 0 && x < 16)
                v = src[z * 256 + y * 16 + x];
            in_s[i] = v;
        }
        for (int i = t; i < 16 * 27; i += 256) {
            int tap = i % 27, co = i / 27;
            ws[tap * 16 + co] = w3[(size_t)(cog * 16 + co) * (CY * 27) + ci * 27 + tap];
        }
        __syncthreads();

        float in_r[27];
#pragma unroll
        for (int dd = 0; dd < 3; dd++)
#pragma unroll
            for (int dy = 0; dy < 3; dy++)
#pragma unroll
                for (int dx = 0; dx < 3; dx++)
                    in_r[dd*9+dy*3+dx] = in_s[dd*324 + (h+dy)*18 + (w+dx)];

#pragma unroll
        for (int tap = 0; tap < 27; tap++) {
            unsigned long long xx;
            asm("mov.b64 %0, {%1, %1};" : "=l"(xx) : "f"(in_r[tap]));
#pragma unroll
            for (int k = 0; k < 8; k++) {
                unsigned long long ww = *(const unsigned long long*)&ws[tap * 16 + 2 * k];
                fma2(acc[k], xx, ww);
            }
        }
        __syncthreads();
    }
    int n = d * 256 + t;
    float* dst = g_Y3p + (size_t)s * (BB * CY * NN)
               + (size_t)(b * CY + cog * 16) * NN + n;
#pragma unroll
    for (int k = 0; k < 8; k++) {
        float lo, hi;
        asm("mov.b64 {%0, %1}, %2;" : "=f"(lo), "=f"(hi) : "l"(acc[k]));
        dst[(2 * k) * NN]     = lo;
        dst[(2 * k + 1) * NN] = hi;
    }
}

// ============================================================================
// FUSE2: [0,128) zout | [128,256) y2out
// ============================================================================
#define FUSE2_SMEM 43008
__global__ __launch_bounds__(256) void k_fuse2(
    const float* __restrict__ S,
    const float* __restrict__ w_o, const float* __restrict__ b_o,
    const float* __restrict__ g_o, const float* __restrict__ be_o,
    const float* __restrict__ w_y2, const float* __restrict__ b_y2,
    const float* __restrict__ g_y2, const float* __restrict__ be_y2,
    const float* __restrict__ b3, float* __restrict__ out)
{
    extern __shared__ __align__(16) float pool[];
    int bx = blockIdx.x, t = threadIdx.x;

    if (bx < 128) {
        int n0 = (bx & 63) * 64, b = bx >> 6;
        float* xs  = pool;
        float* wot = pool + 3072;

        for (int i = t; i < CS * CS; i += 256) {
            int e = i % CS, d = i / CS;
            wot[i] = w_o[e * CS + d];
        }
        {
            int n = t & 63, v = t >> 6;
            const size_t cstride = (size_t)BB * NN * CS;
            const float* src = g_Xp + (size_t)(b * NN + n0 + n) * CS;
#pragma unroll
            for (int r = 0; r < 3; r++) {
                int dv = v + r * 4;
                float4 x  = *(const float4*)&src[dv * 4];
                float4 x1 = *(const float4*)&src[cstride + dv * 4];
                float4 x2 = *(const float4*)&src[2 * cstride + dv * 4];
                float4 x3 = *(const float4*)&src[3 * cstride + dv * 4];
                x.x += x1.x + x2.x + x3.x;
                x.y += x1.y + x2.y + x3.y;
                x.z += x1.z + x2.z + x3.z;
                x.w += x1.w + x2.w + x3.w;
                xs[(dv*4+0)*64+n] = x.x; xs[(dv*4+1)*64+n] = x.y;
                xs[(dv*4+2)*64+n] = x.z; xs[(dv*4+3)*64+n] = x.w;
            }
        }
        __syncthreads();

        int n = t & 63, eg = t >> 6;
        float acc[12];
#pragma unroll
        for (int k = 0; k < 12; k++) acc[k] = 0.f;
        for (int d = 0; d < CS; d++) {
            float x = xs[d * 64 + n];
#pragma unroll
            for (int v = 0; v < 3; v++) {
                float4 w4 = *(const float4*)&wot[d * CS + eg * 12 + v * 4];
                acc[v*4+0] += w4.x * x; acc[v*4+1] += w4.y * x;
                acc[v*4+2] += w4.z * x; acc[v*4+3] += w4.w * x;
            }
        }
        float inv = rsqrtf(1.f + 1e-5f);
#pragma unroll
        for (int k = 0; k < 12; k++) {
            int e = eg * 12 + k;
            float y = (acc[k] + b_o[e]) * (g_o[e] * inv) + be_o[e];
            y = fmaxf(y, 0.f);
            float spe = S[(b * CS + e) * NN + n0 + n]
                      + g_peS[e * 256 + ((n0 + n) & 255)];
            out[(b * 96 + e) * NN + n0 + n] = y * spe;
        }
        return;
    }

    {
        int j = bx - 128;
        int n0 = (j & 63) * 64, b = j >> 6;
        float* in_s = pool;
        float* wt   = pool + 6144;

        for (int i = t; i < CY * CS; i += 256) {
            int e = i % CS, c = i / CS;
            wt[i] = w_y2[e * CY + c];
        }
        const size_t pstride = (size_t)BB * CY * NN;
        const float* src = g_Y3p + (size_t)(b * CY) * NN + n0;
        for (int i = t; i < CY * 64; i += 256) {
            int c = i >> 6, n = i & 63;
            in_s[i] = src[c * NN + n] + src[pstride + c * NN + n]
                    + src[2 * pstride + c * NN + n] + b3[c];
        }
        __syncthreads();

        int n = t & 63, eg = t >> 6;
        float acc[12];
#pragma unroll
        for (int k = 0; k < 12; k++) acc[k] = 0.f;
        for (int c = 0; c < CY; c++) {
            float x = in_s[c * 64 + n];
#pragma unroll
            for (int v = 0; v < 3; v++) {
                float4 w4 = *(const float4*)&wt[c * CS + eg * 12 + v * 4];
                acc[v*4+0] += w4.x * x; acc[v*4+1] += w4.y * x;
                acc[v*4+2] += w4.z * x; acc[v*4+3] += w4.w * x;
            }
        }
        float inv = rsqrtf(1.f + 1e-5f);
#pragma unroll
        for (int k = 0; k < 12; k++) {
            int e = eg * 12 + k;
            float y = (acc[k] + b_y2[e]) * (g_y2[e] * inv) + be_y2[e];
            out[(b * 96 + 48 + e) * NN + n0 + n] = fmaxf(y, 0.f);
        }
    }
}

// ---------------- launch -----------------------------------------------------
extern "C" void kernel_launch(void* const* d_in, const int* in_sizes, int n_in,
                              void* d_out, int out_size)
{
    const float* Y    = (const float*)d_in[0];
    const float* S    = (const float*)d_in[1];
    const float* w_s  = (const float*)d_in[2];
    const float* b_s  = (const float*)d_in[3];
    const float* g_s  = (const float*)d_in[4];
    const float* be_s = (const float*)d_in[5];
    const float* w_y  = (const float*)d_in[6];
    const float* b_y  = (const float*)d_in[7];
    const float* g_y  = (const float*)d_in[8];
    const float* be_y = (const float*)d_in[9];
    const float* Wq   = (const float*)d_in[10];
    const float* Wk   = (const float*)d_in[11];
    const float* Wv   = (const float*)d_in[12];
    const float* w_o  = (const float*)d_in[13];
    const float* b_o  = (const float*)d_in[14];
    const float* g_o  = (const float*)d_in[15];
    const float* be_o = (const float*)d_in[16];
    const float* w3   = (const float*)d_in[17];
    const float* b3   = (const float*)d_in[18];
    const float* w_y2 = (const float*)d_in[19];
    const float* b_y2 = (const float*)d_in[20];
    const float* g_y2 = (const float*)d_in[21];
    const float* be_y2= (const float*)d_in[22];
    float* out = (float*)d_out;

    static cudaStream_t s2 = nullptr;
    static cudaEvent_t ev1 = nullptr, ev2 = nullptr;
    static int attr_done = 0;
    if (!attr_done) {
        cudaFuncSetAttribute(k_fuse1,  cudaFuncAttributeMaxDynamicSharedMemorySize, FUSE1_SMEM);
        cudaFuncSetAttribute(k_colsum, cudaFuncAttributeMaxDynamicSharedMemorySize, CS_SMEM);
        cudaFuncSetAttribute(k_flash,  cudaFuncAttributeMaxDynamicSharedMemorySize, FLASH_SMEM);
        cudaStreamCreateWithFlags(&s2, cudaStreamNonBlocking);
        cudaEventCreateWithFlags(&ev1, cudaEventDisableTiming);
        cudaEventCreateWithFlags(&ev2, cudaEventDisableTiming);
        attr_done = 1;
    }

    k_petab <<<144, 256>>>();
    k_fuse1 <<<1024, 256, FUSE1_SMEM>>>(Y, S, w_s, b_s, g_s, be_s, Wv,
                                        w_y, b_y, g_y, be_y, Wq, Wk);
    // fork: conv3d on s2, attention chain on default stream
    cudaEventRecord(ev1, 0);
    cudaStreamWaitEvent(s2, ev1, 0);
    k_conv3d<<<dim3(6, 16, BB * 3), 256, 0, s2>>>(w3);
    cudaEventRecord(ev2, s2);

    k_colsum<<<dim3(32, 4, BB), 256, CS_SMEM>>>();
    k_vprime<<<dim3(128, BB), 256>>>();
    k_flash <<<dim3(32, 4, BB), 256, FLASH_SMEM>>>();

    cudaStreamWaitEvent(0, ev2, 0);
    k_fuse2 <<<256, 256, FUSE2_SMEM>>>(S, w_o, b_o, g_o, be_o,
                                       w_y2, b_y2, g_y2, be_y2, b3, out);
}

// round 9
// speedup vs baseline: 1.3668x; 1.0001x over previous
#include <cuda_runtime.h>
#include <cuda_bf16.h>
#include <math.h>
#include <stdint.h>

#define BB 2
#define CY 96
#define CS 48
#define NN 4096
#define SCALE 0.14433756729740643f  /* 48^-0.5 */

// ---------------- scratch ----------------------------------------------------
__device__ __align__(16) float g_Ype[BB*CY*NN];
__device__ __align__(16) float g_V  [BB*NN*CS];
__device__ __align__(16) __nv_bfloat16 g_Qh[BB*NN*CS], g_Ql[BB*NN*CS];
__device__ __align__(16) __nv_bfloat16 g_Kh[BB*NN*CS], g_Kl[BB*NN*CS];
__device__ __align__(16) __nv_bfloat16 g_Vth[BB*CS*NN], g_Vtl[BB*CS*NN];
__device__ __align__(16) float g_psum[BB*8*NN];
__device__ __align__(16) float g_Xp[8*BB*NN*CS];
__device__ __align__(16) float g_Y3p[3*BB*CY*NN];
__device__ __align__(16) float g_peS[CS*256];
__device__ __align__(16) float g_peY[CY*256];

// ---------------- helpers ----------------------------------------------------
__device__ __forceinline__ void mma16816(float* c, const uint32_t* a, const uint32_t* b) {
    asm volatile(
        "mma.sync.aligned.m16n8k16.row.col.f32.bf16.bf16.f32 "
        "{%0,%1,%2,%3}, {%4,%5,%6,%7}, {%8,%9}, {%0,%1,%2,%3};\n"
        : "+f"(c[0]), "+f"(c[1]), "+f"(c[2]), "+f"(c[3])
        : "r"(a[0]), "r"(a[1]), "r"(a[2]), "r"(a[3]), "r"(b[0]), "r"(b[1]));
}
__device__ __forceinline__ uint32_t bf2u(__nv_bfloat16 a, __nv_bfloat16 b) {
    __nv_bfloat162 v(a, b);
    return *reinterpret_cast<uint32_t*>(&v);
}
__device__ __forceinline__ void fma2(unsigned long long& d, unsigned long long a,
                                     unsigned long long b) {
    asm("fma.rn.f32x2 %0, %1, %2, %0;" : "+l"(d) : "l"(a), "l"(b));
}
__device__ __forceinline__ void cpa16(__nv_bfloat16* smem, const __nv_bfloat16* gmem) {
    uint32_t s = (uint32_t)__cvta_generic_to_shared(smem);
    asm volatile("cp.async.cg.shared.global [%0], [%1], 16;\n" :: "r"(s), "l"(gmem));
}
#define CPA_COMMIT() asm volatile("cp.async.commit_group;\n" ::: "memory")
#define CPA_WAIT(N)  asm volatile("cp.async.wait_group %0;\n" :: "n"(N) : "memory")

// ---------------- PE tables --------------------------------------------------
__device__ __forceinline__ float pe_val(int ch, int h, int w, int c) {
    int blk = ch / c, t = ch - blk * c;
    int pos = (blk < 2) ? h : w;    // torch broadcast quirk
    int half = c >> 1;
    if (t < half) {
        float invf = powf(10000.f, -2.f * (float)t / (float)c);
        return sinf((float)pos * invf);
    } else {
        float invf = powf(10000.f, -2.f * (float)(t - half) / (float)c);
        return cosf((float)pos * invf);
    }
}
__global__ void k_petab() {
    int i = blockIdx.x * 256 + threadIdx.x;
    if (i < CY * 256) {
        int ch = i >> 8, n = i & 255;
        g_peY[i] = pe_val(ch, n >> 4, n & 15, 32);
    } else {
        int j = i - CY * 256;
        if (j < CS * 256) {
            int ch = j >> 8, n = j & 255;
            g_peS[j] = pe_val(ch, n >> 4, n & 15, 16);
        }
    }
}

// ============================================================================
// FUSE1: [0,768) addpe_y | [768,896) proj_sv->V | [896,1024) proj_y1+QK
// ============================================================================
#define FUSE1_SMEM 55552
__global__ __launch_bounds__(256) void k_fuse1(
    const float* __restrict__ Y, const float* __restrict__ S,
    const float* __restrict__ w_s, const float* __restrict__ b_s,
    const float* __restrict__ g_s, const float* __restrict__ be_s,
    const float* __restrict__ Wv,
    const float* __restrict__ w_y, const float* __restrict__ b_y,
    const float* __restrict__ g_y, const float* __restrict__ be_y,
    const float* __restrict__ Wq, const float* __restrict__ Wk)
{
    extern __shared__ __align__(16) float pool[];
    int bx = blockIdx.x, t = threadIdx.x;

    if (bx < 768) {
        int i = (bx * 256 + t) * 4;
        int n = i & (NN - 1);
        int ch = (i >> 12) % CY;
        float4 s = *(const float4*)&Y[i];
        float4 p = *(const float4*)&g_peY[ch * 256 + (n & 255)];
        s.x += p.x; s.y += p.y; s.z += p.z; s.w += p.w;
        *(float4*)&g_Ype[i] = s;
        return;
    }

    if (bx < 896) {
        int j = bx - 768;
        int n0 = (j & 63) * 64, b = j >> 6;
        float* in_s = pool;
        float* wt   = pool + 3072;
        float* wv   = pool + 5376;
        float* s1   = pool + 7680;

        for (int i = t; i < CS * CS; i += 256) {
            int e = i % CS, c = i / CS;
            wt[i] = w_s[e * CS + c];
            wv[i] = Wv[i];
        }
        for (int i = t; i < CS * 64; i += 256) {
            int c = i >> 6, nl = i & 63;
            in_s[i] = S[(b * CS + c) * NN + n0 + nl]
                    + g_peS[c * 256 + ((n0 + nl) & 255)];
        }
        __syncthreads();

        int n = t & 63, eg = t >> 6;
        float acc[12];
#pragma unroll
        for (int k = 0; k < 12; k++) acc[k] = 0.f;
        for (int c = 0; c < CS; c++) {
            float x = in_s[c * 64 + n];
#pragma unroll
            for (int v = 0; v < 3; v++) {
                float4 w4 = *(const float4*)&wt[c * CS + eg * 12 + v * 4];
                acc[v*4+0] += w4.x * x; acc[v*4+1] += w4.y * x;
                acc[v*4+2] += w4.z * x; acc[v*4+3] += w4.w * x;
            }
        }
        float inv = rsqrtf(1.f + 1e-5f);
#pragma unroll
        for (int k = 0; k < 12; k++) {
            int e = eg * 12 + k;
            float y = (acc[k] + b_s[e]) * (g_s[e] * inv) + be_s[e];
            s1[n * 49 + e] = fmaxf(y, 0.f);
        }
        __syncthreads();

#pragma unroll
        for (int k = 0; k < 12; k++) acc[k] = 0.f;
        for (int d = 0; d < CS; d++) {
            float x = s1[n * 49 + d];
#pragma unroll
            for (int v = 0; v < 3; v++) {
                float4 w4 = *(const float4*)&wv[d * CS + eg * 12 + v * 4];
                acc[v*4+0] += w4.x * x; acc[v*4+1] += w4.y * x;
                acc[v*4+2] += w4.z * x; acc[v*4+3] += w4.w * x;
            }
        }
        float* dst = g_V + ((b * NN + n0 + n) * CS) + eg * 12;
#pragma unroll
        for (int v = 0; v < 3; v++)
            *(float4*)&dst[v * 4] = make_float4(acc[v*4], acc[v*4+1], acc[v*4+2], acc[v*4+3]);
        return;
    }

    {   // proj_y1 + QK fused; Y1 lives only in smem
        int j = bx - 896;
        int n0 = (j & 63) * 64, b = j >> 6;
        float* in_s = pool;            // [96][64]
        float* wt   = pool + 6144;     // [c][e]
        float* s1   = pool + 10752;    // [n][49]

        for (int i = t; i < CY * CS; i += 256) {
            int e = i % CS, c = i / CS;
            wt[i] = w_y[e * CY + c];
        }
        for (int i = t; i < CY * 64; i += 256) {
            int c = i >> 6, nl = i & 63;
            in_s[i] = Y[(b * CY + c) * NN + n0 + nl]
                    + g_peY[c * 256 + ((n0 + nl) & 255)];
        }
        __syncthreads();

        int n = t & 63, eg = t >> 6;
        float acc[12];
#pragma unroll
        for (int k = 0; k < 12; k++) acc[k] = 0.f;
        for (int c = 0; c < CY; c++) {
            float x = in_s[c * 64 + n];
#pragma unroll
            for (int v = 0; v < 3; v++) {
                float4 w4 = *(const float4*)&wt[c * CS + eg * 12 + v * 4];
                acc[v*4+0] += w4.x * x; acc[v*4+1] += w4.y * x;
                acc[v*4+2] += w4.z * x; acc[v*4+3] += w4.w * x;
            }
        }
        float inv = rsqrtf(1.f + 1e-5f);
#pragma unroll
        for (int k = 0; k < 12; k++) {
            int e = eg * 12 + k;
            float y = (acc[k] + b_y[e]) * (g_y[e] * inv) + be_y[e];
            s1[n * 49 + e] = fmaxf(y, 0.f);
        }
        __syncthreads();

        float* wq = pool;
        float* wk = pool + 2304;
        for (int i = t; i < CS * CS; i += 256) { wq[i] = Wq[i]; wk[i] = Wk[i]; }
        __syncthreads();

        float aq[12], ak[12];
#pragma unroll
        for (int k = 0; k < 12; k++) { aq[k] = 0.f; ak[k] = 0.f; }
        for (int d = 0; d < CS; d++) {
            float x = s1[n * 49 + d];
#pragma unroll
            for (int v = 0; v < 3; v++) {
                float4 q4 = *(const float4*)&wq[d * CS + eg * 12 + v * 4];
                float4 k4 = *(const float4*)&wk[d * CS + eg * 12 + v * 4];
                aq[v*4+0] += q4.x * x; aq[v*4+1] += q4.y * x;
                aq[v*4+2] += q4.z * x; aq[v*4+3] += q4.w * x;
                ak[v*4+0] += k4.x * x; ak[v*4+1] += k4.y * x;
                ak[v*4+2] += k4.z * x; ak[v*4+3] += k4.w * x;
            }
        }
        int base = (b * NN + n0 + n) * CS + eg * 12;
#pragma unroll
        for (int k = 0; k < 12; k++) {
            __nv_bfloat16 qh = __float2bfloat16(aq[k]);
            __nv_bfloat16 kh = __float2bfloat16(ak[k]);
            g_Qh[base + k] = qh;
            g_Ql[base + k] = __float2bfloat16(aq[k] - __bfloat162float(qh));
            g_Kh[base + k] = kh;
            g_Kl[base + k] = __float2bfloat16(ak[k] - __bfloat162float(kh));
        }
    }
}

// ============================================================================
// Pass 1: column sums. A = K-tile (persistent frags), B = Q chunks of 64
// (cp.async double-buffered). grid (32 kblk, 8 qq, BB) = 512. smem 57344 -> occ 3.
// ============================================================================
#define CS_SMEM 57344
__global__ __launch_bounds__(256) void k_colsum() {
    extern __shared__ __align__(16) unsigned char dsm[];
    __nv_bfloat16* KH = (__nv_bfloat16*)dsm;          // [128][56]
    __nv_bfloat16* KL = KH + 7168;
    __nv_bfloat16* QB = KH + 14336;                   // 2 bufs x (QH 3584 + QL 3584) el

    int k0 = blockIdx.x * 128, qq = blockIdx.y, b = blockIdx.z;
    int t = threadIdx.x, wid = t >> 5, l = t & 31;
    int lr = l >> 2, lc = (l & 3) * 2;
    int mb = wid * 16;

    {
        const __nv_bfloat16* s = g_Kh + (size_t)(b * NN + k0) * CS;
        for (int i = t; i < 768; i += 256) {
            int r = i / 6, c = i % 6;
            *(uint4*)(KH + r * 56 + c * 8) = *(const uint4*)(s + r * 48 + c * 8);
        }
        s = g_Kl + (size_t)(b * NN + k0) * CS;
        for (int i = t; i < 768; i += 256) {
            int r = i / 6, c = i % 6;
            *(uint4*)(KL + r * 56 + c * 8) = *(const uint4*)(s + r * 48 + c * 8);
        }
    }
    __syncthreads();

    uint32_t kfh[3][4], kfl[3][4];
#pragma unroll
    for (int ks = 0; ks < 3; ks++) {
        int ko = ks * 16;
        kfh[ks][0] = *(uint32_t*)&KH[(mb + lr) * 56 + ko + lc];
        kfh[ks][1] = *(uint32_t*)&KH[(mb + 8 + lr) * 56 + ko + lc];
        kfh[ks][2] = *(uint32_t*)&KH[(mb + lr) * 56 + ko + lc + 8];
        kfh[ks][3] = *(uint32_t*)&KH[(mb + 8 + lr) * 56 + ko + lc + 8];
        kfl[ks][0] = *(uint32_t*)&KL[(mb + lr) * 56 + ko + lc];
        kfl[ks][1] = *(uint32_t*)&KL[(mb + 8 + lr) * 56 + ko + lc];
        kfl[ks][2] = *(uint32_t*)&KL[(mb + lr) * 56 + ko + lc + 8];
        kfl[ks][3] = *(uint32_t*)&KL[(mb + 8 + lr) * 56 + ko + lc + 8];
    }

    // prefetch: stage 64-row Q chunk into buffer bi
    auto prefetchQ = [&](int ch, int bi) {
        int qb = qq * 512 + ch * 64;
        __nv_bfloat16* QH = QB + bi * 7168;
        __nv_bfloat16* QL = QH + 3584;
        const __nv_bfloat16* sh = g_Qh + (size_t)(b * NN + qb) * CS;
        const __nv_bfloat16* sl = g_Ql + (size_t)(b * NN + qb) * CS;
        for (int i = t; i < 384; i += 256) {
            int r = i / 6, c = i % 6;
            cpa16(QH + r * 56 + c * 8, sh + r * 48 + c * 8);
            cpa16(QL + r * 56 + c * 8, sl + r * 48 + c * 8);
        }
        CPA_COMMIT();
    };

    float rs0 = 0.f, rs1 = 0.f;
    prefetchQ(0, 0);
    for (int ch = 0; ch < 8; ch++) {
        if (ch < 7) prefetchQ(ch + 1, (ch + 1) & 1);
        if (ch < 7) { CPA_WAIT(1); } else { CPA_WAIT(0); }
        __syncthreads();
        __nv_bfloat16* QH = QB + (ch & 1) * 7168;
        __nv_bfloat16* QL = QH + 3584;

#pragma unroll
        for (int nfp = 0; nfp < 4; nfp++) {
            float a0[4] = {0.f,0.f,0.f,0.f}, a1[4] = {0.f,0.f,0.f,0.f};
#pragma unroll
            for (int ks = 0; ks < 3; ks++) {
                int ko = ks * 16;
                int i0 = (nfp * 16 + lr) * 56 + ko + lc;
                int i1 = i0 + 8 * 56;
                uint32_t bh0[2] = { *(uint32_t*)&QH[i0], *(uint32_t*)&QH[i0 + 8] };
                uint32_t bl0[2] = { *(uint32_t*)&QL[i0], *(uint32_t*)&QL[i0 + 8] };
                uint32_t bh1[2] = { *(uint32_t*)&QH[i1], *(uint32_t*)&QH[i1 + 8] };
                uint32_t bl1[2] = { *(uint32_t*)&QL[i1], *(uint32_t*)&QL[i1 + 8] };
                mma16816(a0, kfh[ks], bh0); mma16816(a0, kfl[ks], bh0); mma16816(a0, kfh[ks], bl0);
                mma16816(a1, kfh[ks], bh1); mma16816(a1, kfl[ks], bh1); mma16816(a1, kfh[ks], bl1);
            }
            rs0 += __expf(a0[0] * SCALE) + __expf(a0[1] * SCALE)
                 + __expf(a1[0] * SCALE) + __expf(a1[1] * SCALE);
            rs1 += __expf(a0[2] * SCALE) + __expf(a0[3] * SCALE)
                 + __expf(a1[2] * SCALE) + __expf(a1[3] * SCALE);
        }
        __syncthreads();
    }
    rs0 += __shfl_xor_sync(0xffffffffu, rs0, 1);
    rs0 += __shfl_xor_sync(0xffffffffu, rs0, 2);
    rs1 += __shfl_xor_sync(0xffffffffu, rs1, 1);
    rs1 += __shfl_xor_sync(0xffffffffu, rs1, 2);
    if ((l & 3) == 0) {
        g_psum[(b * 8 + qq) * NN + k0 + mb + lr]     = rs0;
        g_psum[(b * 8 + qq) * NN + k0 + mb + 8 + lr] = rs1;
    }
}

// ============================================================================
// vprime: V' = V / colsum, transposed [d][k], bf16 hi/lo. grid (128, BB).
// ============================================================================
__global__ __launch_bounds__(256) void k_vprime() {
    __shared__ float iz_s[32];
    __shared__ __nv_bfloat16 Th[48 * 34], Tl[48 * 34];

    int k0 = blockIdx.x * 32, b = blockIdx.y, t = threadIdx.x;
    if (t < 32) {
        int k = k0 + t;
        float s = 0.f;
#pragma unroll
        for (int i = 0; i < 8; i++) s += g_psum[(b * 8 + i) * NN + k];
        iz_s[t] = 1.f / s;
    }
    __syncthreads();

    const float* vsrc = g_V + (size_t)(b * NN + k0) * CS;
    for (int i = t; i < 32 * CS; i += 256) {
        int kk = i / CS, d = i - kk * CS;
        float val = vsrc[i] * iz_s[kk];
        __nv_bfloat16 h = __float2bfloat16(val);
        Th[d * 34 + kk] = h;
        Tl[d * 34 + kk] = __float2bfloat16(val - __bfloat162float(h));
    }
    __syncthreads();

    for (int j = t; j < 48 * 16; j += 256) {
        int d = j >> 4, c2 = (j & 15) * 2;
        *(uint32_t*)&g_Vth[(size_t)(b * CS + d) * NN + k0 + c2] =
            bf2u(Th[d * 34 + c2], Th[d * 34 + c2 + 1]);
        *(uint32_t*)&g_Vtl[(size_t)(b * CS + d) * NN + k0 + c2] =
            bf2u(Tl[d * 34 + c2], Tl[d * 34 + c2 + 1]);
    }
}

// ============================================================================
// flash pass2: P (recomputed, exp'd, split) fed directly as A-fragments into
// P @ V'. k-chunk 64, cp.async double-buffered K/V. grid (32, 8, BB) = 512.
// Q staging region overlaps K buffers (Q lives in regs after extraction).
// smem 56320 B -> occ 3.
// ============================================================================
#define FLASH_SMEM 56320
__global__ __launch_bounds__(256, 3) void k_flash() {
    extern __shared__ __align__(16) unsigned char dsm[];
    __nv_bfloat16* base = (__nv_bfloat16*)dsm;
    // Q staging (temporary): QH [128][56] at 0, QL at 7168  (14336 el)
    // K bufs: KB + i*7168 (KH), +3584 (KL)                   (14336 el, overlaps Q)
    // V bufs: VB = base+14336; + i*6912 (VH), +3456 (VL)     (13824 el)
    __nv_bfloat16* KB = base;
    __nv_bfloat16* VB = base + 14336;

    int qblk = blockIdx.x, kq = blockIdx.y, b = blockIdx.z;
    int t = threadIdx.x, wid = t >> 5, l = t & 31;
    int lr = l >> 2, lc = (l & 3) * 2;
    int q0 = qblk * 128, mb = wid * 16;

    {   // stage Q into the (soon reused) region
        __nv_bfloat16* QH = base;
        __nv_bfloat16* QL = base + 7168;
        const __nv_bfloat16* s = g_Qh + (size_t)(b * NN + q0) * CS;
        for (int i = t; i < 768; i += 256) {
            int r = i / 6, c = i % 6;
            *(uint4*)(QH + r * 56 + c * 8) = *(const uint4*)(s + r * 48 + c * 8);
        }
        s = g_Ql + (size_t)(b * NN + q0) * CS;
        for (int i = t; i < 768; i += 256) {
            int r = i / 6, c = i % 6;
            *(uint4*)(QL + r * 56 + c * 8) = *(const uint4*)(s + r * 48 + c * 8);
        }
    }
    __syncthreads();

    uint32_t qfh[3][4], qfl[3][4];
    {
        __nv_bfloat16* QH = base;
        __nv_bfloat16* QL = base + 7168;
#pragma unroll
        for (int ks = 0; ks < 3; ks++) {
            int ko = ks * 16;
            qfh[ks][0] = *(uint32_t*)&QH[(mb + lr) * 56 + ko + lc];
            qfh[ks][1] = *(uint32_t*)&QH[(mb + 8 + lr) * 56 + ko + lc];
            qfh[ks][2] = *(uint32_t*)&QH[(mb + lr) * 56 + ko + lc + 8];
            qfh[ks][3] = *(uint32_t*)&QH[(mb + 8 + lr) * 56 + ko + lc + 8];
            qfl[ks][0] = *(uint32_t*)&QL[(mb + lr) * 56 + ko + lc];
            qfl[ks][1] = *(uint32_t*)&QL[(mb + 8 + lr) * 56 + ko + lc];
            qfl[ks][2] = *(uint32_t*)&QL[(mb + lr) * 56 + ko + lc + 8];
            qfl[ks][3] = *(uint32_t*)&QL[(mb + 8 + lr) * 56 + ko + lc + 8];
        }
    }
    __syncthreads();   // all frag extraction done before K bufs overwrite Q region

    auto prefetchKV = [&](int ch, int bi) {
        int kb = kq * 512 + ch * 64;
        __nv_bfloat16* KHc = KB + bi * 7168;
        __nv_bfloat16* KLc = KHc + 3584;
        __nv_bfloat16* VHc = VB + bi * 6912;
        __nv_bfloat16* VLc = VHc + 3456;
        const __nv_bfloat16* skh = g_Kh + (size_t)(b * NN + kb) * CS;
        const __nv_bfloat16* skl = g_Kl + (size_t)(b * NN + kb) * CS;
        for (int i = t; i < 384; i += 256) {
            int r = i / 6, c = i % 6;
            cpa16(KHc + r * 56 + c * 8, skh + r * 48 + c * 8);
            cpa16(KLc + r * 56 + c * 8, skl + r * 48 + c * 8);
        }
        const __nv_bfloat16* svh = g_Vth + (size_t)(b * CS) * NN + kb;
        const __nv_bfloat16* svl = g_Vtl + (size_t)(b * CS) * NN + kb;
        for (int i = t; i < 384; i += 256) {
            int r = i / 8, c = i % 8;
            cpa16(VHc + r * 72 + c * 8, svh + (size_t)r * NN + c * 8);
            cpa16(VLc + r * 72 + c * 8, svl + (size_t)r * NN + c * 8);
        }
        CPA_COMMIT();
    };

    float pv[6][4];
#pragma unroll
    for (int nv = 0; nv < 6; nv++)
#pragma unroll
        for (int c = 0; c < 4; c++) pv[nv][c] = 0.f;

    prefetchKV(0, 0);
    for (int ch = 0; ch < 8; ch++) {
        if (ch < 7) prefetchKV(ch + 1, (ch + 1) & 1);
        if (ch < 7) { CPA_WAIT(1); } else { CPA_WAIT(0); }
        __syncthreads();
        __nv_bfloat16* KHc = KB + (ch & 1) * 7168;
        __nv_bfloat16* KLc = KHc + 3584;
        __nv_bfloat16* VHc = VB + (ch & 1) * 6912;
        __nv_bfloat16* VLc = VHc + 3456;

#pragma unroll
        for (int nfp = 0; nfp < 4; nfp++) {
            float a0[4] = {0.f,0.f,0.f,0.f}, a1[4] = {0.f,0.f,0.f,0.f};
#pragma unroll
            for (int ks = 0; ks < 3; ks++) {
                int ko = ks * 16;
                int i0 = (nfp * 16 + lr) * 56 + ko + lc;
                int i1 = i0 + 8 * 56;
                uint32_t bh0[2] = { *(uint32_t*)&KHc[i0], *(uint32_t*)&KHc[i0 + 8] };
                uint32_t bl0[2] = { *(uint32_t*)&KLc[i0], *(uint32_t*)&KLc[i0 + 8] };
                uint32_t bh1[2] = { *(uint32_t*)&KHc[i1], *(uint32_t*)&KHc[i1 + 8] };
                uint32_t bl1[2] = { *(uint32_t*)&KLc[i1], *(uint32_t*)&KLc[i1 + 8] };
                mma16816(a0, qfh[ks], bh0); mma16816(a0, qfl[ks], bh0); mma16816(a0, qfh[ks], bl0);
                mma16816(a1, qfh[ks], bh1); mma16816(a1, qfl[ks], bh1); mma16816(a1, qfh[ks], bl1);
            }
            float e0 = __expf(a0[0]*SCALE), e1 = __expf(a0[1]*SCALE);
            float e2 = __expf(a0[2]*SCALE), e3 = __expf(a0[3]*SCALE);
            float e4 = __expf(a1[0]*SCALE), e5 = __expf(a1[1]*SCALE);
            float e6 = __expf(a1[2]*SCALE), e7 = __expf(a1[3]*SCALE);
            __nv_bfloat16 h0 = __float2bfloat16(e0), h1 = __float2bfloat16(e1);
            __nv_bfloat16 h2 = __float2bfloat16(e2), h3 = __float2bfloat16(e3);
            __nv_bfloat16 h4 = __float2bfloat16(e4), h5 = __float2bfloat16(e5);
            __nv_bfloat16 h6 = __float2bfloat16(e6), h7 = __float2bfloat16(e7);
            uint32_t ph[4] = { bf2u(h0, h1), bf2u(h2, h3), bf2u(h4, h5), bf2u(h6, h7) };
            uint32_t pl[4] = {
                bf2u(__float2bfloat16(e0 - __bfloat162float(h0)),
                     __float2bfloat16(e1 - __bfloat162float(h1))),
                bf2u(__float2bfloat16(e2 - __bfloat162float(h2)),
                     __float2bfloat16(e3 - __bfloat162float(h3))),
                bf2u(__float2bfloat16(e4 - __bfloat162float(h4)),
                     __float2bfloat16(e5 - __bfloat162float(h5))),
                bf2u(__float2bfloat16(e6 - __bfloat162float(h6)),
                     __float2bfloat16(e7 - __bfloat162float(h7))) };
            int kop = nfp * 16;
#pragma unroll
            for (int nv = 0; nv < 6; nv++) {
                int iv = (nv * 8 + lr) * 72 + kop + lc;
                uint32_t vh[2] = { *(uint32_t*)&VHc[iv], *(uint32_t*)&VHc[iv + 8] };
                uint32_t vl[2] = { *(uint32_t*)&VLc[iv], *(uint32_t*)&VLc[iv + 8] };
                mma16816(pv[nv], ph, vh); mma16816(pv[nv], pl, vh); mma16816(pv[nv], ph, vl);
            }
        }
        __syncthreads();
    }

#pragma unroll
    for (int nv = 0; nv < 6; nv++) {
        int r = q0 + mb + lr, col = nv * 8 + lc;
        float* basep = &g_Xp[((size_t)(kq * BB + b) * NN + r) * CS + col];
        *(float2*)basep = make_float2(pv[nv][0], pv[nv][1]);
        *(float2*)(basep + 8 * CS) = make_float2(pv[nv][2], pv[nv][3]);
    }
}

// ============================================================================
// conv3d 3x3x3 (96->96), SAME, f32x2, ci-split-3; small static smem, own stream
// ============================================================================
__global__ __launch_bounds__(256) void k_conv3d(const float* __restrict__ w3) {
    __shared__ __align__(16) float in_s[3 * 18 * 18];
    __shared__ __align__(16) float ws[27 * 16];

    int cog = blockIdx.x, d = blockIdx.y;
    int b = blockIdx.z / 3, s = blockIdx.z % 3;
    int t = threadIdx.x, h = t >> 4, w = t & 15;

    unsigned long long acc[8];
#pragma unroll
    for (int k = 0; k < 8; k++) acc[k] = 0ull;

    for (int ci0 = 0; ci0 < 32; ci0++) {
        int ci = s * 32 + ci0;
        const float* src = g_Ype + (size_t)(b * CY + ci) * NN;
        for (int i = t; i < 3 * 324; i += 256) {
            int dd = i / 324, rem = i - dd * 324, r = rem / 18, c = rem - r * 18;
            int z = d + dd - 1, y = r - 1, x = c - 1;
            float v = 0.f;
            if (z >= 0 && z < 16 && y >= 0 && y < 16 && x >= 0 && x < 16)
                v = src[z * 256 + y * 16 + x];
            in_s[i] = v;
        }
        for (int i = t; i < 16 * 27; i += 256) {
            int tap = i % 27, co = i / 27;
            ws[tap * 16 + co] = w3[(size_t)(cog * 16 + co) * (CY * 27) + ci * 27 + tap];
        }
        __syncthreads();

        float in_r[27];
#pragma unroll
        for (int dd = 0; dd < 3; dd++)
#pragma unroll
            for (int dy = 0; dy < 3; dy++)
#pragma unroll
                for (int dx = 0; dx < 3; dx++)
                    in_r[dd*9+dy*3+dx] = in_s[dd*324 + (h+dy)*18 + (w+dx)];

#pragma unroll
        for (int tap = 0; tap < 27; tap++) {
            unsigned long long xx;
            asm("mov.b64 %0, {%1, %1};" : "=l"(xx) : "f"(in_r[tap]));
#pragma unroll
            for (int k = 0; k < 8; k++) {
                unsigned long long ww = *(const unsigned long long*)&ws[tap * 16 + 2 * k];
                fma2(acc[k], xx, ww);
            }
        }
        __syncthreads();
    }
    int n = d * 256 + t;
    float* dst = g_Y3p + (size_t)s * (BB * CY * NN)
               + (size_t)(b * CY + cog * 16) * NN + n;
#pragma unroll
    for (int k = 0; k < 8; k++) {
        float lo, hi;
        asm("mov.b64 {%0, %1}, %2;" : "=f"(lo), "=f"(hi) : "l"(acc[k]));
        dst[(2 * k) * NN]     = lo;
        dst[(2 * k + 1) * NN] = hi;
    }
}

// ============================================================================
// FUSE2: [0,128) zout | [128,256) y2out
// ============================================================================
#define FUSE2_SMEM 43008
__global__ __launch_bounds__(256) void k_fuse2(
    const float* __restrict__ S,
    const float* __restrict__ w_o, const float* __restrict__ b_o,
    const float* __restrict__ g_o, const float* __restrict__ be_o,
    const float* __restrict__ w_y2, const float* __restrict__ b_y2,
    const float* __restrict__ g_y2, const float* __restrict__ be_y2,
    const float* __restrict__ b3, float* __restrict__ out)
{
    extern __shared__ __align__(16) float pool[];
    int bx = blockIdx.x, t = threadIdx.x;

    if (bx < 128) {
        int n0 = (bx & 63) * 64, b = bx >> 6;
        float* xs  = pool;
        float* wot = pool + 3072;

        for (int i = t; i < CS * CS; i += 256) {
            int e = i % CS, d = i / CS;
            wot[i] = w_o[e * CS + d];
        }
        {
            int n = t & 63, v = t >> 6;
            const size_t cstride = (size_t)BB * NN * CS;
            const float* src = g_Xp + (size_t)(b * NN + n0 + n) * CS;
#pragma unroll
            for (int r = 0; r < 3; r++) {
                int dv = v + r * 4;
                float4 x = *(const float4*)&src[dv * 4];
#pragma unroll
                for (int p = 1; p < 8; p++) {
                    float4 xp = *(const float4*)&src[p * cstride + dv * 4];
                    x.x += xp.x; x.y += xp.y; x.z += xp.z; x.w += xp.w;
                }
                xs[(dv*4+0)*64+n] = x.x; xs[(dv*4+1)*64+n] = x.y;
                xs[(dv*4+2)*64+n] = x.z; xs[(dv*4+3)*64+n] = x.w;
            }
        }
        __syncthreads();

        int n = t & 63, eg = t >> 6;
        float acc[12];
#pragma unroll
        for (int k = 0; k < 12; k++) acc[k] = 0.f;
        for (int d = 0; d < CS; d++) {
            float x = xs[d * 64 + n];
#pragma unroll
            for (int v = 0; v < 3; v++) {
                float4 w4 = *(const float4*)&wot[d * CS + eg * 12 + v * 4];
                acc[v*4+0] += w4.x * x; acc[v*4+1] += w4.y * x;
                acc[v*4+2] += w4.z * x; acc[v*4+3] += w4.w * x;
            }
        }
        float inv = rsqrtf(1.f + 1e-5f);
#pragma unroll
        for (int k = 0; k < 12; k++) {
            int e = eg * 12 + k;
            float y = (acc[k] + b_o[e]) * (g_o[e] * inv) + be_o[e];
            y = fmaxf(y, 0.f);
            float spe = S[(b * CS + e) * NN + n0 + n]
                      + g_peS[e * 256 + ((n0 + n) & 255)];
            out[(b * 96 + e) * NN + n0 + n] = y * spe;
        }
        return;
    }

    {
        int j = bx - 128;
        int n0 = (j & 63) * 64, b = j >> 6;
        float* in_s = pool;
        float* wt   = pool + 6144;

        for (int i = t; i < CY * CS; i += 256) {
            int e = i % CS, c = i / CS;
            wt[i] = w_y2[e * CY + c];
        }
        const size_t pstride = (size_t)BB * CY * NN;
        const float* src = g_Y3p + (size_t)(b * CY) * NN + n0;
        for (int i = t; i < CY * 64; i += 256) {
            int c = i >> 6, n = i & 63;
            in_s[i] = src[c * NN + n] + src[pstride + c * NN + n]
                    + src[2 * pstride + c * NN + n] + b3[c];
        }
        __syncthreads();

        int n = t & 63, eg = t >> 6;
        float acc[12];
#pragma unroll
        for (int k = 0; k < 12; k++) acc[k] = 0.f;
        for (int c = 0; c < CY; c++) {
            float x = in_s[c * 64 + n];
#pragma unroll
            for (int v = 0; v < 3; v++) {
                float4 w4 = *(const float4*)&wt[c * CS + eg * 12 + v * 4];
                acc[v*4+0] += w4.x * x; acc[v*4+1] += w4.y * x;
                acc[v*4+2] += w4.z * x; acc[v*4+3] += w4.w * x;
            }
        }
        float inv = rsqrtf(1.f + 1e-5f);
#pragma unroll
        for (int k = 0; k < 12; k++) {
            int e = eg * 12 + k;
            float y = (acc[k] + b_y2[e]) * (g_y2[e] * inv) + be_y2[e];
            out[(b * 96 + 48 + e) * NN + n0 + n] = fmaxf(y, 0.f);
        }
    }
}

// ---------------- launch -----------------------------------------------------
extern "C" void kernel_launch(void* const* d_in, const int* in_sizes, int n_in,
                              void* d_out, int out_size)
{
    const float* Y    = (const float*)d_in[0];
    const float* S    = (const float*)d_in[1];
    const float* w_s  = (const float*)d_in[2];
    const float* b_s  = (const float*)d_in[3];
    const float* g_s  = (const float*)d_in[4];
    const float* be_s = (const float*)d_in[5];
    const float* w_y  = (const float*)d_in[6];
    const float* b_y  = (const float*)d_in[7];
    const float* g_y  = (const float*)d_in[8];
    const float* be_y = (const float*)d_in[9];
    const float* Wq   = (const float*)d_in[10];
    const float* Wk   = (const float*)d_in[11];
    const float* Wv   = (const float*)d_in[12];
    const float* w_o  = (const float*)d_in[13];
    const float* b_o  = (const float*)d_in[14];
    const float* g_o  = (const float*)d_in[15];
    const float* be_o = (const float*)d_in[16];
    const float* w3   = (const float*)d_in[17];
    const float* b3   = (const float*)d_in[18];
    const float* w_y2 = (const float*)d_in[19];
    const float* b_y2 = (const float*)d_in[20];
    const float* g_y2 = (const float*)d_in[21];
    const float* be_y2= (const float*)d_in[22];
    float* out = (float*)d_out;

    static cudaStream_t s2 = nullptr;
    static cudaEvent_t ev1 = nullptr, ev2 = nullptr;
    static int attr_done = 0;
    if (!attr_done) {
        cudaFuncSetAttribute(k_fuse1,  cudaFuncAttributeMaxDynamicSharedMemorySize, FUSE1_SMEM);
        cudaFuncSetAttribute(k_colsum, cudaFuncAttributeMaxDynamicSharedMemorySize, CS_SMEM);
        cudaFuncSetAttribute(k_flash,  cudaFuncAttributeMaxDynamicSharedMemorySize, FLASH_SMEM);
        cudaStreamCreateWithFlags(&s2, cudaStreamNonBlocking);
        cudaEventCreateWithFlags(&ev1, cudaEventDisableTiming);
        cudaEventCreateWithFlags(&ev2, cudaEventDisableTiming);
        attr_done = 1;
    }

    k_petab <<<144, 256>>>();
    k_fuse1 <<<1024, 256, FUSE1_SMEM>>>(Y, S, w_s, b_s, g_s, be_s, Wv,
                                        w_y, b_y, g_y, be_y, Wq, Wk);
    // fork: conv3d on s2, attention chain on default stream
    cudaEventRecord(ev1, 0);
    cudaStreamWaitEvent(s2, ev1, 0);
    k_conv3d<<<dim3(6, 16, BB * 3), 256, 0, s2>>>(w3);
    cudaEventRecord(ev2, s2);

    k_colsum<<<dim3(32, 8, BB), 256, CS_SMEM>>>();
    k_vprime<<<dim3(128, BB), 256>>>();
    k_flash <<<dim3(32, 8, BB), 256, FLASH_SMEM>>>();

    cudaStreamWaitEvent(0, ev2, 0);
    k_fuse2 <<<256, 256, FUSE2_SMEM>>>(S, w_o, b_o, g_o, be_o,
                                       w_y2, b_y2, g_y2, be_y2, b3, out);
}

// round 10
// speedup vs baseline: 1.6209x; 1.1859x over previous
#include <cuda_runtime.h>
#include <cuda_bf16.h>
#include <math.h>
#include <stdint.h>

#define BB 2
#define CY 96
#define CS 48
#define NN 4096
#define SCALE 0.14433756729740643f  /* 48^-0.5 */
#define QSC   0.20822193f           /* SCALE * log2(e) */

// ---------------- scratch ----------------------------------------------------
__device__ __align__(16) float g_Ype[BB*CY*NN];
__device__ __align__(16) float g_V  [BB*NN*CS];
__device__ __align__(16) __nv_bfloat16 g_Qh[BB*NN*CS];
__device__ __align__(16) __nv_bfloat16 g_Kh[BB*NN*CS];
__device__ __align__(16) __nv_bfloat16 g_Vth[BB*CS*NN], g_Vtl[BB*CS*NN];
__device__ __align__(16) float g_psum[BB*8*NN];
__device__ __align__(16) float g_Xp[8*BB*NN*CS];
__device__ __align__(16) float g_Y3p[3*BB*CY*NN];
__device__ __align__(16) float g_peS[CS*256];
__device__ __align__(16) float g_peY[CY*256];

// ---------------- helpers ----------------------------------------------------
__device__ __forceinline__ void mma16816(float* c, const uint32_t* a, const uint32_t* b) {
    asm volatile(
        "mma.sync.aligned.m16n8k16.row.col.f32.bf16.bf16.f32 "
        "{%0,%1,%2,%3}, {%4,%5,%6,%7}, {%8,%9}, {%0,%1,%2,%3};\n"
        : "+f"(c[0]), "+f"(c[1]), "+f"(c[2]), "+f"(c[3])
        : "r"(a[0]), "r"(a[1]), "r"(a[2]), "r"(a[3]), "r"(b[0]), "r"(b[1]));
}
__device__ __forceinline__ uint32_t bf2u(__nv_bfloat16 a, __nv_bfloat16 b) {
    __nv_bfloat162 v(a, b);
    return *reinterpret_cast<uint32_t*>(&v);
}
// packed convert: result = {lo: cvt(lo), hi: cvt(hi)}
__device__ __forceinline__ uint32_t cvt2bf(float lo, float hi) {
    uint32_t r;
    asm("cvt.rn.bf16x2.f32 %0, %1, %2;" : "=r"(r) : "f"(hi), "f"(lo));
    return r;
}
__device__ __forceinline__ void fma2(unsigned long long& d, unsigned long long a,
                                     unsigned long long b) {
    asm("fma.rn.f32x2 %0, %1, %2, %0;" : "+l"(d) : "l"(a), "l"(b));
}
__device__ __forceinline__ void cpa16(__nv_bfloat16* smem, const __nv_bfloat16* gmem) {
    uint32_t s = (uint32_t)__cvta_generic_to_shared(smem);
    asm volatile("cp.async.cg.shared.global [%0], [%1], 16;\n" :: "r"(s), "l"(gmem));
}
#define CPA_COMMIT() asm volatile("cp.async.commit_group;\n" ::: "memory")
#define CPA_WAIT(N)  asm volatile("cp.async.wait_group %0;\n" :: "n"(N) : "memory")

// ldmatrix x4 (non-transposed): 4 8x8 bf16 tiles -> 4 regs
__device__ __forceinline__ void ldsm4(uint32_t* r, uint32_t saddr) {
    asm volatile("ldmatrix.sync.aligned.m8n8.x4.shared.b16 {%0,%1,%2,%3}, [%4];"
        : "=r"(r[0]), "=r"(r[1]), "=r"(r[2]), "=r"(r[3]) : "r"(saddr));
}

// ---------------- PE tables --------------------------------------------------
__device__ __forceinline__ float pe_val(int ch, int h, int w, int c) {
    int blk = ch / c, t = ch - blk * c;
    int pos = (blk < 2) ? h : w;    // torch broadcast quirk
    int half = c >> 1;
    if (t < half) {
        float invf = powf(10000.f, -2.f * (float)t / (float)c);
        return sinf((float)pos * invf);
    } else {
        float invf = powf(10000.f, -2.f * (float)(t - half) / (float)c);
        return cosf((float)pos * invf);
    }
}
__global__ void k_petab() {
    int i = blockIdx.x * 256 + threadIdx.x;
    if (i < CY * 256) {
        int ch = i >> 8, n = i & 255;
        g_peY[i] = pe_val(ch, n >> 4, n & 15, 32);
    } else {
        int j = i - CY * 256;
        if (j < CS * 256) {
            int ch = j >> 8, n = j & 255;
            g_peS[j] = pe_val(ch, n >> 4, n & 15, 16);
        }
    }
}

// ============================================================================
// FUSE1: [0,768) addpe_y | [768,896) proj_sv->V | [896,1024) proj_y1+QK
// ============================================================================
#define FUSE1_SMEM 55552
__global__ __launch_bounds__(256) void k_fuse1(
    const float* __restrict__ Y, const float* __restrict__ S,
    const float* __restrict__ w_s, const float* __restrict__ b_s,
    const float* __restrict__ g_s, const float* __restrict__ be_s,
    const float* __restrict__ Wv,
    const float* __restrict__ w_y, const float* __restrict__ b_y,
    const float* __restrict__ g_y, const float* __restrict__ be_y,
    const float* __restrict__ Wq, const float* __restrict__ Wk)
{
    extern __shared__ __align__(16) float pool[];
    int bx = blockIdx.x, t = threadIdx.x;

    if (bx < 768) {
        int i = (bx * 256 + t) * 4;
        int n = i & (NN - 1);
        int ch = (i >> 12) % CY;
        float4 s = *(const float4*)&Y[i];
        float4 p = *(const float4*)&g_peY[ch * 256 + (n & 255)];
        s.x += p.x; s.y += p.y; s.z += p.z; s.w += p.w;
        *(float4*)&g_Ype[i] = s;
        return;
    }

    if (bx < 896) {
        int j = bx - 768;
        int n0 = (j & 63) * 64, b = j >> 6;
        float* in_s = pool;
        float* wt   = pool + 3072;
        float* wv   = pool + 5376;
        float* s1   = pool + 7680;

        for (int i = t; i < CS * CS; i += 256) {
            int e = i % CS, c = i / CS;
            wt[i] = w_s[e * CS + c];
            wv[i] = Wv[i];
        }
        for (int i = t; i < CS * 64; i += 256) {
            int c = i >> 6, nl = i & 63;
            in_s[i] = S[(b * CS + c) * NN + n0 + nl]
                    + g_peS[c * 256 + ((n0 + nl) & 255)];
        }
        __syncthreads();

        int n = t & 63, eg = t >> 6;
        float acc[12];
#pragma unroll
        for (int k = 0; k < 12; k++) acc[k] = 0.f;
        for (int c = 0; c < CS; c++) {
            float x = in_s[c * 64 + n];
#pragma unroll
            for (int v = 0; v < 3; v++) {
                float4 w4 = *(const float4*)&wt[c * CS + eg * 12 + v * 4];
                acc[v*4+0] += w4.x * x; acc[v*4+1] += w4.y * x;
                acc[v*4+2] += w4.z * x; acc[v*4+3] += w4.w * x;
            }
        }
        float inv = rsqrtf(1.f + 1e-5f);
#pragma unroll
        for (int k = 0; k < 12; k++) {
            int e = eg * 12 + k;
            float y = (acc[k] + b_s[e]) * (g_s[e] * inv) + be_s[e];
            s1[n * 49 + e] = fmaxf(y, 0.f);
        }
        __syncthreads();

#pragma unroll
        for (int k = 0; k < 12; k++) acc[k] = 0.f;
        for (int d = 0; d < CS; d++) {
            float x = s1[n * 49 + d];
#pragma unroll
            for (int v = 0; v < 3; v++) {
                float4 w4 = *(const float4*)&wv[d * CS + eg * 12 + v * 4];
                acc[v*4+0] += w4.x * x; acc[v*4+1] += w4.y * x;
                acc[v*4+2] += w4.z * x; acc[v*4+3] += w4.w * x;
            }
        }
        float* dst = g_V + ((b * NN + n0 + n) * CS) + eg * 12;
#pragma unroll
        for (int v = 0; v < 3; v++)
            *(float4*)&dst[v * 4] = make_float4(acc[v*4], acc[v*4+1], acc[v*4+2], acc[v*4+3]);
        return;
    }

    {   // proj_y1 + QK fused; Y1 lives only in smem. Q pre-scaled by QSC.
        int j = bx - 896;
        int n0 = (j & 63) * 64, b = j >> 6;
        float* in_s = pool;            // [96][64]
        float* wt   = pool + 6144;     // [c][e]
        float* s1   = pool + 10752;    // [n][49]

        for (int i = t; i < CY * CS; i += 256) {
            int e = i % CS, c = i / CS;
            wt[i] = w_y[e * CY + c];
        }
        for (int i = t; i < CY * 64; i += 256) {
            int c = i >> 6, nl = i & 63;
            in_s[i] = Y[(b * CY + c) * NN + n0 + nl]
                    + g_peY[c * 256 + ((n0 + nl) & 255)];
        }
        __syncthreads();

        int n = t & 63, eg = t >> 6;
        float acc[12];
#pragma unroll
        for (int k = 0; k < 12; k++) acc[k] = 0.f;
        for (int c = 0; c < CY; c++) {
            float x = in_s[c * 64 + n];
#pragma unroll
            for (int v = 0; v < 3; v++) {
                float4 w4 = *(const float4*)&wt[c * CS + eg * 12 + v * 4];
                acc[v*4+0] += w4.x * x; acc[v*4+1] += w4.y * x;
                acc[v*4+2] += w4.z * x; acc[v*4+3] += w4.w * x;
            }
        }
        float inv = rsqrtf(1.f + 1e-5f);
#pragma unroll
        for (int k = 0; k < 12; k++) {
            int e = eg * 12 + k;
            float y = (acc[k] + b_y[e]) * (g_y[e] * inv) + be_y[e];
            s1[n * 49 + e] = fmaxf(y, 0.f);
        }
        __syncthreads();

        float* wq = pool;
        float* wk = pool + 2304;
        for (int i = t; i < CS * CS; i += 256) { wq[i] = Wq[i]; wk[i] = Wk[i]; }
        __syncthreads();

        float aq[12], ak[12];
#pragma unroll
        for (int k = 0; k < 12; k++) { aq[k] = 0.f; ak[k] = 0.f; }
        for (int d = 0; d < CS; d++) {
            float x = s1[n * 49 + d];
#pragma unroll
            for (int v = 0; v < 3; v++) {
                float4 q4 = *(const float4*)&wq[d * CS + eg * 12 + v * 4];
                float4 k4 = *(const float4*)&wk[d * CS + eg * 12 + v * 4];
                aq[v*4+0] += q4.x * x; aq[v*4+1] += q4.y * x;
                aq[v*4+2] += q4.z * x; aq[v*4+3] += q4.w * x;
                ak[v*4+0] += k4.x * x; ak[v*4+1] += k4.y * x;
                ak[v*4+2] += k4.z * x; ak[v*4+3] += k4.w * x;
            }
        }
        int base = (b * NN + n0 + n) * CS + eg * 12;
#pragma unroll
        for (int k = 0; k < 12; k++) {
            g_Qh[base + k] = __float2bfloat16(aq[k] * QSC);
            g_Kh[base + k] = __float2bfloat16(ak[k]);
        }
    }
}

// ============================================================================
// Pass 1: column sums. A = K-tile (persistent hi frags), B = Q chunks of 64
// (cp.async double-buffered, hi only). 1-term QK. grid (32, 8, BB).
// smem = 14336 (KH) + 2*7168 (QH bufs) = 28672 B.
// ============================================================================
#define CS_SMEM 28672
__global__ __launch_bounds__(256) void k_colsum() {
    extern __shared__ __align__(16) unsigned char dsm[];
    __nv_bfloat16* KH = (__nv_bfloat16*)dsm;          // [128][56]
    __nv_bfloat16* QB = KH + 7168;                    // 2 bufs x QH[64][56]

    int k0 = blockIdx.x * 128, qq = blockIdx.y, b = blockIdx.z;
    int t = threadIdx.x, wid = t >> 5, l = t & 31;
    int lr = l >> 2, lc = (l & 3) * 2;
    int mb = wid * 16;

    {
        const __nv_bfloat16* s = g_Kh + (size_t)(b * NN + k0) * CS;
        for (int i = t; i < 768; i += 256) {
            int r = i / 6, c = i % 6;
            *(uint4*)(KH + r * 56 + c * 8) = *(const uint4*)(s + r * 48 + c * 8);
        }
    }
    __syncthreads();

    uint32_t kfh[3][4];
#pragma unroll
    for (int ks = 0; ks < 3; ks++) {
        int ko = ks * 16;
        kfh[ks][0] = *(uint32_t*)&KH[(mb + lr) * 56 + ko + lc];
        kfh[ks][1] = *(uint32_t*)&KH[(mb + 8 + lr) * 56 + ko + lc];
        kfh[ks][2] = *(uint32_t*)&KH[(mb + lr) * 56 + ko + lc + 8];
        kfh[ks][3] = *(uint32_t*)&KH[(mb + 8 + lr) * 56 + ko + lc + 8];
    }

    // ldmatrix lane addressing for B-frags (rows n, k-offset pattern)
    int lg = l >> 3, lrow = l & 7;
    int rowext = ((lg & 2) ? 8 : 0) + lrow;       // row within 16-row group
    int colext = (lg & 1) ? 8 : 0;                // k offset 0/8

    auto prefetchQ = [&](int ch, int bi) {
        int qb = qq * 512 + ch * 64;
        __nv_bfloat16* QH = QB + bi * 3584;
        const __nv_bfloat16* sh = g_Qh + (size_t)(b * NN + qb) * CS;
        for (int i = t; i < 384; i += 256) {
            int r = i / 6, c = i % 6;
            cpa16(QH + r * 56 + c * 8, sh + r * 48 + c * 8);
        }
        CPA_COMMIT();
    };

    float rs0 = 0.f, rs1 = 0.f;
    prefetchQ(0, 0);
    for (int ch = 0; ch < 8; ch++) {
        if (ch < 7) prefetchQ(ch + 1, (ch + 1) & 1);
        if (ch < 7) { CPA_WAIT(1); } else { CPA_WAIT(0); }
        __syncthreads();
        __nv_bfloat16* QH = QB + (ch & 1) * 3584;
        uint32_t qbase = (uint32_t)__cvta_generic_to_shared(QH);

#pragma unroll
        for (int nfp = 0; nfp < 4; nfp++) {
            float a0[4] = {0.f,0.f,0.f,0.f}, a1[4] = {0.f,0.f,0.f,0.f};
#pragma unroll
            for (int ks = 0; ks < 3; ks++) {
                int ko = ks * 16;
                uint32_t bf[4];
                ldsm4(bf, qbase + ((nfp * 16 + rowext) * 56 + ko + colext) * 2);
                mma16816(a0, kfh[ks], bf);       // bf[0],bf[1]
                mma16816(a1, kfh[ks], bf + 2);   // bf[2],bf[3]
            }
            rs0 += exp2f(a0[0]) + exp2f(a0[1]) + exp2f(a1[0]) + exp2f(a1[1]);
            rs1 += exp2f(a0[2]) + exp2f(a0[3]) + exp2f(a1[2]) + exp2f(a1[3]);
        }
        __syncthreads();
    }
    rs0 += __shfl_xor_sync(0xffffffffu, rs0, 1);
    rs0 += __shfl_xor_sync(0xffffffffu, rs0, 2);
    rs1 += __shfl_xor_sync(0xffffffffu, rs1, 1);
    rs1 += __shfl_xor_sync(0xffffffffu, rs1, 2);
    if ((l & 3) == 0) {
        g_psum[(b * 8 + qq) * NN + k0 + mb + lr]     = rs0;
        g_psum[(b * 8 + qq) * NN + k0 + mb + 8 + lr] = rs1;
    }
}

// ============================================================================
// vprime: V' = V / colsum, transposed [d][k], bf16 hi/lo. grid (128, BB).
// ============================================================================
__global__ __launch_bounds__(256) void k_vprime() {
    __shared__ float iz_s[32];
    __shared__ __nv_bfloat16 Th[48 * 34], Tl[48 * 34];

    int k0 = blockIdx.x * 32, b = blockIdx.y, t = threadIdx.x;
    if (t < 32) {
        int k = k0 + t;
        float s = 0.f;
#pragma unroll
        for (int i = 0; i < 8; i++) s += g_psum[(b * 8 + i) * NN + k];
        iz_s[t] = 1.f / s;
    }
    __syncthreads();

    const float* vsrc = g_V + (size_t)(b * NN + k0) * CS;
    for (int i = t; i < 32 * CS; i += 256) {
        int kk = i / CS, d = i - kk * CS;
        float val = vsrc[i] * iz_s[kk];
        __nv_bfloat16 h = __float2bfloat16(val);
        Th[d * 34 + kk] = h;
        Tl[d * 34 + kk] = __float2bfloat16(val - __bfloat162float(h));
    }
    __syncthreads();

    for (int j = t; j < 48 * 16; j += 256) {
        int d = j >> 4, c2 = (j & 15) * 2;
        *(uint32_t*)&g_Vth[(size_t)(b * CS + d) * NN + k0 + c2] =
            bf2u(Th[d * 34 + c2], Th[d * 34 + c2 + 1]);
        *(uint32_t*)&g_Vtl[(size_t)(b * CS + d) * NN + k0 + c2] =
            bf2u(Tl[d * 34 + c2], Tl[d * 34 + c2 + 1]);
    }
}

// ============================================================================
// flash pass2: 1-term QK recompute -> exp2 -> P (hi) as A-frags into 2-term
// P @ V' (Vh + Vl). k-chunk 64, cp.async double-buffered. grid (32, 8, BB).
// smem: Q staging [128][56] (7168 el) overlapped with K bufs (2x3584 el);
//       V bufs 2 x (VH 3456 + VL 3456) el. total 20992 el = 41984 B.
// ============================================================================
#define FLASH_SMEM 41984
__global__ __launch_bounds__(256) void k_flash() {
    extern __shared__ __align__(16) unsigned char dsm[];
    __nv_bfloat16* base = (__nv_bfloat16*)dsm;
    __nv_bfloat16* KB = base;                 // 2 bufs x KH[64][56], overlaps Q staging
    __nv_bfloat16* VB = base + 7168;          // 2 bufs x (VH[48][72] + VL[48][72])

    int qblk = blockIdx.x, kq = blockIdx.y, b = blockIdx.z;
    int t = threadIdx.x, wid = t >> 5, l = t & 31;
    int lr = l >> 2, lc = (l & 3) * 2;
    int q0 = qblk * 128, mb = wid * 16;

    {   // stage Q hi into the (soon reused) region
        __nv_bfloat16* QH = base;
        const __nv_bfloat16* s = g_Qh + (size_t)(b * NN + q0) * CS;
        for (int i = t; i < 768; i += 256) {
            int r = i / 6, c = i % 6;
            *(uint4*)(QH + r * 56 + c * 8) = *(const uint4*)(s + r * 48 + c * 8);
        }
    }
    __syncthreads();

    uint32_t qfh[3][4];
    {
        __nv_bfloat16* QH = base;
#pragma unroll
        for (int ks = 0; ks < 3; ks++) {
            int ko = ks * 16;
            qfh[ks][0] = *(uint32_t*)&QH[(mb + lr) * 56 + ko + lc];
            qfh[ks][1] = *(uint32_t*)&QH[(mb + 8 + lr) * 56 + ko + lc];
            qfh[ks][2] = *(uint32_t*)&QH[(mb + lr) * 56 + ko + lc + 8];
            qfh[ks][3] = *(uint32_t*)&QH[(mb + 8 + lr) * 56 + ko + lc + 8];
        }
    }
    __syncthreads();   // frag extraction done before K bufs overwrite Q region

    int lg = l >> 3, lrow = l & 7;
    int rowext = ((lg & 2) ? 8 : 0) + lrow;
    int colext = (lg & 1) ? 8 : 0;

    auto prefetchKV = [&](int ch, int bi) {
        int kb = kq * 512 + ch * 64;
        __nv_bfloat16* KHc = KB + bi * 3584;
        __nv_bfloat16* VHc = VB + bi * 6912;
        __nv_bfloat16* VLc = VHc + 3456;
        const __nv_bfloat16* skh = g_Kh + (size_t)(b * NN + kb) * CS;
        for (int i = t; i < 384; i += 256) {
            int r = i / 6, c = i % 6;
            cpa16(KHc + r * 56 + c * 8, skh + r * 48 + c * 8);
        }
        const __nv_bfloat16* svh = g_Vth + (size_t)(b * CS) * NN + kb;
        const __nv_bfloat16* svl = g_Vtl + (size_t)(b * CS) * NN + kb;
        for (int i = t; i < 384; i += 256) {
            int r = i / 8, c = i % 8;
            cpa16(VHc + r * 72 + c * 8, svh + (size_t)r * NN + c * 8);
            cpa16(VLc + r * 72 + c * 8, svl + (size_t)r * NN + c * 8);
        }
        CPA_COMMIT();
    };

    float pv[6][4];
#pragma unroll
    for (int nv = 0; nv < 6; nv++)
#pragma unroll
        for (int c = 0; c < 4; c++) pv[nv][c] = 0.f;

    prefetchKV(0, 0);
    for (int ch = 0; ch < 8; ch++) {
        if (ch < 7) prefetchKV(ch + 1, (ch + 1) & 1);
        if (ch < 7) { CPA_WAIT(1); } else { CPA_WAIT(0); }
        __syncthreads();
        __nv_bfloat16* KHc = KB + (ch & 1) * 3584;
        __nv_bfloat16* VHc = VB + (ch & 1) * 6912;
        __nv_bfloat16* VLc = VHc + 3456;
        uint32_t kbase = (uint32_t)__cvta_generic_to_shared(KHc);
        uint32_t vhb   = (uint32_t)__cvta_generic_to_shared(VHc);
        uint32_t vlb   = (uint32_t)__cvta_generic_to_shared(VLc);

#pragma unroll
        for (int nfp = 0; nfp < 4; nfp++) {
            float a0[4] = {0.f,0.f,0.f,0.f}, a1[4] = {0.f,0.f,0.f,0.f};
#pragma unroll
            for (int ks = 0; ks < 3; ks++) {
                int ko = ks * 16;
                uint32_t bf[4];
                ldsm4(bf, kbase + ((nfp * 16 + rowext) * 56 + ko + colext) * 2);
                mma16816(a0, qfh[ks], bf);
                mma16816(a1, qfh[ks], bf + 2);
            }
            uint32_t ph[4];
            ph[0] = cvt2bf(exp2f(a0[0]), exp2f(a0[1]));
            ph[1] = cvt2bf(exp2f(a0[2]), exp2f(a0[3]));
            ph[2] = cvt2bf(exp2f(a1[0]), exp2f(a1[1]));
            ph[3] = cvt2bf(exp2f(a1[2]), exp2f(a1[3]));
            int kop = nfp * 16;
#pragma unroll
            for (int p2 = 0; p2 < 3; p2++) {   // nv pairs (2p2, 2p2+1)
                uint32_t vh[4], vl[4];
                uint32_t off = ((p2 * 16 + rowext) * 72 + kop + colext) * 2;
                ldsm4(vh, vhb + off);
                ldsm4(vl, vlb + off);
                mma16816(pv[2*p2],     ph, vh);
                mma16816(pv[2*p2],     ph, vl);
                mma16816(pv[2*p2 + 1], ph, vh + 2);
                mma16816(pv[2*p2 + 1], ph, vl + 2);
            }
        }
        __syncthreads();
    }

#pragma unroll
    for (int nv = 0; nv < 6; nv++) {
        int r = q0 + mb + lr, col = nv * 8 + lc;
        float* basep = &g_Xp[((size_t)(kq * BB + b) * NN + r) * CS + col];
        *(float2*)basep = make_float2(pv[nv][0], pv[nv][1]);
        *(float2*)(basep + 8 * CS) = make_float2(pv[nv][2], pv[nv][3]);
    }
}

// ============================================================================
// conv3d 3x3x3 (96->96), SAME, f32x2, ci-split-3; own stream
// ============================================================================
__global__ __launch_bounds__(256) void k_conv3d(const float* __restrict__ w3) {
    __shared__ __align__(16) float in_s[3 * 18 * 18];
    __shared__ __align__(16) float ws[27 * 16];

    int cog = blockIdx.x, d = blockIdx.y;
    int b = blockIdx.z / 3, s = blockIdx.z % 3;
    int t = threadIdx.x, h = t >> 4, w = t & 15;

    unsigned long long acc[8];
#pragma unroll
    for (int k = 0; k < 8; k++) acc[k] = 0ull;

    for (int ci0 = 0; ci0 < 32; ci0++) {
        int ci = s * 32 + ci0;
        const float* src = g_Ype + (size_t)(b * CY + ci) * NN;
        for (int i = t; i < 3 * 324; i += 256) {
            int dd = i / 324, rem = i - dd * 324, r = rem / 18, c = rem - r * 18;
            int z = d + dd - 1, y = r - 1, x = c - 1;
            float v = 0.f;
            if (z >= 0 && z < 16 && y >= 0 && y < 16 && x >= 0 && x < 16)
                v = src[z * 256 + y * 16 + x];
            in_s[i] = v;
        }
        for (int i = t; i < 16 * 27; i += 256) {
            int tap = i % 27, co = i / 27;
            ws[tap * 16 + co] = w3[(size_t)(cog * 16 + co) * (CY * 27) + ci * 27 + tap];
        }
        __syncthreads();

        float in_r[27];
#pragma unroll
        for (int dd = 0; dd < 3; dd++)
#pragma unroll
            for (int dy = 0; dy < 3; dy++)
#pragma unroll
                for (int dx = 0; dx < 3; dx++)
                    in_r[dd*9+dy*3+dx] = in_s[dd*324 + (h+dy)*18 + (w+dx)];

#pragma unroll
        for (int tap = 0; tap < 27; tap++) {
            unsigned long long xx;
            asm("mov.b64 %0, {%1, %1};" : "=l"(xx) : "f"(in_r[tap]));
#pragma unroll
            for (int k = 0; k < 8; k++) {
                unsigned long long ww = *(const unsigned long long*)&ws[tap * 16 + 2 * k];
                fma2(acc[k], xx, ww);
            }
        }
        __syncthreads();
    }
    int n = d * 256 + t;
    float* dst = g_Y3p + (size_t)s * (BB * CY * NN)
               + (size_t)(b * CY + cog * 16) * NN + n;
#pragma unroll
    for (int k = 0; k < 8; k++) {
        float lo, hi;
        asm("mov.b64 {%0, %1}, %2;" : "=f"(lo), "=f"(hi) : "l"(acc[k]));
        dst[(2 * k) * NN]     = lo;
        dst[(2 * k + 1) * NN] = hi;
    }
}

// ============================================================================
// FUSE2: [0,128) zout | [128,256) y2out
// ============================================================================
#define FUSE2_SMEM 43008
__global__ __launch_bounds__(256) void k_fuse2(
    const float* __restrict__ S,
    const float* __restrict__ w_o, const float* __restrict__ b_o,
    const float* __restrict__ g_o, const float* __restrict__ be_o,
    const float* __restrict__ w_y2, const float* __restrict__ b_y2,
    const float* __restrict__ g_y2, const float* __restrict__ be_y2,
    const float* __restrict__ b3, float* __restrict__ out)
{
    extern __shared__ __align__(16) float pool[];
    int bx = blockIdx.x, t = threadIdx.x;

    if (bx < 128) {
        int n0 = (bx & 63) * 64, b = bx >> 6;
        float* xs  = pool;
        float* wot = pool + 3072;

        for (int i = t; i < CS * CS; i += 256) {
            int e = i % CS, d = i / CS;
            wot[i] = w_o[e * CS + d];
        }
        {
            int n = t & 63, v = t >> 6;
            const size_t cstride = (size_t)BB * NN * CS;
            const float* src = g_Xp + (size_t)(b * NN + n0 + n) * CS;
#pragma unroll
            for (int r = 0; r < 3; r++) {
                int dv = v + r * 4;
                float4 x = *(const float4*)&src[dv * 4];
#pragma unroll
                for (int p = 1; p < 8; p++) {
                    float4 xp = *(const float4*)&src[p * cstride + dv * 4];
                    x.x += xp.x; x.y += xp.y; x.z += xp.z; x.w += xp.w;
                }
                xs[(dv*4+0)*64+n] = x.x; xs[(dv*4+1)*64+n] = x.y;
                xs[(dv*4+2)*64+n] = x.z; xs[(dv*4+3)*64+n] = x.w;
            }
        }
        __syncthreads();

        int n = t & 63, eg = t >> 6;
        float acc[12];
#pragma unroll
        for (int k = 0; k < 12; k++) acc[k] = 0.f;
        for (int d = 0; d < CS; d++) {
            float x = xs[d * 64 + n];
#pragma unroll
            for (int v = 0; v < 3; v++) {
                float4 w4 = *(const float4*)&wot[d * CS + eg * 12 + v * 4];
                acc[v*4+0] += w4.x * x; acc[v*4+1] += w4.y * x;
                acc[v*4+2] += w4.z * x; acc[v*4+3] += w4.w * x;
            }
        }
        float inv = rsqrtf(1.f + 1e-5f);
#pragma unroll
        for (int k = 0; k < 12; k++) {
            int e = eg * 12 + k;
            float y = (acc[k] + b_o[e]) * (g_o[e] * inv) + be_o[e];
            y = fmaxf(y, 0.f);
            float spe = S[(b * CS + e) * NN + n0 + n]
                      + g_peS[e * 256 + ((n0 + n) & 255)];
            out[(b * 96 + e) * NN + n0 + n] = y * spe;
        }
        return;
    }

    {
        int j = bx - 128;
        int n0 = (j & 63) * 64, b = j >> 6;
        float* in_s = pool;
        float* wt   = pool + 6144;

        for (int i = t; i < CY * CS; i += 256) {
            int e = i % CS, c = i / CS;
            wt[i] = w_y2[e * CY + c];
        }
        const size_t pstride = (size_t)BB * CY * NN;
        const float* src = g_Y3p + (size_t)(b * CY) * NN + n0;
        for (int i = t; i < CY * 64; i += 256) {
            int c = i >> 6, n = i & 63;
            in_s[i] = src[c * NN + n] + src[pstride + c * NN + n]
                    + src[2 * pstride + c * NN + n] + b3[c];
        }
        __syncthreads();

        int n = t & 63, eg = t >> 6;
        float acc[12];
#pragma unroll
        for (int k = 0; k < 12; k++) acc[k] = 0.f;
        for (int c = 0; c < CY; c++) {
            float x = in_s[c * 64 + n];
#pragma unroll
            for (int v = 0; v < 3; v++) {
                float4 w4 = *(const float4*)&wt[c * CS + eg * 12 + v * 4];
                acc[v*4+0] += w4.x * x; acc[v*4+1] += w4.y * x;
                acc[v*4+2] += w4.z * x; acc[v*4+3] += w4.w * x;
            }
        }
        float inv = rsqrtf(1.f + 1e-5f);
#pragma unroll
        for (int k = 0; k < 12; k++) {
            int e = eg * 12 + k;
            float y = (acc[k] + b_y2[e]) * (g_y2[e] * inv) + be_y2[e];
            out[(b * 96 + 48 + e) * NN + n0 + n] = fmaxf(y, 0.f);
        }
    }
}

// ---------------- launch -----------------------------------------------------
extern "C" void kernel_launch(void* const* d_in, const int* in_sizes, int n_in,
                              void* d_out, int out_size)
{
    const float* Y    = (const float*)d_in[0];
    const float* S    = (const float*)d_in[1];
    const float* w_s  = (const float*)d_in[2];
    const float* b_s  = (const float*)d_in[3];
    const float* g_s  = (const float*)d_in[4];
    const float* be_s = (const float*)d_in[5];
    const float* w_y  = (const float*)d_in[6];
    const float* b_y  = (const float*)d_in[7];
    const float* g_y  = (const float*)d_in[8];
    const float* be_y = (const float*)d_in[9];
    const float* Wq   = (const float*)d_in[10];
    const float* Wk   = (const float*)d_in[11];
    const float* Wv   = (const float*)d_in[12];
    const float* w_o  = (const float*)d_in[13];
    const float* b_o  = (const float*)d_in[14];
    const float* g_o  = (const float*)d_in[15];
    const float* be_o = (const float*)d_in[16];
    const float* w3   = (const float*)d_in[17];
    const float* b3   = (const float*)d_in[18];
    const float* w_y2 = (const float*)d_in[19];
    const float* b_y2 = (const float*)d_in[20];
    const float* g_y2 = (const float*)d_in[21];
    const float* be_y2= (const float*)d_in[22];
    float* out = (float*)d_out;

    static cudaStream_t s2 = nullptr;
    static cudaEvent_t ev1 = nullptr, ev2 = nullptr;
    static int attr_done = 0;
    if (!attr_done) {
        cudaFuncSetAttribute(k_fuse1,  cudaFuncAttributeMaxDynamicSharedMemorySize, FUSE1_SMEM);
        cudaFuncSetAttribute(k_colsum, cudaFuncAttributeMaxDynamicSharedMemorySize, CS_SMEM);
        cudaFuncSetAttribute(k_flash,  cudaFuncAttributeMaxDynamicSharedMemorySize, FLASH_SMEM);
        cudaStreamCreateWithFlags(&s2, cudaStreamNonBlocking);
        cudaEventCreateWithFlags(&ev1, cudaEventDisableTiming);
        cudaEventCreateWithFlags(&ev2, cudaEventDisableTiming);
        attr_done = 1;
    }

    k_petab <<<144, 256>>>();
    k_fuse1 <<<1024, 256, FUSE1_SMEM>>>(Y, S, w_s, b_s, g_s, be_s, Wv,
                                        w_y, b_y, g_y, be_y, Wq, Wk);
    // fork: conv3d on s2, attention chain on default stream
    cudaEventRecord(ev1, 0);
    cudaStreamWaitEvent(s2, ev1, 0);
    k_conv3d<<<dim3(6, 16, BB * 3), 256, 0, s2>>>(w3);
    cudaEventRecord(ev2, s2);

    k_colsum<<<dim3(32, 8, BB), 256, CS_SMEM>>>();
    k_vprime<<<dim3(128, BB), 256>>>();
    k_flash <<<dim3(32, 8, BB), 256, FLASH_SMEM>>>();

    cudaStreamWaitEvent(0, ev2, 0);
    k_fuse2 <<<256, 256, FUSE2_SMEM>>>(S, w_o, b_o, g_o, be_o,
                                       w_y2, b_y2, g_y2, be_y2, b3, out);
}

// round 11
// speedup vs baseline: 2.9417x; 1.8149x over previous
#include <cuda_runtime.h>
#include <cuda_bf16.h>
#include <math.h>
#include <stdint.h>

#define BB 2
#define CY 96
#define CS 48
#define NN 4096
#define QSC 0.20822193f  /* 48^-0.5 * log2(e) */

// ---------------- scratch ----------------------------------------------------
__device__ __align__(16) float g_Ype[BB*CY*NN];
__device__ __align__(16) float g_V  [BB*NN*CS];
__device__ __align__(16) __nv_bfloat16 g_Qh[BB*NN*CS];
__device__ __align__(16) __nv_bfloat16 g_Kh[BB*NN*CS];
__device__ __align__(16) __nv_bfloat16 g_Vth[BB*CS*NN], g_Vtl[BB*CS*NN];
__device__ __align__(16) float g_psum[BB*8*NN];
__device__ __align__(16) float g_Xp[8*BB*NN*CS];
__device__ __align__(16) float g_Y3p[6*BB*CY*NN];         // 6 conv partials
__device__ __align__(16) float g_peS[CS*256];
__device__ __align__(16) float g_peY[CY*256];
// conv implicit-GEMM operands
__device__ __align__(16) __nv_bfloat16 g_Ypadh[BB*18*324*96];  // zero halo (never written)
__device__ __align__(16) __nv_bfloat16 g_Ypadl[BB*18*324*96];
__device__ __align__(16) __nv_bfloat16 g_w3h[27*96*96], g_w3l[27*96*96];

// ---------------- helpers ----------------------------------------------------
__device__ __forceinline__ void mma16816(float* c, const uint32_t* a, const uint32_t* b) {
    asm volatile(
        "mma.sync.aligned.m16n8k16.row.col.f32.bf16.bf16.f32 "
        "{%0,%1,%2,%3}, {%4,%5,%6,%7}, {%8,%9}, {%0,%1,%2,%3};\n"
        : "+f"(c[0]), "+f"(c[1]), "+f"(c[2]), "+f"(c[3])
        : "r"(a[0]), "r"(a[1]), "r"(a[2]), "r"(a[3]), "r"(b[0]), "r"(b[1]));
}
__device__ __forceinline__ uint32_t bf2u(__nv_bfloat16 a, __nv_bfloat16 b) {
    __nv_bfloat162 v(a, b);
    return *reinterpret_cast<uint32_t*>(&v);
}
__device__ __forceinline__ uint32_t cvt2bf(float lo, float hi) {
    uint32_t r;
    asm("cvt.rn.bf16x2.f32 %0, %1, %2;" : "=r"(r) : "f"(hi), "f"(lo));
    return r;
}
__device__ __forceinline__ void cpa16(__nv_bfloat16* smem, const __nv_bfloat16* gmem) {
    uint32_t s = (uint32_t)__cvta_generic_to_shared(smem);
    asm volatile("cp.async.cg.shared.global [%0], [%1], 16;\n" :: "r"(s), "l"(gmem));
}
#define CPA_COMMIT() asm volatile("cp.async.commit_group;\n" ::: "memory")
#define CPA_WAIT(N)  asm volatile("cp.async.wait_group %0;\n" :: "n"(N) : "memory")
__device__ __forceinline__ void ldsm4(uint32_t* r, uint32_t saddr) {
    asm volatile("ldmatrix.sync.aligned.m8n8.x4.shared.b16 {%0,%1,%2,%3}, [%4];"
        : "=r"(r[0]), "=r"(r[1]), "=r"(r[2]), "=r"(r[3]) : "r"(saddr));
}

// ---------------- PE tables --------------------------------------------------
__device__ __forceinline__ float pe_val(int ch, int h, int w, int c) {
    int blk = ch / c, t = ch - blk * c;
    int pos = (blk < 2) ? h : w;    // torch broadcast quirk
    int half = c >> 1;
    if (t < half) {
        float invf = powf(10000.f, -2.f * (float)t / (float)c);
        return sinf((float)pos * invf);
    } else {
        float invf = powf(10000.f, -2.f * (float)(t - half) / (float)c);
        return cosf((float)pos * invf);
    }
}
__global__ void k_petab() {
    int i = blockIdx.x * 256 + threadIdx.x;
    if (i < CY * 256) {
        int ch = i >> 8, n = i & 255;
        g_peY[i] = pe_val(ch, n >> 4, n & 15, 32);
    } else {
        int j = i - CY * 256;
        if (j < CS * 256) {
            int ch = j >> 8, n = j & 255;
            g_peS[j] = pe_val(ch, n >> 4, n & 15, 16);
        }
    }
}

// ---------------- weight prep: w3[co][ci][tap] -> bf16 h/l [tap][co][ci] ----
__global__ void k_wprep(const float* __restrict__ w3) {
    int j = blockIdx.x * 256 + threadIdx.x;
    if (j >= 27 * 96 * 96) return;
    int ci = j % 96, co = (j / 96) % 96, tap = j / 9216;
    float v = w3[(co * 96 + ci) * 27 + tap];
    __nv_bfloat16 h = __float2bfloat16(v);
    g_w3h[j] = h;
    g_w3l[j] = __float2bfloat16(v - __bfloat162float(h));
}

// ---------------- input prep: g_Ype -> channel-last padded bf16 h/l --------
__global__ __launch_bounds__(256) void k_ytrans() {
    int z = blockIdx.x, b = blockIdx.y, t = threadIdx.x;
    int y = t >> 4, x = t & 15;
    size_t dstbase = (((size_t)(b * 18 + z + 1) * 324) + (y + 1) * 18 + (x + 1)) * 96;
#pragma unroll
    for (int half = 0; half < 2; half++) {
        uint32_t hp[24], lp[24];
#pragma unroll
        for (int c2 = 0; c2 < 24; c2++) {
            int ci = half * 48 + c2 * 2;
            float v0 = g_Ype[(size_t)(b * CY + ci) * NN + z * 256 + t];
            float v1 = g_Ype[(size_t)(b * CY + ci + 1) * NN + z * 256 + t];
            __nv_bfloat16 h0 = __float2bfloat16(v0), h1 = __float2bfloat16(v1);
            hp[c2] = bf2u(h0, h1);
            lp[c2] = bf2u(__float2bfloat16(v0 - __bfloat162float(h0)),
                          __float2bfloat16(v1 - __bfloat162float(h1)));
        }
        uint4* dh = (uint4*)(g_Ypadh + dstbase + half * 48);
        uint4* dl = (uint4*)(g_Ypadl + dstbase + half * 48);
#pragma unroll
        for (int q = 0; q < 6; q++) {
            dh[q] = make_uint4(hp[q*4], hp[q*4+1], hp[q*4+2], hp[q*4+3]);
            dl[q] = make_uint4(lp[q*4], lp[q*4+1], lp[q*4+2], lp[q*4+3]);
        }
    }
}

// ============================================================================
// FUSE1: [0,768) addpe_y | [768,896) proj_sv->V | [896,1024) proj_y1+QK
// ============================================================================
#define FUSE1_SMEM 55552
__global__ __launch_bounds__(256) void k_fuse1(
    const float* __restrict__ Y, const float* __restrict__ S,
    const float* __restrict__ w_s, const float* __restrict__ b_s,
    const float* __restrict__ g_s, const float* __restrict__ be_s,
    const float* __restrict__ Wv,
    const float* __restrict__ w_y, const float* __restrict__ b_y,
    const float* __restrict__ g_y, const float* __restrict__ be_y,
    const float* __restrict__ Wq, const float* __restrict__ Wk)
{
    extern __shared__ __align__(16) float pool[];
    int bx = blockIdx.x, t = threadIdx.x;

    if (bx < 768) {
        int i = (bx * 256 + t) * 4;
        int n = i & (NN - 1);
        int ch = (i >> 12) % CY;
        float4 s = *(const float4*)&Y[i];
        float4 p = *(const float4*)&g_peY[ch * 256 + (n & 255)];
        s.x += p.x; s.y += p.y; s.z += p.z; s.w += p.w;
        *(float4*)&g_Ype[i] = s;
        return;
    }

    if (bx < 896) {
        int j = bx - 768;
        int n0 = (j & 63) * 64, b = j >> 6;
        float* in_s = pool;
        float* wt   = pool + 3072;
        float* wv   = pool + 5376;
        float* s1   = pool + 7680;

        for (int i = t; i < CS * CS; i += 256) {
            int e = i % CS, c = i / CS;
            wt[i] = w_s[e * CS + c];
            wv[i] = Wv[i];
        }
        for (int i = t; i < CS * 64; i += 256) {
            int c = i >> 6, nl = i & 63;
            in_s[i] = S[(b * CS + c) * NN + n0 + nl]
                    + g_peS[c * 256 + ((n0 + nl) & 255)];
        }
        __syncthreads();

        int n = t & 63, eg = t >> 6;
        float acc[12];
#pragma unroll
        for (int k = 0; k < 12; k++) acc[k] = 0.f;
        for (int c = 0; c < CS; c++) {
            float x = in_s[c * 64 + n];
#pragma unroll
            for (int v = 0; v < 3; v++) {
                float4 w4 = *(const float4*)&wt[c * CS + eg * 12 + v * 4];
                acc[v*4+0] += w4.x * x; acc[v*4+1] += w4.y * x;
                acc[v*4+2] += w4.z * x; acc[v*4+3] += w4.w * x;
            }
        }
        float inv = rsqrtf(1.f + 1e-5f);
#pragma unroll
        for (int k = 0; k < 12; k++) {
            int e = eg * 12 + k;
            float y = (acc[k] + b_s[e]) * (g_s[e] * inv) + be_s[e];
            s1[n * 49 + e] = fmaxf(y, 0.f);
        }
        __syncthreads();

#pragma unroll
        for (int k = 0; k < 12; k++) acc[k] = 0.f;
        for (int d = 0; d < CS; d++) {
            float x = s1[n * 49 + d];
#pragma unroll
            for (int v = 0; v < 3; v++) {
                float4 w4 = *(const float4*)&wv[d * CS + eg * 12 + v * 4];
                acc[v*4+0] += w4.x * x; acc[v*4+1] += w4.y * x;
                acc[v*4+2] += w4.z * x; acc[v*4+3] += w4.w * x;
            }
        }
        float* dst = g_V + ((b * NN + n0 + n) * CS) + eg * 12;
#pragma unroll
        for (int v = 0; v < 3; v++)
            *(float4*)&dst[v * 4] = make_float4(acc[v*4], acc[v*4+1], acc[v*4+2], acc[v*4+3]);
        return;
    }

    {   // proj_y1 + QK fused; Y1 lives only in smem. Q pre-scaled by QSC.
        int j = bx - 896;
        int n0 = (j & 63) * 64, b = j >> 6;
        float* in_s = pool;            // [96][64]
        float* wt   = pool + 6144;     // [c][e]
        float* s1   = pool + 10752;    // [n][49]

        for (int i = t; i < CY * CS; i += 256) {
            int e = i % CS, c = i / CS;
            wt[i] = w_y[e * CY + c];
        }
        for (int i = t; i < CY * 64; i += 256) {
            int c = i >> 6, nl = i & 63;
            in_s[i] = Y[(b * CY + c) * NN + n0 + nl]
                    + g_peY[c * 256 + ((n0 + nl) & 255)];
        }
        __syncthreads();

        int n = t & 63, eg = t >> 6;
        float acc[12];
#pragma unroll
        for (int k = 0; k < 12; k++) acc[k] = 0.f;
        for (int c = 0; c < CY; c++) {
            float x = in_s[c * 64 + n];
#pragma unroll
            for (int v = 0; v < 3; v++) {
                float4 w4 = *(const float4*)&wt[c * CS + eg * 12 + v * 4];
                acc[v*4+0] += w4.x * x; acc[v*4+1] += w4.y * x;
                acc[v*4+2] += w4.z * x; acc[v*4+3] += w4.w * x;
            }
        }
        float inv = rsqrtf(1.f + 1e-5f);
#pragma unroll
        for (int k = 0; k < 12; k++) {
            int e = eg * 12 + k;
            float y = (acc[k] + b_y[e]) * (g_y[e] * inv) + be_y[e];
            s1[n * 49 + e] = fmaxf(y, 0.f);
        }
        __syncthreads();

        float* wq = pool;
        float* wk = pool + 2304;
        for (int i = t; i < CS * CS; i += 256) { wq[i] = Wq[i]; wk[i] = Wk[i]; }
        __syncthreads();

        float aq[12], ak[12];
#pragma unroll
        for (int k = 0; k < 12; k++) { aq[k] = 0.f; ak[k] = 0.f; }
        for (int d = 0; d < CS; d++) {
            float x = s1[n * 49 + d];
#pragma unroll
            for (int v = 0; v < 3; v++) {
                float4 q4 = *(const float4*)&wq[d * CS + eg * 12 + v * 4];
                float4 k4 = *(const float4*)&wk[d * CS + eg * 12 + v * 4];
                aq[v*4+0] += q4.x * x; aq[v*4+1] += q4.y * x;
                aq[v*4+2] += q4.z * x; aq[v*4+3] += q4.w * x;
                ak[v*4+0] += k4.x * x; ak[v*4+1] += k4.y * x;
                ak[v*4+2] += k4.z * x; ak[v*4+3] += k4.w * x;
            }
        }
        int base = (b * NN + n0 + n) * CS + eg * 12;
#pragma unroll
        for (int k = 0; k < 12; k++) {
            g_Qh[base + k] = __float2bfloat16(aq[k] * QSC);
            g_Kh[base + k] = __float2bfloat16(ak[k]);
        }
    }
}

// ============================================================================
// Pass 1: column sums. A = K-tile persistent frags, B = Q chunks of 64.
// grid (32, 8, BB). smem 28672 B.
// ============================================================================
#define CS_SMEM 28672
__global__ __launch_bounds__(256) void k_colsum() {
    extern __shared__ __align__(16) unsigned char dsm[];
    __nv_bfloat16* KH = (__nv_bfloat16*)dsm;          // [128][56]
    __nv_bfloat16* QB = KH + 7168;                    // 2 bufs x QH[64][56]

    int k0 = blockIdx.x * 128, qq = blockIdx.y, b = blockIdx.z;
    int t = threadIdx.x, wid = t >> 5, l = t & 31;
    int lr = l >> 2, lc = (l & 3) * 2;
    int mb = wid * 16;

    {
        const __nv_bfloat16* s = g_Kh + (size_t)(b * NN + k0) * CS;
        for (int i = t; i < 768; i += 256) {
            int r = i / 6, c = i % 6;
            *(uint4*)(KH + r * 56 + c * 8) = *(const uint4*)(s + r * 48 + c * 8);
        }
    }
    __syncthreads();

    uint32_t kfh[3][4];
#pragma unroll
    for (int ks = 0; ks < 3; ks++) {
        int ko = ks * 16;
        kfh[ks][0] = *(uint32_t*)&KH[(mb + lr) * 56 + ko + lc];
        kfh[ks][1] = *(uint32_t*)&KH[(mb + 8 + lr) * 56 + ko + lc];
        kfh[ks][2] = *(uint32_t*)&KH[(mb + lr) * 56 + ko + lc + 8];
        kfh[ks][3] = *(uint32_t*)&KH[(mb + 8 + lr) * 56 + ko + lc + 8];
    }

    int lg = l >> 3, lrow = l & 7;
    int rowext = ((lg & 2) ? 8 : 0) + lrow;
    int colext = (lg & 1) ? 8 : 0;

    auto prefetchQ = [&](int ch, int bi) {
        int qb = qq * 512 + ch * 64;
        __nv_bfloat16* QH = QB + bi * 3584;
        const __nv_bfloat16* sh = g_Qh + (size_t)(b * NN + qb) * CS;
        for (int i = t; i < 384; i += 256) {
            int r = i / 6, c = i % 6;
            cpa16(QH + r * 56 + c * 8, sh + r * 48 + c * 8);
        }
        CPA_COMMIT();
    };

    float rs0 = 0.f, rs1 = 0.f;
    prefetchQ(0, 0);
    for (int ch = 0; ch < 8; ch++) {
        if (ch < 7) prefetchQ(ch + 1, (ch + 1) & 1);
        if (ch < 7) { CPA_WAIT(1); } else { CPA_WAIT(0); }
        __syncthreads();
        __nv_bfloat16* QH = QB + (ch & 1) * 3584;
        uint32_t qbase = (uint32_t)__cvta_generic_to_shared(QH);

#pragma unroll
        for (int nfp = 0; nfp < 4; nfp++) {
            float a0[4] = {0.f,0.f,0.f,0.f}, a1[4] = {0.f,0.f,0.f,0.f};
#pragma unroll
            for (int ks = 0; ks < 3; ks++) {
                int ko = ks * 16;
                uint32_t bf[4];
                ldsm4(bf, qbase + ((nfp * 16 + rowext) * 56 + ko + colext) * 2);
                mma16816(a0, kfh[ks], bf);
                mma16816(a1, kfh[ks], bf + 2);
            }
            rs0 += exp2f(a0[0]) + exp2f(a0[1]) + exp2f(a1[0]) + exp2f(a1[1]);
            rs1 += exp2f(a0[2]) + exp2f(a0[3]) + exp2f(a1[2]) + exp2f(a1[3]);
        }
        __syncthreads();
    }
    rs0 += __shfl_xor_sync(0xffffffffu, rs0, 1);
    rs0 += __shfl_xor_sync(0xffffffffu, rs0, 2);
    rs1 += __shfl_xor_sync(0xffffffffu, rs1, 1);
    rs1 += __shfl_xor_sync(0xffffffffu, rs1, 2);
    if ((l & 3) == 0) {
        g_psum[(b * 8 + qq) * NN + k0 + mb + lr]     = rs0;
        g_psum[(b * 8 + qq) * NN + k0 + mb + 8 + lr] = rs1;
    }
}

// ============================================================================
// vprime: V' = V / colsum, transposed [d][k], bf16 hi/lo. grid (128, BB).
// ============================================================================
__global__ __launch_bounds__(256) void k_vprime() {
    __shared__ float iz_s[32];
    __shared__ __nv_bfloat16 Th[48 * 34], Tl[48 * 34];

    int k0 = blockIdx.x * 32, b = blockIdx.y, t = threadIdx.x;
    if (t < 32) {
        int k = k0 + t;
        float s = 0.f;
#pragma unroll
        for (int i = 0; i < 8; i++) s += g_psum[(b * 8 + i) * NN + k];
        iz_s[t] = 1.f / s;
    }
    __syncthreads();

    const float* vsrc = g_V + (size_t)(b * NN + k0) * CS;
    for (int i = t; i < 32 * CS; i += 256) {
        int kk = i / CS, d = i - kk * CS;
        float val = vsrc[i] * iz_s[kk];
        __nv_bfloat16 h = __float2bfloat16(val);
        Th[d * 34 + kk] = h;
        Tl[d * 34 + kk] = __float2bfloat16(val - __bfloat162float(h));
    }
    __syncthreads();

    for (int j = t; j < 48 * 16; j += 256) {
        int d = j >> 4, c2 = (j & 15) * 2;
        *(uint32_t*)&g_Vth[(size_t)(b * CS + d) * NN + k0 + c2] =
            bf2u(Th[d * 34 + c2], Th[d * 34 + c2 + 1]);
        *(uint32_t*)&g_Vtl[(size_t)(b * CS + d) * NN + k0 + c2] =
            bf2u(Tl[d * 34 + c2], Tl[d * 34 + c2 + 1]);
    }
}

// ============================================================================
// flash pass2: 1-term QK recompute -> exp2 -> P as A-frags into 2-term P @ V'.
// grid (32, 8, BB). smem 41984 B.
// ============================================================================
#define FLASH_SMEM 41984
__global__ __launch_bounds__(256) void k_flash() {
    extern __shared__ __align__(16) unsigned char dsm[];
    __nv_bfloat16* base = (__nv_bfloat16*)dsm;
    __nv_bfloat16* KB = base;                 // 2 bufs x KH[64][56], overlaps Q staging
    __nv_bfloat16* VB = base + 7168;          // 2 bufs x (VH[48][72] + VL[48][72])

    int qblk = blockIdx.x, kq = blockIdx.y, b = blockIdx.z;
    int t = threadIdx.x, wid = t >> 5, l = t & 31;
    int lr = l >> 2, lc = (l & 3) * 2;
    int q0 = qblk * 128, mb = wid * 16;

    {
        __nv_bfloat16* QH = base;
        const __nv_bfloat16* s = g_Qh + (size_t)(b * NN + q0) * CS;
        for (int i = t; i < 768; i += 256) {
            int r = i / 6, c = i % 6;
            *(uint4*)(QH + r * 56 + c * 8) = *(const uint4*)(s + r * 48 + c * 8);
        }
    }
    __syncthreads();

    uint32_t qfh[3][4];
    {
        __nv_bfloat16* QH = base;
#pragma unroll
        for (int ks = 0; ks < 3; ks++) {
            int ko = ks * 16;
            qfh[ks][0] = *(uint32_t*)&QH[(mb + lr) * 56 + ko + lc];
            qfh[ks][1] = *(uint32_t*)&QH[(mb + 8 + lr) * 56 + ko + lc];
            qfh[ks][2] = *(uint32_t*)&QH[(mb + lr) * 56 + ko + lc + 8];
            qfh[ks][3] = *(uint32_t*)&QH[(mb + 8 + lr) * 56 + ko + lc + 8];
        }
    }
    __syncthreads();

    int lg = l >> 3, lrow = l & 7;
    int rowext = ((lg & 2) ? 8 : 0) + lrow;
    int colext = (lg & 1) ? 8 : 0;

    auto prefetchKV = [&](int ch, int bi) {
        int kb = kq * 512 + ch * 64;
        __nv_bfloat16* KHc = KB + bi * 3584;
        __nv_bfloat16* VHc = VB + bi * 6912;
        __nv_bfloat16* VLc = VHc + 3456;
        const __nv_bfloat16* skh = g_Kh + (size_t)(b * NN + kb) * CS;
        for (int i = t; i < 384; i += 256) {
            int r = i / 6, c = i % 6;
            cpa16(KHc + r * 56 + c * 8, skh + r * 48 + c * 8);
        }
        const __nv_bfloat16* svh = g_Vth + (size_t)(b * CS) * NN + kb;
        const __nv_bfloat16* svl = g_Vtl + (size_t)(b * CS) * NN + kb;
        for (int i = t; i < 384; i += 256) {
            int r = i / 8, c = i % 8;
            cpa16(VHc + r * 72 + c * 8, svh + (size_t)r * NN + c * 8);
            cpa16(VLc + r * 72 + c * 8, svl + (size_t)r * NN + c * 8);
        }
        CPA_COMMIT();
    };

    float pv[6][4];
#pragma unroll
    for (int nv = 0; nv < 6; nv++)
#pragma unroll
        for (int c = 0; c < 4; c++) pv[nv][c] = 0.f;

    prefetchKV(0, 0);
    for (int ch = 0; ch < 8; ch++) {
        if (ch < 7) prefetchKV(ch + 1, (ch + 1) & 1);
        if (ch < 7) { CPA_WAIT(1); } else { CPA_WAIT(0); }
        __syncthreads();
        __nv_bfloat16* KHc = KB + (ch & 1) * 3584;
        __nv_bfloat16* VHc = VB + (ch & 1) * 6912;
        __nv_bfloat16* VLc = VHc + 3456;
        uint32_t kbase = (uint32_t)__cvta_generic_to_shared(KHc);
        uint32_t vhb   = (uint32_t)__cvta_generic_to_shared(VHc);
        uint32_t vlb   = (uint32_t)__cvta_generic_to_shared(VLc);

#pragma unroll
        for (int nfp = 0; nfp < 4; nfp++) {
            float a0[4] = {0.f,0.f,0.f,0.f}, a1[4] = {0.f,0.f,0.f,0.f};
#pragma unroll
            for (int ks = 0; ks < 3; ks++) {
                int ko = ks * 16;
                uint32_t bf[4];
                ldsm4(bf, kbase + ((nfp * 16 + rowext) * 56 + ko + colext) * 2);
                mma16816(a0, qfh[ks], bf);
                mma16816(a1, qfh[ks], bf + 2);
            }
            uint32_t ph[4];
            ph[0] = cvt2bf(exp2f(a0[0]), exp2f(a0[1]));
            ph[1] = cvt2bf(exp2f(a0[2]), exp2f(a0[3]));
            ph[2] = cvt2bf(exp2f(a1[0]), exp2f(a1[1]));
            ph[3] = cvt2bf(exp2f(a1[2]), exp2f(a1[3]));
            int kop = nfp * 16;
#pragma unroll
            for (int p2 = 0; p2 < 3; p2++) {
                uint32_t vh[4], vl[4];
                uint32_t off = ((p2 * 16 + rowext) * 72 + kop + colext) * 2;
                ldsm4(vh, vhb + off);
                ldsm4(vl, vlb + off);
                mma16816(pv[2*p2],     ph, vh);
                mma16816(pv[2*p2],     ph, vl);
                mma16816(pv[2*p2 + 1], ph, vh + 2);
                mma16816(pv[2*p2 + 1], ph, vl + 2);
            }
        }
        __syncthreads();
    }

#pragma unroll
    for (int nv = 0; nv < 6; nv++) {
        int r = q0 + mb + lr, col = nv * 8 + lc;
        float* basep = &g_Xp[((size_t)(kq * BB + b) * NN + r) * CS + col];
        *(float2*)basep = make_float2(pv[nv][0], pv[nv][1]);
        *(float2*)(basep + 8 * CS) = make_float2(pv[nv][2], pv[nv][3]);
    }
}

// ============================================================================
// conv3d as implicit GEMM on tensor cores, 3-term bf16 (XhWh + XlWh + XhWl).
// grid (16 z, 6 = dz*2+cihalf, BB). One 62 KB input slab per block; W via LDG.
// D[co][n] partials -> g_Y3p[s][b][co][z*256+n].
// ============================================================================
#define CONV_SMEM 62208
__global__ __launch_bounds__(256) void k_conv() {
    extern __shared__ __align__(16) unsigned char dsm[];
    __nv_bfloat16* SH = (__nv_bfloat16*)dsm;      // [324][48] hi
    __nv_bfloat16* SL = SH + 324 * 48;            // [324][48] lo

    int z = blockIdx.x, s = blockIdx.y, b = blockIdx.z;
    int dz = s >> 1, half = s & 1;
    int t = threadIdx.x, wid = t >> 5, l = t & 31;
    int wm = wid >> 2, wn = wid & 3;              // 2 m-warps x 4 n-warps
    int lg = l >> 3, lrow = l & 7;
    int rowext = ((lg & 2) ? 8 : 0) + lrow;       // B ldsm pattern
    int colext = (lg & 1) ? 8 : 0;

    // stage slab z' = z + dz (padded coords), ci-half
    {
        const __nv_bfloat16* srch = g_Ypadh + ((size_t)(b * 18 + z + dz) * 324) * 96 + half * 48;
        const __nv_bfloat16* srcl = g_Ypadl + ((size_t)(b * 18 + z + dz) * 324) * 96 + half * 48;
        for (int i = t; i < 324 * 6; i += 256) {
            int r = i / 6, c = i % 6;
            cpa16(SH + r * 48 + c * 8, srch + (size_t)r * 96 + c * 8);
            cpa16(SL + r * 48 + c * 8, srcl + (size_t)r * 96 + c * 8);
        }
        CPA_COMMIT(); CPA_WAIT(0);
    }
    __syncthreads();

    // per-lane spatial coords for the 4 ldsm pairs (n = wn*64 + pair*16 + rowext)
    int py[4], px[4];
#pragma unroll
    for (int pair = 0; pair < 4; pair++) {
        int n = wn * 64 + pair * 16 + rowext;
        py[pair] = n >> 4;
        px[pair] = n & 15;
    }
    uint32_t sbh = (uint32_t)__cvta_generic_to_shared(SH);
    uint32_t sbl = (uint32_t)__cvta_generic_to_shared(SL);

    float acc[3][8][4];
#pragma unroll
    for (int mf = 0; mf < 3; mf++)
#pragma unroll
        for (int nf = 0; nf < 8; nf++)
#pragma unroll
            for (int c = 0; c < 4; c++) acc[mf][nf][c] = 0.f;

    int arow = l >> 2;          // A-frag row within 8
    int acol = (l & 3) * 2;     // A-frag ci pair

    for (int tap = 0; tap < 9; tap++) {
        int dy = tap / 3, dx = tap % 3;
        int tapg = dz * 9 + tap;
#pragma unroll
        for (int ks = 0; ks < 3; ks++) {
            // A-frags: W[tapg][co][ci] bf16 hi/lo via LDG (L2-hot, 1 MB total)
            uint32_t ah[3][4], al[3][4];
#pragma unroll
            for (int mf = 0; mf < 3; mf++) {
                size_t aoff = (size_t)tapg * 9216
                            + (size_t)(wm * 48 + mf * 16 + arow) * 96
                            + half * 48 + ks * 16 + acol;
                const __nv_bfloat16* ph = g_w3h + aoff;
                ah[mf][0] = *(const uint32_t*)ph;
                ah[mf][1] = *(const uint32_t*)(ph + 8 * 96);
                ah[mf][2] = *(const uint32_t*)(ph + 8);
                ah[mf][3] = *(const uint32_t*)(ph + 8 * 96 + 8);
                const __nv_bfloat16* pl = g_w3l + aoff;
                al[mf][0] = *(const uint32_t*)pl;
                al[mf][1] = *(const uint32_t*)(pl + 8 * 96);
                al[mf][2] = *(const uint32_t*)(pl + 8);
                al[mf][3] = *(const uint32_t*)(pl + 8 * 96 + 8);
            }
            // B-frags: shifted spatial rows via per-lane ldmatrix addressing
            uint32_t bh[4][4], bl[4][4];
#pragma unroll
            for (int pair = 0; pair < 4; pair++) {
                int srow = (py[pair] + dy) * 18 + px[pair] + dx;
                uint32_t off = (uint32_t)(srow * 48 + ks * 16 + colext) * 2;
                ldsm4(bh[pair], sbh + off);
                ldsm4(bl[pair], sbl + off);
            }
#pragma unroll
            for (int mf = 0; mf < 3; mf++)
#pragma unroll
                for (int pair = 0; pair < 4; pair++) {
                    mma16816(acc[mf][2*pair],     ah[mf], bh[pair]);
                    mma16816(acc[mf][2*pair],     al[mf], bh[pair]);
                    mma16816(acc[mf][2*pair],     ah[mf], bl[pair]);
                    mma16816(acc[mf][2*pair + 1], ah[mf], bh[pair] + 2);
                    mma16816(acc[mf][2*pair + 1], al[mf], bh[pair] + 2);
                    mma16816(acc[mf][2*pair + 1], ah[mf], bl[pair] + 2);
                }
        }
    }

    // store partials: D[co][spatial]
    float* out = g_Y3p + (size_t)s * (BB * CY * NN) + (size_t)(b * CY) * NN + z * 256;
#pragma unroll
    for (int mf = 0; mf < 3; mf++) {
        int r0 = wm * 48 + mf * 16 + (l >> 2);
#pragma unroll
        for (int nf = 0; nf < 8; nf++) {
            int c = wn * 64 + nf * 8 + (l & 3) * 2;
            *(float2*)&out[(size_t)r0 * NN + c]       = make_float2(acc[mf][nf][0], acc[mf][nf][1]);
            *(float2*)&out[(size_t)(r0 + 8) * NN + c] = make_float2(acc[mf][nf][2], acc[mf][nf][3]);
        }
    }
}

// ============================================================================
// FUSE2: [0,128) zout | [128,256) y2out (sums 6 conv partials)
// ============================================================================
#define FUSE2_SMEM 43008
__global__ __launch_bounds__(256) void k_fuse2(
    const float* __restrict__ S,
    const float* __restrict__ w_o, const float* __restrict__ b_o,
    const float* __restrict__ g_o, const float* __restrict__ be_o,
    const float* __restrict__ w_y2, const float* __restrict__ b_y2,
    const float* __restrict__ g_y2, const float* __restrict__ be_y2,
    const float* __restrict__ b3, float* __restrict__ out)
{
    extern __shared__ __align__(16) float pool[];
    int bx = blockIdx.x, t = threadIdx.x;

    if (bx < 128) {
        int n0 = (bx & 63) * 64, b = bx >> 6;
        float* xs  = pool;
        float* wot = pool + 3072;

        for (int i = t; i < CS * CS; i += 256) {
            int e = i % CS, d = i / CS;
            wot[i] = w_o[e * CS + d];
        }
        {
            int n = t & 63, v = t >> 6;
            const size_t cstride = (size_t)BB * NN * CS;
            const float* src = g_Xp + (size_t)(b * NN + n0 + n) * CS;
#pragma unroll
            for (int r = 0; r < 3; r++) {
                int dv = v + r * 4;
                float4 x = *(const float4*)&src[dv * 4];
#pragma unroll
                for (int p = 1; p < 8; p++) {
                    float4 xp = *(const float4*)&src[p * cstride + dv * 4];
                    x.x += xp.x; x.y += xp.y; x.z += xp.z; x.w += xp.w;
                }
                xs[(dv*4+0)*64+n] = x.x; xs[(dv*4+1)*64+n] = x.y;
                xs[(dv*4+2)*64+n] = x.z; xs[(dv*4+3)*64+n] = x.w;
            }
        }
        __syncthreads();

        int n = t & 63, eg = t >> 6;
        float acc[12];
#pragma unroll
        for (int k = 0; k < 12; k++) acc[k] = 0.f;
        for (int d = 0; d < CS; d++) {
            float x = xs[d * 64 + n];
#pragma unroll
            for (int v = 0; v < 3; v++) {
                float4 w4 = *(const float4*)&wot[d * CS + eg * 12 + v * 4];
                acc[v*4+0] += w4.x * x; acc[v*4+1] += w4.y * x;
                acc[v*4+2] += w4.z * x; acc[v*4+3] += w4.w * x;
            }
        }
        float inv = rsqrtf(1.f + 1e-5f);
#pragma unroll
        for (int k = 0; k < 12; k++) {
            int e = eg * 12 + k;
            float y = (acc[k] + b_o[e]) * (g_o[e] * inv) + be_o[e];
            y = fmaxf(y, 0.f);
            float spe = S[(b * CS + e) * NN + n0 + n]
                      + g_peS[e * 256 + ((n0 + n) & 255)];
            out[(b * 96 + e) * NN + n0 + n] = y * spe;
        }
        return;
    }

    {
        int j = bx - 128;
        int n0 = (j & 63) * 64, b = j >> 6;
        float* in_s = pool;
        float* wt   = pool + 6144;

        for (int i = t; i < CY * CS; i += 256) {
            int e = i % CS, c = i / CS;
            wt[i] = w_y2[e * CY + c];
        }
        const size_t pstride = (size_t)BB * CY * NN;
        const float* src = g_Y3p + (size_t)(b * CY) * NN + n0;
        for (int i = t; i < CY * 64; i += 256) {
            int c = i >> 6, n = i & 63;
            float v = b3[c];
#pragma unroll
            for (int p = 0; p < 6; p++) v += src[p * pstride + c * NN + n];
            in_s[i] = v;
        }
        __syncthreads();

        int n = t & 63, eg = t >> 6;
        float acc[12];
#pragma unroll
        for (int k = 0; k < 12; k++) acc[k] = 0.f;
        for (int c = 0; c < CY; c++) {
            float x = in_s[c * 64 + n];
#pragma unroll
            for (int v = 0; v < 3; v++) {
                float4 w4 = *(const float4*)&wt[c * CS + eg * 12 + v * 4];
                acc[v*4+0] += w4.x * x; acc[v*4+1] += w4.y * x;
                acc[v*4+2] += w4.z * x; acc[v*4+3] += w4.w * x;
            }
        }
        float inv = rsqrtf(1.f + 1e-5f);
#pragma unroll
        for (int k = 0; k < 12; k++) {
            int e = eg * 12 + k;
            float y = (acc[k] + b_y2[e]) * (g_y2[e] * inv) + be_y2[e];
            out[(b * 96 + 48 + e) * NN + n0 + n] = fmaxf(y, 0.f);
        }
    }
}

// ---------------- launch -----------------------------------------------------
extern "C" void kernel_launch(void* const* d_in, const int* in_sizes, int n_in,
                              void* d_out, int out_size)
{
    const float* Y    = (const float*)d_in[0];
    const float* S    = (const float*)d_in[1];
    const float* w_s  = (const float*)d_in[2];
    const float* b_s  = (const float*)d_in[3];
    const float* g_s  = (const float*)d_in[4];
    const float* be_s = (const float*)d_in[5];
    const float* w_y  = (const float*)d_in[6];
    const float* b_y  = (const float*)d_in[7];
    const float* g_y  = (const float*)d_in[8];
    const float* be_y = (const float*)d_in[9];
    const float* Wq   = (const float*)d_in[10];
    const float* Wk   = (const float*)d_in[11];
    const float* Wv   = (const float*)d_in[12];
    const float* w_o  = (const float*)d_in[13];
    const float* b_o  = (const float*)d_in[14];
    const float* g_o  = (const float*)d_in[15];
    const float* be_o = (const float*)d_in[16];
    const float* w3   = (const float*)d_in[17];
    const float* b3   = (const float*)d_in[18];
    const float* w_y2 = (const float*)d_in[19];
    const float* b_y2 = (const float*)d_in[20];
    const float* g_y2 = (const float*)d_in[21];
    const float* be_y2= (const float*)d_in[22];
    float* out = (float*)d_out;

    static cudaStream_t s2 = nullptr;
    static cudaEvent_t ev1 = nullptr, ev2 = nullptr;
    static int attr_done = 0;
    if (!attr_done) {
        cudaFuncSetAttribute(k_fuse1,  cudaFuncAttributeMaxDynamicSharedMemorySize, FUSE1_SMEM);
        cudaFuncSetAttribute(k_colsum, cudaFuncAttributeMaxDynamicSharedMemorySize, CS_SMEM);
        cudaFuncSetAttribute(k_flash,  cudaFuncAttributeMaxDynamicSharedMemorySize, FLASH_SMEM);
        cudaFuncSetAttribute(k_conv,   cudaFuncAttributeMaxDynamicSharedMemorySize, CONV_SMEM);
        cudaStreamCreateWithFlags(&s2, cudaStreamNonBlocking);
        cudaEventCreateWithFlags(&ev1, cudaEventDisableTiming);
        cudaEventCreateWithFlags(&ev2, cudaEventDisableTiming);
        attr_done = 1;
    }

    k_petab <<<144, 256>>>();
    k_wprep <<<972, 256, 0, s2>>>(w3);      // independent: runs alongside fuse1
    k_fuse1 <<<1024, 256, FUSE1_SMEM>>>(Y, S, w_s, b_s, g_s, be_s, Wv,
                                        w_y, b_y, g_y, be_y, Wq, Wk);
    // fork: conv branch on s2, attention chain on default stream
    cudaEventRecord(ev1, 0);
    cudaStreamWaitEvent(s2, ev1, 0);
    k_ytrans<<<dim3(16, BB), 256, 0, s2>>>();
    k_conv  <<<dim3(16, 6, BB), 256, CONV_SMEM, s2>>>();
    cudaEventRecord(ev2, s2);

    k_colsum<<<dim3(32, 8, BB), 256, CS_SMEM>>>();
    k_vprime<<<dim3(128, BB), 256>>>();
    k_flash <<<dim3(32, 8, BB), 256, FLASH_SMEM>>>();

    cudaStreamWaitEvent(0, ev2, 0);
    k_fuse2 <<<256, 256, FUSE2_SMEM>>>(S, w_o, b_o, g_o, be_o,
                                       w_y2, b_y2, g_y2, be_y2, b3, out);
}